// round 2
// baseline (speedup 1.0000x reference)
#include <cuda_runtime.h>
#include <math.h>

// Problem dims (fixed by the dataset)
static constexpr int  BB  = 2;
static constexpr int  NN_ = 4096;
static constexpr int  CC  = 512;
static constexpr int  MM  = BB * NN_;               // 8192 rows total
static constexpr size_t SBATCH = (size_t)NN_ * NN_; // 16777216

// Scratch (device globals: no cudaMalloc allowed)
__device__ float g_q[(size_t)MM * CC];
__device__ float g_k[(size_t)MM * CC];
__device__ float g_v[(size_t)MM * CC];
__device__ float g_S[(size_t)BB * SBATCH];     // 128 MiB logits
__device__ float g_rowm[MM];
__device__ float g_rowinvl[MM];
__device__ float g_cpart[8 * MM];
__device__ float g_srow[MM];

// FMA-only exp for x <= 0 (avoids MUFU throughput wall; ~1e-7 rel err)
__device__ __forceinline__ float fast_exp_neg(float x) {
    if (x < -87.0f) return 0.0f;
    float y = x * 1.4426950408889634f;   // x * log2(e)
    float n = rintf(y);
    float f = y - n;                     // exact (|f| <= 0.5)
    float p = 1.5403530e-4f;
    p = fmaf(p, f, 1.3333558146e-3f);
    p = fmaf(p, f, 9.6181291918e-3f);
    p = fmaf(p, f, 5.5504108664e-2f);
    p = fmaf(p, f, 2.4022650696e-1f);
    p = fmaf(p, f, 6.9314718056e-1f);
    p = fmaf(p, f, 1.0f);
    int in = (int)n;                     // in >= -126 given x >= -87
    return p * __int_as_float((in + 127) << 23);
}

// ---------------------------------------------------------------------------
// Tiled fp32 GEMM: 128x128 tile, BK=8, 256 threads, 8x8 per thread.
// BT=false: C = A[MxK] * B[KxN] (both row-major)
// BT=true : C = A[MxK] * B[NxK]^T (both row-major, K contiguous)
// MODE 0: C = acc + bias[col]                 (QKV projections)
// MODE 1: C = acc                             (logits)
// MODE 2: full epilogue: scale*acc + bo, BN, relu, + residual
// ---------------------------------------------------------------------------
template<int MODE, bool BT>
__global__ void __launch_bounds__(256)
sgemm_kernel(const float* __restrict__ A, const float* __restrict__ Bm,
             float* __restrict__ C, int M, int N, int K,
             size_t sA, size_t sB, size_t sC,
             const float* __restrict__ bias,
             const float* __restrict__ srow,
             const float* __restrict__ xres,
             const float* __restrict__ bnscale,
             const float* __restrict__ bnbias,
             const float* __restrict__ bnmean,
             const float* __restrict__ bnvar)
{
    A  += (size_t)blockIdx.z * sA;
    Bm += (size_t)blockIdx.z * sB;
    C  += (size_t)blockIdx.z * sC;

    __shared__ float As[8][128];
    __shared__ float Bs[8][128];

    const int tid = threadIdx.x;
    const int bm  = blockIdx.y * 128;
    const int bn  = blockIdx.x * 128;

    const int lrow  = tid >> 1;          // 0..127
    const int lcol  = (tid & 1) * 4;     // 0 or 4
    const int brow8 = tid >> 5;          // 0..7   (NN B-tile load)
    const int bcol8 = (tid & 31) * 4;    // 0..124

    const int tm = (tid >> 4) * 8;
    const int tn = (tid & 15) * 8;

    float acc[8][8];
#pragma unroll
    for (int i = 0; i < 8; i++)
#pragma unroll
        for (int j = 0; j < 8; j++) acc[i][j] = 0.0f;

    const float* Aptr = A + (size_t)(bm + lrow) * K + lcol;
    const float* Bptr = BT ? (Bm + (size_t)(bn + lrow) * K + lcol)
                           : (Bm + (size_t)brow8 * N + bn + bcol8);

    for (int k0 = 0; k0 < K; k0 += 8) {
        float4 av = *(const float4*)(Aptr + k0);
        As[lcol + 0][lrow] = av.x; As[lcol + 1][lrow] = av.y;
        As[lcol + 2][lrow] = av.z; As[lcol + 3][lrow] = av.w;
        if (BT) {
            float4 bv = *(const float4*)(Bptr + k0);
            Bs[lcol + 0][lrow] = bv.x; Bs[lcol + 1][lrow] = bv.y;
            Bs[lcol + 2][lrow] = bv.z; Bs[lcol + 3][lrow] = bv.w;
        } else {
            float4 bv = *(const float4*)(Bptr + (size_t)k0 * N);
            *(float4*)&Bs[brow8][bcol8] = bv;
        }
        __syncthreads();
#pragma unroll
        for (int kk = 0; kk < 8; kk++) {
            float ra[8], rb[8];
#pragma unroll
            for (int i = 0; i < 8; i++) ra[i] = As[kk][tm + i];
#pragma unroll
            for (int j = 0; j < 8; j++) rb[j] = Bs[kk][tn + j];
#pragma unroll
            for (int i = 0; i < 8; i++)
#pragma unroll
                for (int j = 0; j < 8; j++)
                    acc[i][j] = fmaf(ra[i], rb[j], acc[i][j]);
        }
        __syncthreads();
    }

#pragma unroll
    for (int i = 0; i < 8; i++) {
        const int row = bm + tm + i;
        float s = 1.0f;
        if (MODE == 2) s = srow[row];
#pragma unroll
        for (int j = 0; j < 8; j++) {
            const int col = bn + tn + j;
            float v = acc[i][j];
            if (MODE == 0) {
                v += bias[col];
            } else if (MODE == 2) {
                v = v * s + bias[col];
                v = (v - bnmean[col]) * rsqrtf(bnvar[col] + 1e-5f) * bnscale[col]
                    + bnbias[col];
                v = fmaxf(v, 0.0f) + xres[(size_t)row * N + col];
            }
            C[(size_t)row * N + col] = v;
        }
    }
}

// ---------------------------------------------------------------------------
// Row softmax stats: one block per row of S (4096 elems), cached in smem.
// ---------------------------------------------------------------------------
__global__ void __launch_bounds__(256)
rowstats_kernel(const float* __restrict__ S,
                float* __restrict__ rowm, float* __restrict__ rowinvl)
{
    __shared__ float buf[4096];
    __shared__ float red[33];
    const int row = blockIdx.x;
    const float* Sr = S + (size_t)row * 4096;
    const int tid = threadIdx.x;

    float mx = -3.0e38f;
    for (int i = tid; i < 4096; i += 256) {
        float v = Sr[i];
        buf[i] = v;
        mx = fmaxf(mx, v);
    }
#pragma unroll
    for (int o = 16; o > 0; o >>= 1)
        mx = fmaxf(mx, __shfl_xor_sync(0xffffffffu, mx, o));
    if ((tid & 31) == 0) red[tid >> 5] = mx;
    __syncthreads();
    if (tid < 32) {
        float v = (tid < 8) ? red[tid] : -3.0e38f;
#pragma unroll
        for (int o = 4; o > 0; o >>= 1)
            v = fmaxf(v, __shfl_xor_sync(0xffffffffu, v, o));
        if (tid == 0) red[32] = v;
    }
    __syncthreads();
    mx = red[32];

    float tot = 0.0f;
    for (int i = tid; i < 4096; i += 256) tot += fast_exp_neg(buf[i] - mx);
#pragma unroll
    for (int o = 16; o > 0; o >>= 1)
        tot += __shfl_xor_sync(0xffffffffu, tot, o);
    if ((tid & 31) == 0) red[tid >> 5] = tot;
    __syncthreads();
    if (tid == 0) {
        float t = 0.0f;
#pragma unroll
        for (int w = 0; w < 8; w++) t += red[w];
        rowm[row]    = mx;
        rowinvl[row] = 1.0f / t;
    }
}

// ---------------------------------------------------------------------------
// Column sums of normalized attention: deterministic two-stage reduction.
// Stage 1: each block owns 256 columns x 512 rows, writes a partial.
// ---------------------------------------------------------------------------
__global__ void __launch_bounds__(256)
colsum_part_kernel(const float* __restrict__ S,
                   const float* __restrict__ rowm,
                   const float* __restrict__ rowinvl,
                   float* __restrict__ cpart)
{
    __shared__ float sm[512], si[512];
    const int b     = blockIdx.z;
    const int n     = blockIdx.x * 256 + threadIdx.x;
    const int m0    = blockIdx.y * 512;
    const int rbase = b * 4096;
    for (int i = threadIdx.x; i < 512; i += 256) {
        sm[i] = rowm[rbase + m0 + i];
        si[i] = rowinvl[rbase + m0 + i];
    }
    __syncthreads();
    const float* Sb = S + (size_t)b * SBATCH + (size_t)m0 * 4096 + n;
    float acc = 0.0f;
#pragma unroll 4
    for (int mm = 0; mm < 512; mm++)
        acc += fast_exp_neg(Sb[(size_t)mm * 4096] - sm[mm]) * si[mm];
    cpart[(size_t)blockIdx.y * MM + rbase + n] = acc;
}

__global__ void __launch_bounds__(256)
colsum_final_kernel(const float* __restrict__ cpart, float* __restrict__ srow)
{
    const int i = blockIdx.x * 256 + threadIdx.x;
    float c = 0.0f;
#pragma unroll
    for (int p = 0; p < 8; p++) c += cpart[(size_t)p * MM + i];
    srow[i] = c / (c + 1e-9f);   // s = colsum / (eps + colsum)
}

// ---------------------------------------------------------------------------
extern "C" void kernel_launch(void* const* d_in, const int* in_sizes, int n_in,
                              void* d_out, int out_size)
{
    // metadata order: inputs, Wq, Wk, Wv, Wo, bq, bk, bv, bo, bn_scale,
    //                 bn_bias, bn_mean, bn_var   (two separate loops in setup!)
    const float* x   = (const float*)d_in[0];
    const float* Wq  = (const float*)d_in[1];
    const float* Wk  = (const float*)d_in[2];
    const float* Wv  = (const float*)d_in[3];
    const float* Wo  = (const float*)d_in[4];
    const float* bq  = (const float*)d_in[5];
    const float* bk  = (const float*)d_in[6];
    const float* bv  = (const float*)d_in[7];
    const float* bo  = (const float*)d_in[8];
    const float* bns = (const float*)d_in[9];
    const float* bnb = (const float*)d_in[10];
    const float* bnm = (const float*)d_in[11];
    const float* bnv = (const float*)d_in[12];
    float* out = (float*)d_out;

    float *q, *k, *v, *S, *rowm, *rowinvl, *cpart, *srow;
    cudaGetSymbolAddress((void**)&q,       g_q);
    cudaGetSymbolAddress((void**)&k,       g_k);
    cudaGetSymbolAddress((void**)&v,       g_v);
    cudaGetSymbolAddress((void**)&S,       g_S);
    cudaGetSymbolAddress((void**)&rowm,    g_rowm);
    cudaGetSymbolAddress((void**)&rowinvl, g_rowinvl);
    cudaGetSymbolAddress((void**)&cpart,   g_cpart);
    cudaGetSymbolAddress((void**)&srow,    g_srow);

    dim3 blk(256);
    dim3 gProj(CC / 128, MM / 128, 1);        // (4, 64)

    // K1: QKV projections (fp32, fused bias)
    sgemm_kernel<0, false><<<gProj, blk>>>(x, Wq, q, MM, CC, CC, 0, 0, 0,
        bq, nullptr, nullptr, nullptr, nullptr, nullptr, nullptr);
    sgemm_kernel<0, false><<<gProj, blk>>>(x, Wk, k, MM, CC, CC, 0, 0, 0,
        bk, nullptr, nullptr, nullptr, nullptr, nullptr, nullptr);
    sgemm_kernel<0, false><<<gProj, blk>>>(x, Wv, v, MM, CC, CC, 0, 0, 0,
        bv, nullptr, nullptr, nullptr, nullptr, nullptr, nullptr);

    // K2: S = q @ k^T per batch
    dim3 gS(NN_ / 128, NN_ / 128, BB);        // (32, 32, 2)
    sgemm_kernel<1, true><<<gS, blk>>>(q, k, S, NN_, NN_, CC,
        (size_t)NN_ * CC, (size_t)NN_ * CC, SBATCH,
        nullptr, nullptr, nullptr, nullptr, nullptr, nullptr, nullptr);

    // K3: per-row softmax stats
    rowstats_kernel<<<MM, blk>>>(S, rowm, rowinvl);

    // K4: column sums -> s[n] (deterministic two-stage)
    colsum_part_kernel<<<dim3(16, 8, 2), blk>>>(S, rowm, rowinvl, cpart);
    colsum_final_kernel<<<32, blk>>>(cpart, srow);

    // K5: out = relu(BN((v*s) @ Wo + bo)) + x
    sgemm_kernel<2, false><<<gProj, blk>>>(v, Wo, out, MM, CC, CC, 0, 0, 0,
        bo, srow, x, bns, bnb, bnm, bnv);
}

// round 4
// speedup vs baseline: 2.3341x; 2.3341x over previous
#include <cuda_runtime.h>
#include <cuda_bf16.h>
#include <math.h>
#include <stdint.h>

// Problem dims (fixed by the dataset)
static constexpr int  BB  = 2;
static constexpr int  NN_ = 4096;
static constexpr int  CC  = 512;
static constexpr int  MM  = BB * NN_;               // 8192 rows total
static constexpr size_t SBATCH = (size_t)NN_ * NN_; // 16777216

// Scratch (device globals: no cudaMalloc allowed)
__device__ __align__(256) unsigned short g_qh[(size_t)MM * CC];     // bf16 q
__device__ __align__(256) unsigned short g_kh[(size_t)MM * CC];     // bf16 k
__device__ __align__(256) float          g_v [(size_t)MM * CC];     // fp32 v
__device__ __align__(256) unsigned short g_S [(size_t)BB * SBATCH]; // bf16 logits
__device__ float g_rowm[MM];
__device__ float g_rowinvl[MM];
__device__ float g_cpart[8 * MM];
__device__ float g_srow[MM];

// ---------------------------------------------------------------------------
// PTX helpers (plain sm_103-compatible: mma.sync / ldmatrix / cp.async)
// ---------------------------------------------------------------------------
__device__ __forceinline__ uint32_t smem_u32(const void* p) {
    uint32_t a;
    asm("{ .reg .u64 t; cvta.to.shared.u64 t, %1; cvt.u32.u64 %0, t; }"
        : "=r"(a) : "l"(p));
    return a;
}
__device__ __forceinline__ void cp_async16(uint32_t dst, const void* src) {
    asm volatile("cp.async.cg.shared.global [%0], [%1], 16;"
                 :: "r"(dst), "l"(src) : "memory");
}
__device__ __forceinline__ void cp_commit() {
    asm volatile("cp.async.commit_group;" ::: "memory");
}
template<int N>
__device__ __forceinline__ void cp_wait() {
    asm volatile("cp.async.wait_group %0;" :: "n"(N) : "memory");
}
__device__ __forceinline__ void ldmatrix_x4(uint32_t& r0, uint32_t& r1,
                                            uint32_t& r2, uint32_t& r3,
                                            uint32_t addr) {
    asm volatile("ldmatrix.sync.aligned.m8n8.x4.shared.b16 {%0,%1,%2,%3}, [%4];"
                 : "=r"(r0), "=r"(r1), "=r"(r2), "=r"(r3) : "r"(addr));
}
__device__ __forceinline__ void mma_bf16(float& c0, float& c1, float& c2, float& c3,
                                         uint32_t a0, uint32_t a1, uint32_t a2, uint32_t a3,
                                         uint32_t b0, uint32_t b1) {
    asm volatile(
        "mma.sync.aligned.m16n8k16.row.col.f32.bf16.bf16.f32 "
        "{%0,%1,%2,%3}, {%4,%5,%6,%7}, {%8,%9}, {%0,%1,%2,%3};"
        : "+f"(c0), "+f"(c1), "+f"(c2), "+f"(c3)
        : "r"(a0), "r"(a1), "r"(a2), "r"(a3), "r"(b0), "r"(b1));
}

// smem tile layout: row-major [row][32 bf16] = 64B/row; 16B granules XOR-swizzled
__device__ __forceinline__ uint32_t sw_off(int row, int kg) {
    return (uint32_t)(row * 64 + ((kg ^ ((row >> 1) & 3)) << 4));
}

// FMA-only exp for x <= 0 (avoids MUFU throughput wall; ~1e-7 rel err)
__device__ __forceinline__ float fast_exp_neg(float x) {
    if (x < -87.0f) return 0.0f;
    float y = x * 1.4426950408889634f;
    float n = rintf(y);
    float f = y - n;
    float p = 1.5403530e-4f;
    p = fmaf(p, f, 1.3333558146e-3f);
    p = fmaf(p, f, 9.6181291918e-3f);
    p = fmaf(p, f, 5.5504108664e-2f);
    p = fmaf(p, f, 2.4022650696e-1f);
    p = fmaf(p, f, 6.9314718056e-1f);
    p = fmaf(p, f, 1.0f);
    int in = (int)n;
    return p * __int_as_float((in + 127) << 23);
}

// ---------------------------------------------------------------------------
// K2: S[b] = q[b] @ k[b]^T via mma.sync bf16. Block tile 128x128, BK=32,
// 8 warps (4M x 2N, warp tile 32x64), 3-stage cp.async pipeline.
// ---------------------------------------------------------------------------
__global__ void __launch_bounds__(256)
qk_mma_kernel(const __nv_bfloat16* __restrict__ Q,
              const __nv_bfloat16* __restrict__ Kmat,
              __nv_bfloat16* __restrict__ S)
{
    __shared__ __align__(1024) char smem[3 * 16384];   // 3 stages x (8KB A + 8KB B)
    const uint32_t sbase = smem_u32(smem);

    const int tid = threadIdx.x;
    const int wid = tid >> 5;
    const int lid = tid & 31;
    const int wm  = wid & 3;      // 0..3  -> M offset wm*32
    const int wn  = wid >> 2;     // 0..1  -> N offset wn*64
    const int n0  = blockIdx.x * 128;
    const int m0  = blockIdx.y * 128;
    const int bz  = blockIdx.z;

    const __nv_bfloat16* Qb = Q    + ((size_t)bz * NN_ + m0) * CC;
    const __nv_bfloat16* Kb = Kmat + ((size_t)bz * NN_ + n0) * CC;

    // Per-thread gmem->smem mapping (2 chunks of 16B for A, 2 for B per stage)
    // chunk idx = tid + it*256 ; row = idx>>2 ; kg = idx&3
    // Precompute per-lane ldmatrix offsets (relative to stage base)
    const int mgrp = lid >> 3;         // which 8x8 matrix this lane addresses
    const int lr   = lid & 7;
    uint32_t aoff[2][2], boff[4][2];
#pragma unroll
    for (int mt = 0; mt < 2; mt++)
#pragma unroll
        for (int kh = 0; kh < 2; kh++) {
            int row = wm * 32 + mt * 16 + lr + ((mgrp & 1) << 3);
            int kg  = 2 * kh + (mgrp >> 1);
            aoff[mt][kh] = sw_off(row, kg);
        }
#pragma unroll
    for (int i = 0; i < 4; i++)
#pragma unroll
        for (int kh = 0; kh < 2; kh++) {
            int row = wn * 64 + i * 16 + lr + ((mgrp >> 1) << 3);
            int kg  = 2 * kh + (mgrp & 1);
            boff[i][kh] = 8192u + sw_off(row, kg);
        }

    float acc[2][8][4];
#pragma unroll
    for (int mt = 0; mt < 2; mt++)
#pragma unroll
        for (int nt = 0; nt < 8; nt++)
#pragma unroll
            for (int e = 0; e < 4; e++) acc[mt][nt][e] = 0.0f;

    auto load_stage = [&](int kb, int buf) {
        uint32_t dstb = sbase + buf * 16384;
#pragma unroll
        for (int it = 0; it < 2; it++) {
            int idx = tid + it * 256;
            int row = idx >> 2, kg = idx & 3;
            cp_async16(dstb + sw_off(row, kg), Qb + (size_t)row * CC + kb * 32 + kg * 8);
        }
#pragma unroll
        for (int it = 0; it < 2; it++) {
            int idx = tid + it * 256;
            int row = idx >> 2, kg = idx & 3;
            cp_async16(dstb + 8192 + sw_off(row, kg), Kb + (size_t)row * CC + kb * 32 + kg * 8);
        }
        cp_commit();
    };

    load_stage(0, 0);
    load_stage(1, 1);

    const int KB = CC / 32;   // 16
    for (int kb = 0; kb < KB; kb++) {
        const int buf = kb % 3;
        if (kb < KB - 1) cp_wait<1>(); else cp_wait<0>();
        __syncthreads();
        if (kb + 2 < KB) load_stage(kb + 2, (kb + 2) % 3);

        const uint32_t stb = sbase + buf * 16384;
#pragma unroll
        for (int kh = 0; kh < 2; kh++) {
            uint32_t af[2][4], bf[4][4];
#pragma unroll
            for (int mt = 0; mt < 2; mt++)
                ldmatrix_x4(af[mt][0], af[mt][1], af[mt][2], af[mt][3],
                            stb + aoff[mt][kh]);
#pragma unroll
            for (int i = 0; i < 4; i++)
                ldmatrix_x4(bf[i][0], bf[i][1], bf[i][2], bf[i][3],
                            stb + boff[i][kh]);
#pragma unroll
            for (int mt = 0; mt < 2; mt++)
#pragma unroll
                for (int i = 0; i < 4; i++) {
                    mma_bf16(acc[mt][2*i][0], acc[mt][2*i][1], acc[mt][2*i][2], acc[mt][2*i][3],
                             af[mt][0], af[mt][1], af[mt][2], af[mt][3],
                             bf[i][0], bf[i][1]);
                    mma_bf16(acc[mt][2*i+1][0], acc[mt][2*i+1][1], acc[mt][2*i+1][2], acc[mt][2*i+1][3],
                             af[mt][0], af[mt][1], af[mt][2], af[mt][3],
                             bf[i][2], bf[i][3]);
                }
        }
    }

    // Epilogue: write bf16 S. Lane mapping of m16n8 acc:
    // c0,c1 -> (row = lid/4, col = (lid%4)*2), c2,c3 -> row+8.
    const int grow = lid >> 2;
    const int gcol = (lid & 3) * 2;
#pragma unroll
    for (int mt = 0; mt < 2; mt++) {
#pragma unroll
        for (int nt = 0; nt < 8; nt++) {
            const int col = n0 + wn * 64 + nt * 8 + gcol;
            const int rowa = m0 + wm * 32 + mt * 16 + grow;
            __nv_bfloat162 h0 = __float22bfloat162_rn(
                make_float2(acc[mt][nt][0], acc[mt][nt][1]));
            __nv_bfloat162 h1 = __float22bfloat162_rn(
                make_float2(acc[mt][nt][2], acc[mt][nt][3]));
            *(__nv_bfloat162*)(S + (size_t)bz * SBATCH + (size_t)rowa * NN_ + col) = h0;
            *(__nv_bfloat162*)(S + (size_t)bz * SBATCH + (size_t)(rowa + 8) * NN_ + col) = h1;
        }
    }
}

// ---------------------------------------------------------------------------
// Tiled fp32 GEMM: 128x128 tile, BK=8, 256 threads, 8x8 per thread.
// MODE 0: C = acc + bias[col] (optionally bf16 output)
// MODE 2: full epilogue: scale*acc + bo, BN, relu, + residual
// ---------------------------------------------------------------------------
template<int MODE, bool OBF16>
__global__ void __launch_bounds__(256)
sgemm_kernel(const float* __restrict__ A, const float* __restrict__ Bm,
             void* __restrict__ Cout, int N, int K,
             const float* __restrict__ bias,
             const float* __restrict__ srow,
             const float* __restrict__ xres,
             const float* __restrict__ bnscale,
             const float* __restrict__ bnbias,
             const float* __restrict__ bnmean,
             const float* __restrict__ bnvar)
{
    __shared__ float As[8][128];
    __shared__ float Bs[8][128];

    const int tid = threadIdx.x;
    const int bm  = blockIdx.y * 128;
    const int bn  = blockIdx.x * 128;

    const int lrow  = tid >> 1;
    const int lcol  = (tid & 1) * 4;
    const int brow8 = tid >> 5;
    const int bcol8 = (tid & 31) * 4;

    const int tm = (tid >> 4) * 8;
    const int tn = (tid & 15) * 8;

    float acc[8][8];
#pragma unroll
    for (int i = 0; i < 8; i++)
#pragma unroll
        for (int j = 0; j < 8; j++) acc[i][j] = 0.0f;

    const float* Aptr = A + (size_t)(bm + lrow) * K + lcol;
    const float* Bptr = Bm + (size_t)brow8 * N + bn + bcol8;

    for (int k0 = 0; k0 < K; k0 += 8) {
        float4 av = *(const float4*)(Aptr + k0);
        As[lcol + 0][lrow] = av.x; As[lcol + 1][lrow] = av.y;
        As[lcol + 2][lrow] = av.z; As[lcol + 3][lrow] = av.w;
        float4 bv = *(const float4*)(Bptr + (size_t)k0 * N);
        *(float4*)&Bs[brow8][bcol8] = bv;
        __syncthreads();
#pragma unroll
        for (int kk = 0; kk < 8; kk++) {
            float ra[8], rb[8];
#pragma unroll
            for (int i = 0; i < 8; i++) ra[i] = As[kk][tm + i];
#pragma unroll
            for (int j = 0; j < 8; j++) rb[j] = Bs[kk][tn + j];
#pragma unroll
            for (int i = 0; i < 8; i++)
#pragma unroll
                for (int j = 0; j < 8; j++)
                    acc[i][j] = fmaf(ra[i], rb[j], acc[i][j]);
        }
        __syncthreads();
    }

#pragma unroll
    for (int i = 0; i < 8; i++) {
        const int row = bm + tm + i;
        float s = 1.0f;
        if (MODE == 2) s = srow[row];
#pragma unroll
        for (int j = 0; j < 8; j++) {
            const int col = bn + tn + j;
            float v = acc[i][j];
            if (MODE == 0) {
                v += bias[col];
            } else {
                v = v * s + bias[col];
                v = (v - bnmean[col]) * rsqrtf(bnvar[col] + 1e-5f) * bnscale[col]
                    + bnbias[col];
                v = fmaxf(v, 0.0f) + xres[(size_t)row * N + col];
            }
            if (OBF16)
                ((__nv_bfloat16*)Cout)[(size_t)row * N + col] = __float2bfloat16(v);
            else
                ((float*)Cout)[(size_t)row * N + col] = v;
        }
    }
}

// ---------------------------------------------------------------------------
// Row softmax stats over bf16 S: one block per row (4096 elems).
// ---------------------------------------------------------------------------
__global__ void __launch_bounds__(256)
rowstats_kernel(const __nv_bfloat16* __restrict__ S,
                float* __restrict__ rowm, float* __restrict__ rowinvl)
{
    __shared__ float buf[4096];
    __shared__ float red[33];
    const int row = blockIdx.x;
    const __nv_bfloat16* Sr = S + (size_t)row * 4096;
    const int tid = threadIdx.x;

    float mx = -3.0e38f;
    for (int c = tid; c < 512; c += 256) {
        uint4 u = ((const uint4*)Sr)[c];
        float2 f0 = __bfloat1622float2(reinterpret_cast<__nv_bfloat162&>(u.x));
        float2 f1 = __bfloat1622float2(reinterpret_cast<__nv_bfloat162&>(u.y));
        float2 f2 = __bfloat1622float2(reinterpret_cast<__nv_bfloat162&>(u.z));
        float2 f3 = __bfloat1622float2(reinterpret_cast<__nv_bfloat162&>(u.w));
        float* bp = &buf[c * 8];
        bp[0] = f0.x; bp[1] = f0.y; bp[2] = f1.x; bp[3] = f1.y;
        bp[4] = f2.x; bp[5] = f2.y; bp[6] = f3.x; bp[7] = f3.y;
        mx = fmaxf(mx, fmaxf(fmaxf(f0.x, f0.y), fmaxf(f1.x, f1.y)));
        mx = fmaxf(mx, fmaxf(fmaxf(f2.x, f2.y), fmaxf(f3.x, f3.y)));
    }
#pragma unroll
    for (int o = 16; o > 0; o >>= 1)
        mx = fmaxf(mx, __shfl_xor_sync(0xffffffffu, mx, o));
    if ((tid & 31) == 0) red[tid >> 5] = mx;
    __syncthreads();
    if (tid < 32) {
        float v = (tid < 8) ? red[tid] : -3.0e38f;
#pragma unroll
        for (int o = 4; o > 0; o >>= 1)
            v = fmaxf(v, __shfl_xor_sync(0xffffffffu, v, o));
        if (tid == 0) red[32] = v;
    }
    __syncthreads();
    mx = red[32];

    float tot = 0.0f;
    for (int i = tid; i < 4096; i += 256) tot += fast_exp_neg(buf[i] - mx);
#pragma unroll
    for (int o = 16; o > 0; o >>= 1)
        tot += __shfl_xor_sync(0xffffffffu, tot, o);
    if ((tid & 31) == 0) red[tid >> 5] = tot;
    __syncthreads();
    if (tid == 0) {
        float t = 0.0f;
#pragma unroll
        for (int w = 0; w < 8; w++) t += red[w];
        rowm[row]    = mx;
        rowinvl[row] = 1.0f / t;
    }
}

// ---------------------------------------------------------------------------
// Column sums of normalized attention (bf16 S), two-stage deterministic.
// ---------------------------------------------------------------------------
__global__ void __launch_bounds__(256)
colsum_part_kernel(const __nv_bfloat16* __restrict__ S,
                   const float* __restrict__ rowm,
                   const float* __restrict__ rowinvl,
                   float* __restrict__ cpart)
{
    __shared__ float sm[512], si[512];
    const int b     = blockIdx.z;
    const int n     = blockIdx.x * 256 + threadIdx.x;
    const int m0    = blockIdx.y * 512;
    const int rbase = b * 4096;
    for (int i = threadIdx.x; i < 512; i += 256) {
        sm[i] = rowm[rbase + m0 + i];
        si[i] = rowinvl[rbase + m0 + i];
    }
    __syncthreads();
    const __nv_bfloat16* Sb = S + (size_t)b * SBATCH + (size_t)m0 * 4096 + n;
    float acc = 0.0f;
#pragma unroll 4
    for (int mm = 0; mm < 512; mm++)
        acc += fast_exp_neg(__bfloat162float(Sb[(size_t)mm * 4096]) - sm[mm]) * si[mm];
    cpart[(size_t)blockIdx.y * MM + rbase + n] = acc;
}

__global__ void __launch_bounds__(256)
colsum_final_kernel(const float* __restrict__ cpart, float* __restrict__ srow)
{
    const int i = blockIdx.x * 256 + threadIdx.x;
    float c = 0.0f;
#pragma unroll
    for (int p = 0; p < 8; p++) c += cpart[(size_t)p * MM + i];
    srow[i] = c / (c + 1e-9f);
}

// ---------------------------------------------------------------------------
extern "C" void kernel_launch(void* const* d_in, const int* in_sizes, int n_in,
                              void* d_out, int out_size)
{
    // metadata order: inputs, Wq, Wk, Wv, Wo, bq, bk, bv, bo, bn_* (two loops!)
    const float* x   = (const float*)d_in[0];
    const float* Wq  = (const float*)d_in[1];
    const float* Wk  = (const float*)d_in[2];
    const float* Wv  = (const float*)d_in[3];
    const float* Wo  = (const float*)d_in[4];
    const float* bq  = (const float*)d_in[5];
    const float* bk  = (const float*)d_in[6];
    const float* bv  = (const float*)d_in[7];
    const float* bo  = (const float*)d_in[8];
    const float* bns = (const float*)d_in[9];
    const float* bnb = (const float*)d_in[10];
    const float* bnm = (const float*)d_in[11];
    const float* bnv = (const float*)d_in[12];
    float* out = (float*)d_out;

    void *qh, *kh, *v, *S, *rowm, *rowinvl, *cpart, *srow;
    cudaGetSymbolAddress(&qh,      g_qh);
    cudaGetSymbolAddress(&kh,      g_kh);
    cudaGetSymbolAddress(&v,       g_v);
    cudaGetSymbolAddress(&S,       g_S);
    cudaGetSymbolAddress(&rowm,    g_rowm);
    cudaGetSymbolAddress(&rowinvl, g_rowinvl);
    cudaGetSymbolAddress(&cpart,   g_cpart);
    cudaGetSymbolAddress(&srow,    g_srow);

    dim3 blk(256);
    dim3 gProj(CC / 128, MM / 128, 1);        // (4, 64)

    // K1: projections. q,k -> bf16; v -> fp32.
    sgemm_kernel<0, true><<<gProj, blk>>>(x, Wq, qh, CC, CC,
        bq, nullptr, nullptr, nullptr, nullptr, nullptr, nullptr);
    sgemm_kernel<0, true><<<gProj, blk>>>(x, Wk, kh, CC, CC,
        bk, nullptr, nullptr, nullptr, nullptr, nullptr, nullptr);
    sgemm_kernel<0, false><<<gProj, blk>>>(x, Wv, v, CC, CC,
        bv, nullptr, nullptr, nullptr, nullptr, nullptr, nullptr);

    // K2: S = q @ k^T per batch (mma.sync bf16, fp32 accum, bf16 out)
    qk_mma_kernel<<<dim3(32, 32, 2), blk>>>(
        (const __nv_bfloat16*)qh, (const __nv_bfloat16*)kh, (__nv_bfloat16*)S);

    // K3: per-row softmax stats
    rowstats_kernel<<<MM, blk>>>((const __nv_bfloat16*)S,
                                 (float*)rowm, (float*)rowinvl);

    // K4: column sums -> s[n]
    colsum_part_kernel<<<dim3(16, 8, 2), blk>>>((const __nv_bfloat16*)S,
        (const float*)rowm, (const float*)rowinvl, (float*)cpart);
    colsum_final_kernel<<<32, blk>>>((const float*)cpart, (float*)srow);

    // K5: out = relu(BN((v*s) @ Wo + bo)) + x   (fp32 for accuracy)
    sgemm_kernel<2, false><<<gProj, blk>>>((const float*)v, Wo, out, CC, CC,
        bo, (const float*)srow, x, bns, bnb, bnm, bnv);
}

// round 5
// speedup vs baseline: 4.6685x; 2.0001x over previous
#include <cuda_runtime.h>
#include <cuda_bf16.h>
#include <math.h>
#include <stdint.h>

// Problem dims (fixed by the dataset)
static constexpr int  BB  = 2;
static constexpr int  NN_ = 4096;
static constexpr int  CC  = 512;
static constexpr int  MM  = BB * NN_;               // 8192 rows total
static constexpr size_t SBATCH = (size_t)NN_ * NN_; // 16777216

// Scratch (device globals: no cudaMalloc allowed)
__device__ __align__(256) unsigned short g_xh[(size_t)MM * CC];  // bf16 x hi
__device__ __align__(256) unsigned short g_xl[(size_t)MM * CC];  // bf16 x lo
__device__ __align__(256) unsigned short g_qh[(size_t)MM * CC];  // bf16 q
__device__ __align__(256) unsigned short g_kh[(size_t)MM * CC];  // bf16 k
__device__ __align__(256) float          g_v [(size_t)MM * CC];  // fp32 v
__device__ __align__(256) unsigned short g_vsh[(size_t)MM * CC]; // bf16 v*s hi
__device__ __align__(256) unsigned short g_vsl[(size_t)MM * CC]; // bf16 v*s lo
__device__ __align__(256) unsigned short g_S [(size_t)BB * SBATCH]; // bf16 logits
// transposed weights [N x K] bf16
__device__ __align__(256) unsigned short g_WqT[CC * CC];
__device__ __align__(256) unsigned short g_WkT[CC * CC];
__device__ __align__(256) unsigned short g_WvhT[CC * CC];
__device__ __align__(256) unsigned short g_WvlT[CC * CC];
__device__ __align__(256) unsigned short g_WohT[CC * CC];
__device__ __align__(256) unsigned short g_WolT[CC * CC];
__device__ float g_rowm[MM];
__device__ float g_rowinvl[MM];
__device__ float g_cpart[8 * MM];
__device__ float g_srow[MM];

// ---------------------------------------------------------------------------
// PTX helpers (plain sm_103-compatible: mma.sync / ldmatrix / cp.async)
// ---------------------------------------------------------------------------
__device__ __forceinline__ uint32_t smem_u32(const void* p) {
    uint32_t a;
    asm("{ .reg .u64 t; cvta.to.shared.u64 t, %1; cvt.u32.u64 %0, t; }"
        : "=r"(a) : "l"(p));
    return a;
}
__device__ __forceinline__ void cp_async16(uint32_t dst, const void* src) {
    asm volatile("cp.async.cg.shared.global [%0], [%1], 16;"
                 :: "r"(dst), "l"(src) : "memory");
}
__device__ __forceinline__ void cp_commit() {
    asm volatile("cp.async.commit_group;" ::: "memory");
}
template<int N>
__device__ __forceinline__ void cp_wait() {
    asm volatile("cp.async.wait_group %0;" :: "n"(N) : "memory");
}
__device__ __forceinline__ void ldmatrix_x4(uint32_t& r0, uint32_t& r1,
                                            uint32_t& r2, uint32_t& r3,
                                            uint32_t addr) {
    asm volatile("ldmatrix.sync.aligned.m8n8.x4.shared.b16 {%0,%1,%2,%3}, [%4];"
                 : "=r"(r0), "=r"(r1), "=r"(r2), "=r"(r3) : "r"(addr));
}
__device__ __forceinline__ void mma_bf16(float& c0, float& c1, float& c2, float& c3,
                                         uint32_t a0, uint32_t a1, uint32_t a2, uint32_t a3,
                                         uint32_t b0, uint32_t b1) {
    asm volatile(
        "mma.sync.aligned.m16n8k16.row.col.f32.bf16.bf16.f32 "
        "{%0,%1,%2,%3}, {%4,%5,%6,%7}, {%8,%9}, {%0,%1,%2,%3};"
        : "+f"(c0), "+f"(c1), "+f"(c2), "+f"(c3)
        : "r"(a0), "r"(a1), "r"(a2), "r"(a3), "r"(b0), "r"(b1));
}

// smem tile layout: row-major [row][32 bf16] = 64B/row; 16B granules XOR-swizzled
__device__ __forceinline__ uint32_t sw_off(int row, int kg) {
    return (uint32_t)(row * 64 + ((kg ^ ((row >> 1) & 3)) << 4));
}

// FMA-only exp for x <= 0 (avoids MUFU throughput wall; ~1e-7 rel err)
__device__ __forceinline__ float fast_exp_neg(float x) {
    if (x < -87.0f) return 0.0f;
    float y = x * 1.4426950408889634f;
    float n = rintf(y);
    float f = y - n;
    float p = 1.5403530e-4f;
    p = fmaf(p, f, 1.3333558146e-3f);
    p = fmaf(p, f, 9.6181291918e-3f);
    p = fmaf(p, f, 5.5504108664e-2f);
    p = fmaf(p, f, 2.4022650696e-1f);
    p = fmaf(p, f, 6.9314718056e-1f);
    p = fmaf(p, f, 1.0f);
    int in = (int)n;
    return p * __int_as_float((in + 127) << 23);
}

// ---------------------------------------------------------------------------
// K2: S[b] = q[b] @ k[b]^T via mma.sync bf16. Block tile 128x128, BK=32,
// 8 warps (4M x 2N, warp tile 32x64), 3-stage cp.async pipeline.
// ---------------------------------------------------------------------------
__global__ void __launch_bounds__(256)
qk_mma_kernel(const __nv_bfloat16* __restrict__ Q,
              const __nv_bfloat16* __restrict__ Kmat,
              __nv_bfloat16* __restrict__ S)
{
    __shared__ __align__(1024) char smem[3 * 16384];
    const uint32_t sbase = smem_u32(smem);

    const int tid = threadIdx.x;
    const int wid = tid >> 5;
    const int lid = tid & 31;
    const int wm  = wid & 3;
    const int wn  = wid >> 2;
    const int n0  = blockIdx.x * 128;
    const int m0  = blockIdx.y * 128;
    const int bz  = blockIdx.z;

    const __nv_bfloat16* Qb = Q    + ((size_t)bz * NN_ + m0) * CC;
    const __nv_bfloat16* Kb = Kmat + ((size_t)bz * NN_ + n0) * CC;

    const int mgrp = lid >> 3;
    const int lr   = lid & 7;
    uint32_t aoff[2][2], boff[4][2];
#pragma unroll
    for (int mt = 0; mt < 2; mt++)
#pragma unroll
        for (int kh = 0; kh < 2; kh++) {
            int row = wm * 32 + mt * 16 + lr + ((mgrp & 1) << 3);
            int kg  = 2 * kh + (mgrp >> 1);
            aoff[mt][kh] = sw_off(row, kg);
        }
#pragma unroll
    for (int i = 0; i < 4; i++)
#pragma unroll
        for (int kh = 0; kh < 2; kh++) {
            int row = wn * 64 + i * 16 + lr + ((mgrp >> 1) << 3);
            int kg  = 2 * kh + (mgrp & 1);
            boff[i][kh] = 8192u + sw_off(row, kg);
        }

    float acc[2][8][4];
#pragma unroll
    for (int mt = 0; mt < 2; mt++)
#pragma unroll
        for (int nt = 0; nt < 8; nt++)
#pragma unroll
            for (int e = 0; e < 4; e++) acc[mt][nt][e] = 0.0f;

    auto load_stage = [&](int kb, int buf) {
        uint32_t dstb = sbase + buf * 16384;
#pragma unroll
        for (int it = 0; it < 2; it++) {
            int idx = tid + it * 256;
            int row = idx >> 2, kg = idx & 3;
            cp_async16(dstb + sw_off(row, kg), Qb + (size_t)row * CC + kb * 32 + kg * 8);
        }
#pragma unroll
        for (int it = 0; it < 2; it++) {
            int idx = tid + it * 256;
            int row = idx >> 2, kg = idx & 3;
            cp_async16(dstb + 8192 + sw_off(row, kg), Kb + (size_t)row * CC + kb * 32 + kg * 8);
        }
        cp_commit();
    };

    load_stage(0, 0);
    load_stage(1, 1);

    const int KB = CC / 32;
    for (int kb = 0; kb < KB; kb++) {
        const int buf = kb % 3;
        if (kb < KB - 1) cp_wait<1>(); else cp_wait<0>();
        __syncthreads();
        if (kb + 2 < KB) load_stage(kb + 2, (kb + 2) % 3);

        const uint32_t stb = sbase + buf * 16384;
#pragma unroll
        for (int kh = 0; kh < 2; kh++) {
            uint32_t af[2][4], bf[4][4];
#pragma unroll
            for (int mt = 0; mt < 2; mt++)
                ldmatrix_x4(af[mt][0], af[mt][1], af[mt][2], af[mt][3],
                            stb + aoff[mt][kh]);
#pragma unroll
            for (int i = 0; i < 4; i++)
                ldmatrix_x4(bf[i][0], bf[i][1], bf[i][2], bf[i][3],
                            stb + boff[i][kh]);
#pragma unroll
            for (int mt = 0; mt < 2; mt++)
#pragma unroll
                for (int i = 0; i < 4; i++) {
                    mma_bf16(acc[mt][2*i][0], acc[mt][2*i][1], acc[mt][2*i][2], acc[mt][2*i][3],
                             af[mt][0], af[mt][1], af[mt][2], af[mt][3],
                             bf[i][0], bf[i][1]);
                    mma_bf16(acc[mt][2*i+1][0], acc[mt][2*i+1][1], acc[mt][2*i+1][2], acc[mt][2*i+1][3],
                             af[mt][0], af[mt][1], af[mt][2], af[mt][3],
                             bf[i][2], bf[i][3]);
                }
        }
    }

    const int grow = lid >> 2;
    const int gcol = (lid & 3) * 2;
#pragma unroll
    for (int mt = 0; mt < 2; mt++) {
#pragma unroll
        for (int nt = 0; nt < 8; nt++) {
            const int col = n0 + wn * 64 + nt * 8 + gcol;
            const int rowa = m0 + wm * 32 + mt * 16 + grow;
            __nv_bfloat162 h0 = __float22bfloat162_rn(
                make_float2(acc[mt][nt][0], acc[mt][nt][1]));
            __nv_bfloat162 h1 = __float22bfloat162_rn(
                make_float2(acc[mt][nt][2], acc[mt][nt][3]));
            *(__nv_bfloat162*)(S + (size_t)bz * SBATCH + (size_t)rowa * NN_ + col) = h0;
            *(__nv_bfloat162*)(S + (size_t)bz * SBATCH + (size_t)(rowa + 8) * NN_ + col) = h1;
        }
    }
}

// ---------------------------------------------------------------------------
// Generic mma GEMM: C[M x N] = sum over TERMS of A-variants @ B-variants^T.
// A: [M x K] bf16 K-contig (hi, lo); B: [N x K] bf16 K-contig (hi, lo).
// TERMS=1: Ah@Bh.  TERMS=3: Ah@Bh + Ah@Bl + Al@Bh (split-bf16 fp32 emulation).
// EPI 0: +bias -> bf16 out. EPI 1: +bias -> fp32 out.
// EPI 2: +bias, BN, relu, +xres -> fp32 out.
// ---------------------------------------------------------------------------
template<int TERMS, int EPI>
__global__ void __launch_bounds__(256)
mma_gemm_kernel(const __nv_bfloat16* __restrict__ Ah,
                const __nv_bfloat16* __restrict__ Al,
                const __nv_bfloat16* __restrict__ Bh,
                const __nv_bfloat16* __restrict__ Bl,
                void* __restrict__ Cout, int N, int K,
                const float* __restrict__ bias,
                const float* __restrict__ xres,
                const float* __restrict__ bns,
                const float* __restrict__ bnb,
                const float* __restrict__ bnm,
                const float* __restrict__ bnv)
{
    constexpr int STAGE = (TERMS == 3) ? 32768 : 16384;
    constexpr uint32_t BOFF = (TERMS == 3) ? 16384u : 8192u;
    extern __shared__ __align__(1024) char smem[];
    const uint32_t sbase = smem_u32(smem);

    const int tid = threadIdx.x;
    const int wid = tid >> 5;
    const int lid = tid & 31;
    const int wm  = wid & 3;
    const int wn  = wid >> 2;
    const int n0  = blockIdx.x * 128;
    const int m0  = blockIdx.y * 128;

    const __nv_bfloat16* Ahb = Ah + (size_t)m0 * K;
    const __nv_bfloat16* Alb = (TERMS == 3) ? Al + (size_t)m0 * K : nullptr;
    const __nv_bfloat16* Bhb = Bh + (size_t)n0 * K;
    const __nv_bfloat16* Blb = (TERMS == 3) ? Bl + (size_t)n0 * K : nullptr;

    const int mgrp = lid >> 3;
    const int lr   = lid & 7;
    uint32_t aoff[2][2], boff[4][2];
#pragma unroll
    for (int mt = 0; mt < 2; mt++)
#pragma unroll
        for (int kh = 0; kh < 2; kh++) {
            int row = wm * 32 + mt * 16 + lr + ((mgrp & 1) << 3);
            int kg  = 2 * kh + (mgrp >> 1);
            aoff[mt][kh] = sw_off(row, kg);
        }
#pragma unroll
    for (int i = 0; i < 4; i++)
#pragma unroll
        for (int kh = 0; kh < 2; kh++) {
            int row = wn * 64 + i * 16 + lr + ((mgrp >> 1) << 3);
            int kg  = 2 * kh + (mgrp & 1);
            boff[i][kh] = BOFF + sw_off(row, kg);
        }

    float acc[2][8][4];
#pragma unroll
    for (int mt = 0; mt < 2; mt++)
#pragma unroll
        for (int nt = 0; nt < 8; nt++)
#pragma unroll
            for (int e = 0; e < 4; e++) acc[mt][nt][e] = 0.0f;

    auto load_stage = [&](int kb, int buf) {
        uint32_t dstb = sbase + buf * STAGE;
#pragma unroll
        for (int it = 0; it < 2; it++) {
            int idx = tid + it * 256;
            int row = idx >> 2, kg = idx & 3;
            size_t goff = (size_t)row * K + kb * 32 + kg * 8;
            uint32_t so = sw_off(row, kg);
            cp_async16(dstb + so, Ahb + goff);
            if (TERMS == 3) cp_async16(dstb + 8192u + so, Alb + goff);
            cp_async16(dstb + BOFF + so, Bhb + goff);
            if (TERMS == 3) cp_async16(dstb + BOFF + 8192u + so, Blb + goff);
        }
        cp_commit();
    };

    load_stage(0, 0);
    load_stage(1, 1);

    const int KB = K / 32;
    for (int kb = 0; kb < KB; kb++) {
        const int buf = kb % 3;
        if (kb < KB - 1) cp_wait<1>(); else cp_wait<0>();
        __syncthreads();
        if (kb + 2 < KB) load_stage(kb + 2, (kb + 2) % 3);

        const uint32_t stb = sbase + buf * STAGE;
#pragma unroll
        for (int kh = 0; kh < 2; kh++) {
            uint32_t afh[2][4], bfh[4][4];
            uint32_t afl[2][4], bfl[4][4];
#pragma unroll
            for (int mt = 0; mt < 2; mt++) {
                ldmatrix_x4(afh[mt][0], afh[mt][1], afh[mt][2], afh[mt][3],
                            stb + aoff[mt][kh]);
                if (TERMS == 3)
                    ldmatrix_x4(afl[mt][0], afl[mt][1], afl[mt][2], afl[mt][3],
                                stb + 8192u + aoff[mt][kh]);
            }
#pragma unroll
            for (int i = 0; i < 4; i++) {
                ldmatrix_x4(bfh[i][0], bfh[i][1], bfh[i][2], bfh[i][3],
                            stb + boff[i][kh]);
                if (TERMS == 3)
                    ldmatrix_x4(bfl[i][0], bfl[i][1], bfl[i][2], bfl[i][3],
                                stb + 8192u + boff[i][kh]);
            }
#pragma unroll
            for (int mt = 0; mt < 2; mt++)
#pragma unroll
                for (int i = 0; i < 4; i++) {
#pragma unroll
                    for (int h = 0; h < 2; h++) {
                        float* c0 = acc[mt][2*i + h];
                        mma_bf16(c0[0], c0[1], c0[2], c0[3],
                                 afh[mt][0], afh[mt][1], afh[mt][2], afh[mt][3],
                                 bfh[i][2*h], bfh[i][2*h + 1]);
                        if (TERMS == 3) {
                            mma_bf16(c0[0], c0[1], c0[2], c0[3],
                                     afh[mt][0], afh[mt][1], afh[mt][2], afh[mt][3],
                                     bfl[i][2*h], bfl[i][2*h + 1]);
                            mma_bf16(c0[0], c0[1], c0[2], c0[3],
                                     afl[mt][0], afl[mt][1], afl[mt][2], afl[mt][3],
                                     bfh[i][2*h], bfh[i][2*h + 1]);
                        }
                    }
                }
        }
    }

    const int grow = lid >> 2;
    const int gcol = (lid & 3) * 2;
#pragma unroll
    for (int mt = 0; mt < 2; mt++) {
#pragma unroll
        for (int nt = 0; nt < 8; nt++) {
            const int col  = n0 + wn * 64 + nt * 8 + gcol;
            const int rowa = m0 + wm * 32 + mt * 16 + grow;
            float b0 = bias[col], b1 = bias[col + 1];
            float v00 = acc[mt][nt][0] + b0, v01 = acc[mt][nt][1] + b1;
            float v10 = acc[mt][nt][2] + b0, v11 = acc[mt][nt][3] + b1;
            if (EPI == 0) {
                *(__nv_bfloat162*)((__nv_bfloat16*)Cout + (size_t)rowa * N + col)
                    = __float22bfloat162_rn(make_float2(v00, v01));
                *(__nv_bfloat162*)((__nv_bfloat16*)Cout + (size_t)(rowa + 8) * N + col)
                    = __float22bfloat162_rn(make_float2(v10, v11));
            } else if (EPI == 1) {
                *(float2*)((float*)Cout + (size_t)rowa * N + col)
                    = make_float2(v00, v01);
                *(float2*)((float*)Cout + (size_t)(rowa + 8) * N + col)
                    = make_float2(v10, v11);
            } else {
                float g0 = rsqrtf(bnv[col] + 1e-5f) * bns[col];
                float g1 = rsqrtf(bnv[col + 1] + 1e-5f) * bns[col + 1];
                float m0c = bnm[col], m1c = bnm[col + 1];
                float a0 = bnb[col], a1 = bnb[col + 1];
                v00 = fmaxf((v00 - m0c) * g0 + a0, 0.0f);
                v01 = fmaxf((v01 - m1c) * g1 + a1, 0.0f);
                v10 = fmaxf((v10 - m0c) * g0 + a0, 0.0f);
                v11 = fmaxf((v11 - m1c) * g1 + a1, 0.0f);
                float2 r0 = *(const float2*)(xres + (size_t)rowa * N + col);
                float2 r1 = *(const float2*)(xres + (size_t)(rowa + 8) * N + col);
                *(float2*)((float*)Cout + (size_t)rowa * N + col)
                    = make_float2(v00 + r0.x, v01 + r0.y);
                *(float2*)((float*)Cout + (size_t)(rowa + 8) * N + col)
                    = make_float2(v10 + r1.x, v11 + r1.y);
            }
        }
    }
}

// ---------------------------------------------------------------------------
// Prep kernels
// ---------------------------------------------------------------------------
// Split fp32 array into bf16 hi/lo. 4 elems/thread.
__global__ void __launch_bounds__(256)
split_kernel(const float* __restrict__ x,
             __nv_bfloat16* __restrict__ xh, __nv_bfloat16* __restrict__ xl)
{
    size_t i = ((size_t)blockIdx.x * 256 + threadIdx.x) * 4;
    float4 v = *(const float4*)(x + i);
    __nv_bfloat16 h0 = __float2bfloat16(v.x), h1 = __float2bfloat16(v.y);
    __nv_bfloat16 h2 = __float2bfloat16(v.z), h3 = __float2bfloat16(v.w);
    __nv_bfloat16 l0 = __float2bfloat16(v.x - __bfloat162float(h0));
    __nv_bfloat16 l1 = __float2bfloat16(v.y - __bfloat162float(h1));
    __nv_bfloat16 l2 = __float2bfloat16(v.z - __bfloat162float(h2));
    __nv_bfloat16 l3 = __float2bfloat16(v.w - __bfloat162float(h3));
    __nv_bfloat162 hp[2] = {{h0, h1}, {h2, h3}};
    __nv_bfloat162 lp[2] = {{l0, l1}, {l2, l3}};
    *(uint2*)(xh + i) = *(uint2*)hp;
    *(uint2*)(xl + i) = *(uint2*)lp;
}

// vs = v * srow[row]; split into bf16 hi/lo.
__global__ void __launch_bounds__(256)
split_vs_kernel(const float* __restrict__ v, const float* __restrict__ srow,
                __nv_bfloat16* __restrict__ vh, __nv_bfloat16* __restrict__ vl)
{
    size_t i = ((size_t)blockIdx.x * 256 + threadIdx.x) * 4;
    float s = srow[i >> 9];
    float4 x = *(const float4*)(v + i);
    x.x *= s; x.y *= s; x.z *= s; x.w *= s;
    __nv_bfloat16 h0 = __float2bfloat16(x.x), h1 = __float2bfloat16(x.y);
    __nv_bfloat16 h2 = __float2bfloat16(x.z), h3 = __float2bfloat16(x.w);
    __nv_bfloat16 l0 = __float2bfloat16(x.x - __bfloat162float(h0));
    __nv_bfloat16 l1 = __float2bfloat16(x.y - __bfloat162float(h1));
    __nv_bfloat16 l2 = __float2bfloat16(x.z - __bfloat162float(h2));
    __nv_bfloat16 l3 = __float2bfloat16(x.w - __bfloat162float(h3));
    __nv_bfloat162 hp[2] = {{h0, h1}, {h2, h3}};
    __nv_bfloat162 lp[2] = {{l0, l1}, {l2, l3}};
    *(uint2*)(vh + i) = *(uint2*)hp;
    *(uint2*)(vl + i) = *(uint2*)lp;
}

// Transpose 512x512 fp32 W [K x N] -> bf16 WT [N x K] hi (+ optional lo).
__global__ void __launch_bounds__(1024)
wprep_kernel(const float* __restrict__ W,
             __nv_bfloat16* __restrict__ Th, __nv_bfloat16* __restrict__ Tl)
{
    __shared__ float t[32][33];
    const int tx = threadIdx.x, ty = threadIdx.y;
    const int bx = blockIdx.x * 32, by = blockIdx.y * 32;
    t[ty][tx] = W[(size_t)(by + ty) * CC + bx + tx];   // k = by+ty, n = bx+tx
    __syncthreads();
    const int n = bx + ty, k = by + tx;
    float v = t[tx][ty];
    __nv_bfloat16 h = __float2bfloat16(v);
    Th[(size_t)n * CC + k] = h;
    if (Tl) Tl[(size_t)n * CC + k] = __float2bfloat16(v - __bfloat162float(h));
}

// ---------------------------------------------------------------------------
// Row softmax stats over bf16 S: one block per row (4096 elems).
// ---------------------------------------------------------------------------
__global__ void __launch_bounds__(256)
rowstats_kernel(const __nv_bfloat16* __restrict__ S,
                float* __restrict__ rowm, float* __restrict__ rowinvl)
{
    __shared__ float buf[4096];
    __shared__ float red[33];
    const int row = blockIdx.x;
    const __nv_bfloat16* Sr = S + (size_t)row * 4096;
    const int tid = threadIdx.x;

    float mx = -3.0e38f;
    for (int c = tid; c < 512; c += 256) {
        uint4 u = ((const uint4*)Sr)[c];
        float2 f0 = __bfloat1622float2(reinterpret_cast<__nv_bfloat162&>(u.x));
        float2 f1 = __bfloat1622float2(reinterpret_cast<__nv_bfloat162&>(u.y));
        float2 f2 = __bfloat1622float2(reinterpret_cast<__nv_bfloat162&>(u.z));
        float2 f3 = __bfloat1622float2(reinterpret_cast<__nv_bfloat162&>(u.w));
        float* bp = &buf[c * 8];
        bp[0] = f0.x; bp[1] = f0.y; bp[2] = f1.x; bp[3] = f1.y;
        bp[4] = f2.x; bp[5] = f2.y; bp[6] = f3.x; bp[7] = f3.y;
        mx = fmaxf(mx, fmaxf(fmaxf(f0.x, f0.y), fmaxf(f1.x, f1.y)));
        mx = fmaxf(mx, fmaxf(fmaxf(f2.x, f2.y), fmaxf(f3.x, f3.y)));
    }
#pragma unroll
    for (int o = 16; o > 0; o >>= 1)
        mx = fmaxf(mx, __shfl_xor_sync(0xffffffffu, mx, o));
    if ((tid & 31) == 0) red[tid >> 5] = mx;
    __syncthreads();
    if (tid < 32) {
        float v = (tid < 8) ? red[tid] : -3.0e38f;
#pragma unroll
        for (int o = 4; o > 0; o >>= 1)
            v = fmaxf(v, __shfl_xor_sync(0xffffffffu, v, o));
        if (tid == 0) red[32] = v;
    }
    __syncthreads();
    mx = red[32];

    float tot = 0.0f;
    for (int i = tid; i < 4096; i += 256) tot += fast_exp_neg(buf[i] - mx);
#pragma unroll
    for (int o = 16; o > 0; o >>= 1)
        tot += __shfl_xor_sync(0xffffffffu, tot, o);
    if ((tid & 31) == 0) red[tid >> 5] = tot;
    __syncthreads();
    if (tid == 0) {
        float t = 0.0f;
#pragma unroll
        for (int w = 0; w < 8; w++) t += red[w];
        rowm[row]    = mx;
        rowinvl[row] = 1.0f / t;
    }
}

// ---------------------------------------------------------------------------
// Column sums of normalized attention (bf16 S), two-stage deterministic.
// ---------------------------------------------------------------------------
__global__ void __launch_bounds__(256)
colsum_part_kernel(const __nv_bfloat16* __restrict__ S,
                   const float* __restrict__ rowm,
                   const float* __restrict__ rowinvl,
                   float* __restrict__ cpart)
{
    __shared__ float sm[512], si[512];
    const int b     = blockIdx.z;
    const int n     = blockIdx.x * 256 + threadIdx.x;
    const int m0    = blockIdx.y * 512;
    const int rbase = b * 4096;
    for (int i = threadIdx.x; i < 512; i += 256) {
        sm[i] = rowm[rbase + m0 + i];
        si[i] = rowinvl[rbase + m0 + i];
    }
    __syncthreads();
    const __nv_bfloat16* Sb = S + (size_t)b * SBATCH + (size_t)m0 * 4096 + n;
    float acc = 0.0f;
#pragma unroll 4
    for (int mm = 0; mm < 512; mm++)
        acc += fast_exp_neg(__bfloat162float(Sb[(size_t)mm * 4096]) - sm[mm]) * si[mm];
    cpart[(size_t)blockIdx.y * MM + rbase + n] = acc;
}

__global__ void __launch_bounds__(256)
colsum_final_kernel(const float* __restrict__ cpart, float* __restrict__ srow)
{
    const int i = blockIdx.x * 256 + threadIdx.x;
    float c = 0.0f;
#pragma unroll
    for (int p = 0; p < 8; p++) c += cpart[(size_t)p * MM + i];
    srow[i] = c / (c + 1e-9f);
}

// ---------------------------------------------------------------------------
extern "C" void kernel_launch(void* const* d_in, const int* in_sizes, int n_in,
                              void* d_out, int out_size)
{
    // metadata order: inputs, Wq, Wk, Wv, Wo, bq, bk, bv, bo, bn_* (two loops!)
    const float* x   = (const float*)d_in[0];
    const float* Wq  = (const float*)d_in[1];
    const float* Wk  = (const float*)d_in[2];
    const float* Wv  = (const float*)d_in[3];
    const float* Wo  = (const float*)d_in[4];
    const float* bq  = (const float*)d_in[5];
    const float* bk  = (const float*)d_in[6];
    const float* bv  = (const float*)d_in[7];
    const float* bo  = (const float*)d_in[8];
    const float* bns = (const float*)d_in[9];
    const float* bnb = (const float*)d_in[10];
    const float* bnm = (const float*)d_in[11];
    const float* bnv = (const float*)d_in[12];
    float* out = (float*)d_out;

    void *xh, *xl, *qh, *kh, *v, *vsh, *vsl, *S;
    void *WqT, *WkT, *WvhT, *WvlT, *WohT, *WolT;
    void *rowm, *rowinvl, *cpart, *srow;
    cudaGetSymbolAddress(&xh,   g_xh);   cudaGetSymbolAddress(&xl,   g_xl);
    cudaGetSymbolAddress(&qh,   g_qh);   cudaGetSymbolAddress(&kh,   g_kh);
    cudaGetSymbolAddress(&v,    g_v);
    cudaGetSymbolAddress(&vsh,  g_vsh);  cudaGetSymbolAddress(&vsl,  g_vsl);
    cudaGetSymbolAddress(&S,    g_S);
    cudaGetSymbolAddress(&WqT,  g_WqT);  cudaGetSymbolAddress(&WkT,  g_WkT);
    cudaGetSymbolAddress(&WvhT, g_WvhT); cudaGetSymbolAddress(&WvlT, g_WvlT);
    cudaGetSymbolAddress(&WohT, g_WohT); cudaGetSymbolAddress(&WolT, g_WolT);
    cudaGetSymbolAddress(&rowm,    g_rowm);
    cudaGetSymbolAddress(&rowinvl, g_rowinvl);
    cudaGetSymbolAddress(&cpart,   g_cpart);
    cudaGetSymbolAddress(&srow,    g_srow);

    static bool attr_done = false;
    if (!attr_done) {
        cudaFuncSetAttribute(mma_gemm_kernel<1, 0>,
            cudaFuncAttributeMaxDynamicSharedMemorySize, 49152);
        cudaFuncSetAttribute(mma_gemm_kernel<3, 1>,
            cudaFuncAttributeMaxDynamicSharedMemorySize, 98304);
        cudaFuncSetAttribute(mma_gemm_kernel<3, 2>,
            cudaFuncAttributeMaxDynamicSharedMemorySize, 98304);
        attr_done = true;
    }

    dim3 blk(256);
    dim3 gProj(CC / 128, MM / 128);           // (4, 64)
    dim3 wblk(32, 32);
    dim3 wgrd(16, 16);

    // P1: split x into bf16 hi/lo
    split_kernel<<<(MM * CC) / 1024, blk>>>(x, (__nv_bfloat16*)xh, (__nv_bfloat16*)xl);
    // P2: transpose+split weights
    wprep_kernel<<<wgrd, wblk>>>(Wq, (__nv_bfloat16*)WqT, nullptr);
    wprep_kernel<<<wgrd, wblk>>>(Wk, (__nv_bfloat16*)WkT, nullptr);
    wprep_kernel<<<wgrd, wblk>>>(Wv, (__nv_bfloat16*)WvhT, (__nv_bfloat16*)WvlT);
    wprep_kernel<<<wgrd, wblk>>>(Wo, (__nv_bfloat16*)WohT, (__nv_bfloat16*)WolT);

    // G1/G2: q,k projections (single bf16 term, bf16 out)
    mma_gemm_kernel<1, 0><<<gProj, blk, 49152>>>(
        (const __nv_bfloat16*)xh, nullptr, (const __nv_bfloat16*)WqT, nullptr,
        qh, CC, CC, bq, nullptr, nullptr, nullptr, nullptr, nullptr);
    mma_gemm_kernel<1, 0><<<gProj, blk, 49152>>>(
        (const __nv_bfloat16*)xh, nullptr, (const __nv_bfloat16*)WkT, nullptr,
        kh, CC, CC, bk, nullptr, nullptr, nullptr, nullptr, nullptr);
    // G3: v projection (split-bf16, fp32 out)
    mma_gemm_kernel<3, 1><<<gProj, blk, 98304>>>(
        (const __nv_bfloat16*)xh, (const __nv_bfloat16*)xl,
        (const __nv_bfloat16*)WvhT, (const __nv_bfloat16*)WvlT,
        v, CC, CC, bv, nullptr, nullptr, nullptr, nullptr, nullptr);

    // K2: S = q @ k^T per batch
    qk_mma_kernel<<<dim3(32, 32, 2), blk>>>(
        (const __nv_bfloat16*)qh, (const __nv_bfloat16*)kh, (__nv_bfloat16*)S);

    // K3: per-row softmax stats
    rowstats_kernel<<<MM, blk>>>((const __nv_bfloat16*)S,
                                 (float*)rowm, (float*)rowinvl);

    // K4: column sums -> s[n]
    colsum_part_kernel<<<dim3(16, 8, 2), blk>>>((const __nv_bfloat16*)S,
        (const float*)rowm, (const float*)rowinvl, (float*)cpart);
    colsum_final_kernel<<<32, blk>>>((const float*)cpart, (float*)srow);

    // P3: vs = v * s[row], split into bf16 hi/lo
    split_vs_kernel<<<(MM * CC) / 1024, blk>>>(
        (const float*)v, (const float*)srow,
        (__nv_bfloat16*)vsh, (__nv_bfloat16*)vsl);

    // G4: out = relu(BN(vs @ Wo + bo)) + x  (split-bf16, fp32 epilogue)
    mma_gemm_kernel<3, 2><<<gProj, blk, 98304>>>(
        (const __nv_bfloat16*)vsh, (const __nv_bfloat16*)vsl,
        (const __nv_bfloat16*)WohT, (const __nv_bfloat16*)WolT,
        out, CC, CC, bo, x, bns, bnb, bnm, bnv);
}

// round 6
// speedup vs baseline: 5.8603x; 1.2553x over previous
#include <cuda_runtime.h>
#include <cuda_bf16.h>
#include <math.h>
#include <stdint.h>

// Problem dims (fixed by the dataset)
static constexpr int  BB  = 2;
static constexpr int  NN_ = 4096;
static constexpr int  CC  = 512;
static constexpr int  MM  = BB * NN_;               // 8192 rows total
static constexpr size_t SBATCH = (size_t)NN_ * NN_; // 16777216

// Scratch (device globals: no cudaMalloc allowed)
__device__ __align__(256) unsigned short g_xh[(size_t)MM * CC];  // bf16 x hi
__device__ __align__(256) unsigned short g_xl[(size_t)MM * CC];  // bf16 x lo
__device__ __align__(256) unsigned short g_qh[(size_t)MM * CC];  // bf16 q
__device__ __align__(256) unsigned short g_kh[(size_t)MM * CC];  // bf16 k
__device__ __align__(256) float          g_v [(size_t)MM * CC];  // fp32 v
__device__ __align__(256) unsigned short g_vsh[(size_t)MM * CC]; // bf16 v*s hi
__device__ __align__(256) unsigned short g_vsl[(size_t)MM * CC]; // bf16 v*s lo
__device__ __align__(256) unsigned short g_S [(size_t)BB * SBATCH]; // bf16 logits
// transposed weights [N x K] bf16
__device__ __align__(256) unsigned short g_WqT[CC * CC];
__device__ __align__(256) unsigned short g_WkT[CC * CC];
__device__ __align__(256) unsigned short g_WvhT[CC * CC];
__device__ __align__(256) unsigned short g_WvlT[CC * CC];
__device__ __align__(256) unsigned short g_WohT[CC * CC];
__device__ __align__(256) unsigned short g_WolT[CC * CC];
// per-(row, n-tile) softmax partials (32 n-tiles per batch row)
__device__ float g_pm[32 * MM];
__device__ float g_pl[32 * MM];
__device__ float g_rowm[MM];
__device__ float g_rowinvl[MM];
__device__ float g_cpart[16 * MM];
__device__ float g_srow[MM];

// ---------------------------------------------------------------------------
// PTX helpers (plain sm_103-compatible: mma.sync / ldmatrix / cp.async)
// ---------------------------------------------------------------------------
__device__ __forceinline__ uint32_t smem_u32(const void* p) {
    uint32_t a;
    asm("{ .reg .u64 t; cvta.to.shared.u64 t, %1; cvt.u32.u64 %0, t; }"
        : "=r"(a) : "l"(p));
    return a;
}
__device__ __forceinline__ void cp_async16(uint32_t dst, const void* src) {
    asm volatile("cp.async.cg.shared.global [%0], [%1], 16;"
                 :: "r"(dst), "l"(src) : "memory");
}
__device__ __forceinline__ void cp_commit() {
    asm volatile("cp.async.commit_group;" ::: "memory");
}
template<int N>
__device__ __forceinline__ void cp_wait() {
    asm volatile("cp.async.wait_group %0;" :: "n"(N) : "memory");
}
__device__ __forceinline__ void ldmatrix_x4(uint32_t& r0, uint32_t& r1,
                                            uint32_t& r2, uint32_t& r3,
                                            uint32_t addr) {
    asm volatile("ldmatrix.sync.aligned.m8n8.x4.shared.b16 {%0,%1,%2,%3}, [%4];"
                 : "=r"(r0), "=r"(r1), "=r"(r2), "=r"(r3) : "r"(addr));
}
__device__ __forceinline__ void mma_bf16(float& c0, float& c1, float& c2, float& c3,
                                         uint32_t a0, uint32_t a1, uint32_t a2, uint32_t a3,
                                         uint32_t b0, uint32_t b1) {
    asm volatile(
        "mma.sync.aligned.m16n8k16.row.col.f32.bf16.bf16.f32 "
        "{%0,%1,%2,%3}, {%4,%5,%6,%7}, {%8,%9}, {%0,%1,%2,%3};"
        : "+f"(c0), "+f"(c1), "+f"(c2), "+f"(c3)
        : "r"(a0), "r"(a1), "r"(a2), "r"(a3), "r"(b0), "r"(b1));
}

// smem tile layout: row-major [row][32 bf16] = 64B/row; 16B granules XOR-swizzled
__device__ __forceinline__ uint32_t sw_off(int row, int kg) {
    return (uint32_t)(row * 64 + ((kg ^ ((row >> 1) & 3)) << 4));
}

// exp via MUFU ex2.approx (1 FMA + 1 MUFU; overlaps with FMA pipe).
// Large-negative inputs flush to 0 naturally.
__device__ __forceinline__ float fexp(float x) {
    float y = x * 1.4426950408889634f;
    float r;
    asm("ex2.approx.f32 %0, %1;" : "=f"(r) : "f"(y));
    return r;
}
// round fp32 -> bf16 -> fp32 (to keep stats exactly consistent with stored S)
__device__ __forceinline__ float rnd_bf(float a) {
    return __bfloat162float(__float2bfloat16(a));
}

// ---------------------------------------------------------------------------
// K2: S[b] = q[b] @ k[b]^T via mma.sync bf16. Block tile 128x128, BK=32,
// 8 warps (4M x 2N, warp tile 32x64), 3-stage cp.async pipeline.
// Fused epilogue: writes bf16 S AND per-tile softmax partials (rowmax, sumexp)
// computed from the bf16-ROUNDED values (exact consistency with stored S).
// ---------------------------------------------------------------------------
__global__ void __launch_bounds__(256, 2)
qk_mma_kernel(const __nv_bfloat16* __restrict__ Q,
              const __nv_bfloat16* __restrict__ Kmat,
              __nv_bfloat16* __restrict__ S,
              float* __restrict__ pm, float* __restrict__ pl)
{
    __shared__ __align__(1024) char smem[3 * 16384];
    const uint32_t sbase = smem_u32(smem);

    const int tid = threadIdx.x;
    const int wid = tid >> 5;
    const int lid = tid & 31;
    const int wm  = wid & 3;
    const int wn  = wid >> 2;
    const int n0  = blockIdx.x * 128;
    const int m0  = blockIdx.y * 128;
    const int bz  = blockIdx.z;

    const __nv_bfloat16* Qb = Q    + ((size_t)bz * NN_ + m0) * CC;
    const __nv_bfloat16* Kb = Kmat + ((size_t)bz * NN_ + n0) * CC;

    const int mgrp = lid >> 3;
    const int lr   = lid & 7;
    uint32_t aoff[2][2], boff[4][2];
#pragma unroll
    for (int mt = 0; mt < 2; mt++)
#pragma unroll
        for (int kh = 0; kh < 2; kh++) {
            int row = wm * 32 + mt * 16 + lr + ((mgrp & 1) << 3);
            int kg  = 2 * kh + (mgrp >> 1);
            aoff[mt][kh] = sw_off(row, kg);
        }
#pragma unroll
    for (int i = 0; i < 4; i++)
#pragma unroll
        for (int kh = 0; kh < 2; kh++) {
            int row = wn * 64 + i * 16 + lr + ((mgrp >> 1) << 3);
            int kg  = 2 * kh + (mgrp & 1);
            boff[i][kh] = 8192u + sw_off(row, kg);
        }

    float acc[2][8][4];
#pragma unroll
    for (int mt = 0; mt < 2; mt++)
#pragma unroll
        for (int nt = 0; nt < 8; nt++)
#pragma unroll
            for (int e = 0; e < 4; e++) acc[mt][nt][e] = 0.0f;

    auto load_stage = [&](int kb, int buf) {
        uint32_t dstb = sbase + buf * 16384;
#pragma unroll
        for (int it = 0; it < 2; it++) {
            int idx = tid + it * 256;
            int row = idx >> 2, kg = idx & 3;
            cp_async16(dstb + sw_off(row, kg), Qb + (size_t)row * CC + kb * 32 + kg * 8);
        }
#pragma unroll
        for (int it = 0; it < 2; it++) {
            int idx = tid + it * 256;
            int row = idx >> 2, kg = idx & 3;
            cp_async16(dstb + 8192 + sw_off(row, kg), Kb + (size_t)row * CC + kb * 32 + kg * 8);
        }
        cp_commit();
    };

    load_stage(0, 0);
    load_stage(1, 1);

    const int KB = CC / 32;
    for (int kb = 0; kb < KB; kb++) {
        const int buf = kb % 3;
        if (kb < KB - 1) cp_wait<1>(); else cp_wait<0>();
        __syncthreads();
        if (kb + 2 < KB) load_stage(kb + 2, (kb + 2) % 3);

        const uint32_t stb = sbase + buf * 16384;
#pragma unroll
        for (int kh = 0; kh < 2; kh++) {
            uint32_t af[2][4], bf[4][4];
#pragma unroll
            for (int mt = 0; mt < 2; mt++)
                ldmatrix_x4(af[mt][0], af[mt][1], af[mt][2], af[mt][3],
                            stb + aoff[mt][kh]);
#pragma unroll
            for (int i = 0; i < 4; i++)
                ldmatrix_x4(bf[i][0], bf[i][1], bf[i][2], bf[i][3],
                            stb + boff[i][kh]);
#pragma unroll
            for (int mt = 0; mt < 2; mt++)
#pragma unroll
                for (int i = 0; i < 4; i++) {
                    mma_bf16(acc[mt][2*i][0], acc[mt][2*i][1], acc[mt][2*i][2], acc[mt][2*i][3],
                             af[mt][0], af[mt][1], af[mt][2], af[mt][3],
                             bf[i][0], bf[i][1]);
                    mma_bf16(acc[mt][2*i+1][0], acc[mt][2*i+1][1], acc[mt][2*i+1][2], acc[mt][2*i+1][3],
                             af[mt][0], af[mt][1], af[mt][2], af[mt][3],
                             bf[i][2], bf[i][3]);
                }
        }
    }

    __syncthreads();   // pipeline smem now reusable for reductions

    float* s_red = (float*)smem;        // [128][2] per-(row, wn) max
    float* s_tm  = s_red + 256;         // [128] tile row max
    float* s_l   = s_tm + 128;          // [128][2] per-(row, wn) sumexp

    const int grow = lid >> 2;
    const int gcol = (lid & 3) * 2;

    // Sweep 1: per-thread row maxes over bf16-rounded values
    float pmax[2][2];
#pragma unroll
    for (int mt = 0; mt < 2; mt++) { pmax[mt][0] = -3.0e38f; pmax[mt][1] = -3.0e38f; }
#pragma unroll
    for (int mt = 0; mt < 2; mt++)
#pragma unroll
        for (int nt = 0; nt < 8; nt++) {
            float r00 = rnd_bf(acc[mt][nt][0]), r01 = rnd_bf(acc[mt][nt][1]);
            float r10 = rnd_bf(acc[mt][nt][2]), r11 = rnd_bf(acc[mt][nt][3]);
            pmax[mt][0] = fmaxf(pmax[mt][0], fmaxf(r00, r01));
            pmax[mt][1] = fmaxf(pmax[mt][1], fmaxf(r10, r11));
        }
#pragma unroll
    for (int mt = 0; mt < 2; mt++)
#pragma unroll
        for (int h = 0; h < 2; h++) {
            float v = pmax[mt][h];
            v = fmaxf(v, __shfl_xor_sync(0xffffffffu, v, 1));
            v = fmaxf(v, __shfl_xor_sync(0xffffffffu, v, 2));
            if ((lid & 3) == 0)
                s_red[(wm * 32 + mt * 16 + h * 8 + grow) * 2 + wn] = v;
        }
    __syncthreads();
    if (tid < 128) s_tm[tid] = fmaxf(s_red[tid * 2], s_red[tid * 2 + 1]);
    __syncthreads();

    // Sweep 2: store bf16 S + per-thread sumexp with tile max
    float psum[2][2] = {{0.0f, 0.0f}, {0.0f, 0.0f}};
#pragma unroll
    for (int mt = 0; mt < 2; mt++) {
        const float tm0 = s_tm[wm * 32 + mt * 16 + grow];
        const float tm1 = s_tm[wm * 32 + mt * 16 + 8 + grow];
        const int rowa = m0 + wm * 32 + mt * 16 + grow;
#pragma unroll
        for (int nt = 0; nt < 8; nt++) {
            const int col = n0 + wn * 64 + nt * 8 + gcol;
            __nv_bfloat162 h0 = __float22bfloat162_rn(
                make_float2(acc[mt][nt][0], acc[mt][nt][1]));
            __nv_bfloat162 h1 = __float22bfloat162_rn(
                make_float2(acc[mt][nt][2], acc[mt][nt][3]));
            *(__nv_bfloat162*)(S + (size_t)bz * SBATCH + (size_t)rowa * NN_ + col) = h0;
            *(__nv_bfloat162*)(S + (size_t)bz * SBATCH + (size_t)(rowa + 8) * NN_ + col) = h1;
            float2 f0 = __bfloat1622float2(h0);
            float2 f1 = __bfloat1622float2(h1);
            psum[mt][0] += fexp(f0.x - tm0) + fexp(f0.y - tm0);
            psum[mt][1] += fexp(f1.x - tm1) + fexp(f1.y - tm1);
        }
    }
#pragma unroll
    for (int mt = 0; mt < 2; mt++)
#pragma unroll
        for (int h = 0; h < 2; h++) {
            float v = psum[mt][h];
            v += __shfl_xor_sync(0xffffffffu, v, 1);
            v += __shfl_xor_sync(0xffffffffu, v, 2);
            if ((lid & 3) == 0)
                s_l[(wm * 32 + mt * 16 + h * 8 + grow) * 2 + wn] = v;
        }
    __syncthreads();
    if (tid < 128) {
        const size_t brow = (size_t)bz * NN_ + m0 + tid;
        pm[(size_t)blockIdx.x * MM + brow] = s_tm[tid];
        pl[(size_t)blockIdx.x * MM + brow] = s_l[tid * 2] + s_l[tid * 2 + 1];
    }
}

// Combine 32 per-tile partials into rowm / rowinvl.
__global__ void __launch_bounds__(256)
combine_kernel(const float* __restrict__ pm, const float* __restrict__ pl,
               float* __restrict__ rowm, float* __restrict__ rowinvl)
{
    const int r = blockIdx.x * 256 + threadIdx.x;
    float M = -3.0e38f;
#pragma unroll
    for (int t = 0; t < 32; t++) M = fmaxf(M, pm[(size_t)t * MM + r]);
    float L = 0.0f;
#pragma unroll
    for (int t = 0; t < 32; t++)
        L += pl[(size_t)t * MM + r] * fexp(pm[(size_t)t * MM + r] - M);
    rowm[r] = M;
    rowinvl[r] = 1.0f / L;
}

// ---------------------------------------------------------------------------
// Generic mma GEMM: C[M x N] = sum over TERMS of A-variants @ B-variants^T.
// TERMS=1: Ah@Bh.  TERMS=3: Ah@Bh + Ah@Bl + Al@Bh (split-bf16 fp32 emulation).
// EPI 0: +bias -> bf16 out. EPI 1: +bias -> fp32 out.
// EPI 2: +bias, BN, relu, +xres -> fp32 out.
// ---------------------------------------------------------------------------
template<int TERMS, int EPI>
__global__ void __launch_bounds__(256)
mma_gemm_kernel(const __nv_bfloat16* __restrict__ Ah,
                const __nv_bfloat16* __restrict__ Al,
                const __nv_bfloat16* __restrict__ Bh,
                const __nv_bfloat16* __restrict__ Bl,
                void* __restrict__ Cout, int N, int K,
                const float* __restrict__ bias,
                const float* __restrict__ xres,
                const float* __restrict__ bns,
                const float* __restrict__ bnb,
                const float* __restrict__ bnm,
                const float* __restrict__ bnv)
{
    constexpr int STAGE = (TERMS == 3) ? 32768 : 16384;
    constexpr uint32_t BOFF = (TERMS == 3) ? 16384u : 8192u;
    extern __shared__ __align__(1024) char smem[];
    const uint32_t sbase = smem_u32(smem);

    const int tid = threadIdx.x;
    const int wid = tid >> 5;
    const int lid = tid & 31;
    const int wm  = wid & 3;
    const int wn  = wid >> 2;
    const int n0  = blockIdx.x * 128;
    const int m0  = blockIdx.y * 128;

    const __nv_bfloat16* Ahb = Ah + (size_t)m0 * K;
    const __nv_bfloat16* Alb = (TERMS == 3) ? Al + (size_t)m0 * K : nullptr;
    const __nv_bfloat16* Bhb = Bh + (size_t)n0 * K;
    const __nv_bfloat16* Blb = (TERMS == 3) ? Bl + (size_t)n0 * K : nullptr;

    const int mgrp = lid >> 3;
    const int lr   = lid & 7;
    uint32_t aoff[2][2], boff[4][2];
#pragma unroll
    for (int mt = 0; mt < 2; mt++)
#pragma unroll
        for (int kh = 0; kh < 2; kh++) {
            int row = wm * 32 + mt * 16 + lr + ((mgrp & 1) << 3);
            int kg  = 2 * kh + (mgrp >> 1);
            aoff[mt][kh] = sw_off(row, kg);
        }
#pragma unroll
    for (int i = 0; i < 4; i++)
#pragma unroll
        for (int kh = 0; kh < 2; kh++) {
            int row = wn * 64 + i * 16 + lr + ((mgrp >> 1) << 3);
            int kg  = 2 * kh + (mgrp & 1);
            boff[i][kh] = BOFF + sw_off(row, kg);
        }

    float acc[2][8][4];
#pragma unroll
    for (int mt = 0; mt < 2; mt++)
#pragma unroll
        for (int nt = 0; nt < 8; nt++)
#pragma unroll
            for (int e = 0; e < 4; e++) acc[mt][nt][e] = 0.0f;

    auto load_stage = [&](int kb, int buf) {
        uint32_t dstb = sbase + buf * STAGE;
#pragma unroll
        for (int it = 0; it < 2; it++) {
            int idx = tid + it * 256;
            int row = idx >> 2, kg = idx & 3;
            size_t goff = (size_t)row * K + kb * 32 + kg * 8;
            uint32_t so = sw_off(row, kg);
            cp_async16(dstb + so, Ahb + goff);
            if (TERMS == 3) cp_async16(dstb + 8192u + so, Alb + goff);
            cp_async16(dstb + BOFF + so, Bhb + goff);
            if (TERMS == 3) cp_async16(dstb + BOFF + 8192u + so, Blb + goff);
        }
        cp_commit();
    };

    load_stage(0, 0);
    load_stage(1, 1);

    const int KB = K / 32;
    for (int kb = 0; kb < KB; kb++) {
        const int buf = kb % 3;
        if (kb < KB - 1) cp_wait<1>(); else cp_wait<0>();
        __syncthreads();
        if (kb + 2 < KB) load_stage(kb + 2, (kb + 2) % 3);

        const uint32_t stb = sbase + buf * STAGE;
#pragma unroll
        for (int kh = 0; kh < 2; kh++) {
            uint32_t afh[2][4], bfh[4][4];
            uint32_t afl[2][4], bfl[4][4];
#pragma unroll
            for (int mt = 0; mt < 2; mt++) {
                ldmatrix_x4(afh[mt][0], afh[mt][1], afh[mt][2], afh[mt][3],
                            stb + aoff[mt][kh]);
                if (TERMS == 3)
                    ldmatrix_x4(afl[mt][0], afl[mt][1], afl[mt][2], afl[mt][3],
                                stb + 8192u + aoff[mt][kh]);
            }
#pragma unroll
            for (int i = 0; i < 4; i++) {
                ldmatrix_x4(bfh[i][0], bfh[i][1], bfh[i][2], bfh[i][3],
                            stb + boff[i][kh]);
                if (TERMS == 3)
                    ldmatrix_x4(bfl[i][0], bfl[i][1], bfl[i][2], bfl[i][3],
                                stb + 8192u + boff[i][kh]);
            }
#pragma unroll
            for (int mt = 0; mt < 2; mt++)
#pragma unroll
                for (int i = 0; i < 4; i++) {
#pragma unroll
                    for (int h = 0; h < 2; h++) {
                        float* c0 = acc[mt][2*i + h];
                        mma_bf16(c0[0], c0[1], c0[2], c0[3],
                                 afh[mt][0], afh[mt][1], afh[mt][2], afh[mt][3],
                                 bfh[i][2*h], bfh[i][2*h + 1]);
                        if (TERMS == 3) {
                            mma_bf16(c0[0], c0[1], c0[2], c0[3],
                                     afh[mt][0], afh[mt][1], afh[mt][2], afh[mt][3],
                                     bfl[i][2*h], bfl[i][2*h + 1]);
                            mma_bf16(c0[0], c0[1], c0[2], c0[3],
                                     afl[mt][0], afl[mt][1], afl[mt][2], afl[mt][3],
                                     bfh[i][2*h], bfh[i][2*h + 1]);
                        }
                    }
                }
        }
    }

    const int grow = lid >> 2;
    const int gcol = (lid & 3) * 2;
#pragma unroll
    for (int mt = 0; mt < 2; mt++) {
#pragma unroll
        for (int nt = 0; nt < 8; nt++) {
            const int col  = n0 + wn * 64 + nt * 8 + gcol;
            const int rowa = m0 + wm * 32 + mt * 16 + grow;
            float b0 = bias[col], b1 = bias[col + 1];
            float v00 = acc[mt][nt][0] + b0, v01 = acc[mt][nt][1] + b1;
            float v10 = acc[mt][nt][2] + b0, v11 = acc[mt][nt][3] + b1;
            if (EPI == 0) {
                *(__nv_bfloat162*)((__nv_bfloat16*)Cout + (size_t)rowa * N + col)
                    = __float22bfloat162_rn(make_float2(v00, v01));
                *(__nv_bfloat162*)((__nv_bfloat16*)Cout + (size_t)(rowa + 8) * N + col)
                    = __float22bfloat162_rn(make_float2(v10, v11));
            } else if (EPI == 1) {
                *(float2*)((float*)Cout + (size_t)rowa * N + col)
                    = make_float2(v00, v01);
                *(float2*)((float*)Cout + (size_t)(rowa + 8) * N + col)
                    = make_float2(v10, v11);
            } else {
                float g0 = rsqrtf(bnv[col] + 1e-5f) * bns[col];
                float g1 = rsqrtf(bnv[col + 1] + 1e-5f) * bns[col + 1];
                float m0c = bnm[col], m1c = bnm[col + 1];
                float a0 = bnb[col], a1 = bnb[col + 1];
                v00 = fmaxf((v00 - m0c) * g0 + a0, 0.0f);
                v01 = fmaxf((v01 - m1c) * g1 + a1, 0.0f);
                v10 = fmaxf((v10 - m0c) * g0 + a0, 0.0f);
                v11 = fmaxf((v11 - m1c) * g1 + a1, 0.0f);
                float2 r0 = *(const float2*)(xres + (size_t)rowa * N + col);
                float2 r1 = *(const float2*)(xres + (size_t)(rowa + 8) * N + col);
                *(float2*)((float*)Cout + (size_t)rowa * N + col)
                    = make_float2(v00 + r0.x, v01 + r0.y);
                *(float2*)((float*)Cout + (size_t)(rowa + 8) * N + col)
                    = make_float2(v10 + r1.x, v11 + r1.y);
            }
        }
    }
}

// ---------------------------------------------------------------------------
// Prep kernels
// ---------------------------------------------------------------------------
__global__ void __launch_bounds__(256)
split_kernel(const float* __restrict__ x,
             __nv_bfloat16* __restrict__ xh, __nv_bfloat16* __restrict__ xl)
{
    size_t i = ((size_t)blockIdx.x * 256 + threadIdx.x) * 4;
    float4 v = *(const float4*)(x + i);
    __nv_bfloat16 h0 = __float2bfloat16(v.x), h1 = __float2bfloat16(v.y);
    __nv_bfloat16 h2 = __float2bfloat16(v.z), h3 = __float2bfloat16(v.w);
    __nv_bfloat16 l0 = __float2bfloat16(v.x - __bfloat162float(h0));
    __nv_bfloat16 l1 = __float2bfloat16(v.y - __bfloat162float(h1));
    __nv_bfloat16 l2 = __float2bfloat16(v.z - __bfloat162float(h2));
    __nv_bfloat16 l3 = __float2bfloat16(v.w - __bfloat162float(h3));
    __nv_bfloat162 hp[2] = {{h0, h1}, {h2, h3}};
    __nv_bfloat162 lp[2] = {{l0, l1}, {l2, l3}};
    *(uint2*)(xh + i) = *(uint2*)hp;
    *(uint2*)(xl + i) = *(uint2*)lp;
}

__global__ void __launch_bounds__(256)
split_vs_kernel(const float* __restrict__ v, const float* __restrict__ srow,
                __nv_bfloat16* __restrict__ vh, __nv_bfloat16* __restrict__ vl)
{
    size_t i = ((size_t)blockIdx.x * 256 + threadIdx.x) * 4;
    float s = srow[i >> 9];
    float4 x = *(const float4*)(v + i);
    x.x *= s; x.y *= s; x.z *= s; x.w *= s;
    __nv_bfloat16 h0 = __float2bfloat16(x.x), h1 = __float2bfloat16(x.y);
    __nv_bfloat16 h2 = __float2bfloat16(x.z), h3 = __float2bfloat16(x.w);
    __nv_bfloat16 l0 = __float2bfloat16(x.x - __bfloat162float(h0));
    __nv_bfloat16 l1 = __float2bfloat16(x.y - __bfloat162float(h1));
    __nv_bfloat16 l2 = __float2bfloat16(x.z - __bfloat162float(h2));
    __nv_bfloat16 l3 = __float2bfloat16(x.w - __bfloat162float(h3));
    __nv_bfloat162 hp[2] = {{h0, h1}, {h2, h3}};
    __nv_bfloat162 lp[2] = {{l0, l1}, {l2, l3}};
    *(uint2*)(vh + i) = *(uint2*)hp;
    *(uint2*)(vl + i) = *(uint2*)lp;
}

// Transpose+split all 4 weights in ONE launch (z selects the weight).
__global__ void __launch_bounds__(1024)
wprep_all_kernel(const float* __restrict__ Wq, const float* __restrict__ Wk,
                 const float* __restrict__ Wv, const float* __restrict__ Wo,
                 __nv_bfloat16* __restrict__ WqT, __nv_bfloat16* __restrict__ WkT,
                 __nv_bfloat16* __restrict__ WvhT, __nv_bfloat16* __restrict__ WvlT,
                 __nv_bfloat16* __restrict__ WohT, __nv_bfloat16* __restrict__ WolT)
{
    const float* W;
    __nv_bfloat16 *Th, *Tl = nullptr;
    switch (blockIdx.z) {
        case 0:  W = Wq; Th = WqT;  break;
        case 1:  W = Wk; Th = WkT;  break;
        case 2:  W = Wv; Th = WvhT; Tl = WvlT; break;
        default: W = Wo; Th = WohT; Tl = WolT; break;
    }
    __shared__ float t[32][33];
    const int tx = threadIdx.x, ty = threadIdx.y;
    const int bx = blockIdx.x * 32, by = blockIdx.y * 32;
    t[ty][tx] = W[(size_t)(by + ty) * CC + bx + tx];
    __syncthreads();
    const int n = bx + ty, k = by + tx;
    float v = t[tx][ty];
    __nv_bfloat16 h = __float2bfloat16(v);
    Th[(size_t)n * CC + k] = h;
    if (Tl) Tl[(size_t)n * CC + k] = __float2bfloat16(v - __bfloat162float(h));
}

// ---------------------------------------------------------------------------
// Column sums of normalized attention (bf16 S), 16-way m-split, 2 cols/thread.
// ---------------------------------------------------------------------------
__global__ void __launch_bounds__(256)
colsum_part_kernel(const __nv_bfloat16* __restrict__ S,
                   const float* __restrict__ rowm,
                   const float* __restrict__ rowinvl,
                   float* __restrict__ cpart)
{
    __shared__ float sm[256], si[256];
    const int b     = blockIdx.z;
    const int n     = blockIdx.x * 512 + threadIdx.x * 2;
    const int m0    = blockIdx.y * 256;
    const int rbase = b * 4096;
    sm[threadIdx.x] = rowm[rbase + m0 + threadIdx.x];
    si[threadIdx.x] = rowinvl[rbase + m0 + threadIdx.x];
    __syncthreads();
    const __nv_bfloat16* Sb = S + (size_t)b * SBATCH + (size_t)m0 * 4096 + n;
    float a0 = 0.0f, a1 = 0.0f;
#pragma unroll 8
    for (int mm = 0; mm < 256; mm++) {
        __nv_bfloat162 h = *(const __nv_bfloat162*)(Sb + (size_t)mm * 4096);
        float2 f = __bfloat1622float2(h);
        float m = sm[mm], iv = si[mm];
        a0 += fexp(f.x - m) * iv;
        a1 += fexp(f.y - m) * iv;
    }
    *(float2*)(cpart + (size_t)blockIdx.y * MM + rbase + n) = make_float2(a0, a1);
}

__global__ void __launch_bounds__(256)
colsum_final_kernel(const float* __restrict__ cpart, float* __restrict__ srow)
{
    const int i = blockIdx.x * 256 + threadIdx.x;
    float c = 0.0f;
#pragma unroll
    for (int p = 0; p < 16; p++) c += cpart[(size_t)p * MM + i];
    srow[i] = c / (c + 1e-9f);
}

// ---------------------------------------------------------------------------
extern "C" void kernel_launch(void* const* d_in, const int* in_sizes, int n_in,
                              void* d_out, int out_size)
{
    // metadata order: inputs, Wq, Wk, Wv, Wo, bq, bk, bv, bo, bn_* (two loops!)
    const float* x   = (const float*)d_in[0];
    const float* Wq  = (const float*)d_in[1];
    const float* Wk  = (const float*)d_in[2];
    const float* Wv  = (const float*)d_in[3];
    const float* Wo  = (const float*)d_in[4];
    const float* bq  = (const float*)d_in[5];
    const float* bk  = (const float*)d_in[6];
    const float* bv  = (const float*)d_in[7];
    const float* bo  = (const float*)d_in[8];
    const float* bns = (const float*)d_in[9];
    const float* bnb = (const float*)d_in[10];
    const float* bnm = (const float*)d_in[11];
    const float* bnv = (const float*)d_in[12];
    float* out = (float*)d_out;

    void *xh, *xl, *qh, *kh, *v, *vsh, *vsl, *S;
    void *WqT, *WkT, *WvhT, *WvlT, *WohT, *WolT;
    void *pm, *pl, *rowm, *rowinvl, *cpart, *srow;
    cudaGetSymbolAddress(&xh,   g_xh);   cudaGetSymbolAddress(&xl,   g_xl);
    cudaGetSymbolAddress(&qh,   g_qh);   cudaGetSymbolAddress(&kh,   g_kh);
    cudaGetSymbolAddress(&v,    g_v);
    cudaGetSymbolAddress(&vsh,  g_vsh);  cudaGetSymbolAddress(&vsl,  g_vsl);
    cudaGetSymbolAddress(&S,    g_S);
    cudaGetSymbolAddress(&WqT,  g_WqT);  cudaGetSymbolAddress(&WkT,  g_WkT);
    cudaGetSymbolAddress(&WvhT, g_WvhT); cudaGetSymbolAddress(&WvlT, g_WvlT);
    cudaGetSymbolAddress(&WohT, g_WohT); cudaGetSymbolAddress(&WolT, g_WolT);
    cudaGetSymbolAddress(&pm,      g_pm);
    cudaGetSymbolAddress(&pl,      g_pl);
    cudaGetSymbolAddress(&rowm,    g_rowm);
    cudaGetSymbolAddress(&rowinvl, g_rowinvl);
    cudaGetSymbolAddress(&cpart,   g_cpart);
    cudaGetSymbolAddress(&srow,    g_srow);

    static bool attr_done = false;
    if (!attr_done) {
        cudaFuncSetAttribute(mma_gemm_kernel<1, 0>,
            cudaFuncAttributeMaxDynamicSharedMemorySize, 49152);
        cudaFuncSetAttribute(mma_gemm_kernel<3, 1>,
            cudaFuncAttributeMaxDynamicSharedMemorySize, 98304);
        cudaFuncSetAttribute(mma_gemm_kernel<3, 2>,
            cudaFuncAttributeMaxDynamicSharedMemorySize, 98304);
        attr_done = true;
    }

    dim3 blk(256);
    dim3 gProj(CC / 128, MM / 128);           // (4, 64)

    // P1: split x into bf16 hi/lo
    split_kernel<<<(MM * CC) / 1024, blk>>>(x, (__nv_bfloat16*)xh, (__nv_bfloat16*)xl);
    // P2: transpose+split all weights (one launch)
    wprep_all_kernel<<<dim3(16, 16, 4), dim3(32, 32)>>>(
        Wq, Wk, Wv, Wo,
        (__nv_bfloat16*)WqT, (__nv_bfloat16*)WkT,
        (__nv_bfloat16*)WvhT, (__nv_bfloat16*)WvlT,
        (__nv_bfloat16*)WohT, (__nv_bfloat16*)WolT);

    // G1/G2: q,k projections (single bf16 term, bf16 out)
    mma_gemm_kernel<1, 0><<<gProj, blk, 49152>>>(
        (const __nv_bfloat16*)xh, nullptr, (const __nv_bfloat16*)WqT, nullptr,
        qh, CC, CC, bq, nullptr, nullptr, nullptr, nullptr, nullptr);
    mma_gemm_kernel<1, 0><<<gProj, blk, 49152>>>(
        (const __nv_bfloat16*)xh, nullptr, (const __nv_bfloat16*)WkT, nullptr,
        kh, CC, CC, bk, nullptr, nullptr, nullptr, nullptr, nullptr);
    // G3: v projection (split-bf16, fp32 out)
    mma_gemm_kernel<3, 1><<<gProj, blk, 98304>>>(
        (const __nv_bfloat16*)xh, (const __nv_bfloat16*)xl,
        (const __nv_bfloat16*)WvhT, (const __nv_bfloat16*)WvlT,
        v, CC, CC, bv, nullptr, nullptr, nullptr, nullptr, nullptr);

    // K2: S = q @ k^T per batch + fused per-tile softmax stats
    qk_mma_kernel<<<dim3(32, 32, 2), blk>>>(
        (const __nv_bfloat16*)qh, (const __nv_bfloat16*)kh, (__nv_bfloat16*)S,
        (float*)pm, (float*)pl);

    // K3': combine partials -> rowm, rowinvl
    combine_kernel<<<MM / 256, blk>>>((const float*)pm, (const float*)pl,
                                      (float*)rowm, (float*)rowinvl);

    // K4: column sums -> s[n]
    colsum_part_kernel<<<dim3(8, 16, 2), blk>>>((const __nv_bfloat16*)S,
        (const float*)rowm, (const float*)rowinvl, (float*)cpart);
    colsum_final_kernel<<<MM / 256, blk>>>((const float*)cpart, (float*)srow);

    // P3: vs = v * s[row], split into bf16 hi/lo
    split_vs_kernel<<<(MM * CC) / 1024, blk>>>(
        (const float*)v, (const float*)srow,
        (__nv_bfloat16*)vsh, (__nv_bfloat16*)vsl);

    // G4: out = relu(BN(vs @ Wo + bo)) + x  (split-bf16, fp32 epilogue)
    mma_gemm_kernel<3, 2><<<gProj, blk, 98304>>>(
        (const __nv_bfloat16*)vsh, (const __nv_bfloat16*)vsl,
        (const __nv_bfloat16*)WohT, (const __nv_bfloat16*)WolT,
        out, CC, CC, bo, x, bns, bnb, bnm, bnv);
}

// round 7
// speedup vs baseline: 5.9051x; 1.0076x over previous
#include <cuda_runtime.h>
#include <cuda_bf16.h>
#include <math.h>
#include <stdint.h>

// Problem dims (fixed by the dataset)
static constexpr int  BB  = 2;
static constexpr int  NN_ = 4096;
static constexpr int  CC  = 512;
static constexpr int  MM  = BB * NN_;               // 8192 rows total
static constexpr size_t SBATCH = (size_t)NN_ * NN_; // 16777216

// Scratch (device globals: no cudaMalloc allowed)
__device__ __align__(256) unsigned short g_xh[(size_t)MM * CC];  // bf16 x hi
__device__ __align__(256) unsigned short g_xl[(size_t)MM * CC];  // bf16 x lo
__device__ __align__(256) unsigned short g_qh[(size_t)MM * CC];  // bf16 q
__device__ __align__(256) unsigned short g_kh[(size_t)MM * CC];  // bf16 k
__device__ __align__(256) float          g_v [(size_t)MM * CC];  // fp32 v
__device__ __align__(256) unsigned short g_vsh[(size_t)MM * CC]; // bf16 v*s hi
__device__ __align__(256) unsigned short g_vsl[(size_t)MM * CC]; // bf16 v*s lo
__device__ __align__(256) unsigned short g_S [(size_t)BB * SBATCH]; // bf16 logits
// transposed weights [N x K] bf16
__device__ __align__(256) unsigned short g_WqT[CC * CC];
__device__ __align__(256) unsigned short g_WkT[CC * CC];
__device__ __align__(256) unsigned short g_WvhT[CC * CC];
__device__ __align__(256) unsigned short g_WvlT[CC * CC];
__device__ __align__(256) unsigned short g_WohT[CC * CC];
__device__ __align__(256) unsigned short g_WolT[CC * CC];
// per-(row, n-tile) softmax partials (32 n-tiles per batch row)
__device__ float g_pm[32 * MM];
__device__ float g_pl[32 * MM];
__device__ float g_rowm[MM];
__device__ float g_rowinvl[MM];
__device__ float g_cpart[32 * MM];
__device__ float g_srow[MM];

// ---------------------------------------------------------------------------
// PTX helpers (plain sm_103-compatible: mma.sync / ldmatrix / cp.async)
// ---------------------------------------------------------------------------
__device__ __forceinline__ uint32_t smem_u32(const void* p) {
    uint32_t a;
    asm("{ .reg .u64 t; cvta.to.shared.u64 t, %1; cvt.u32.u64 %0, t; }"
        : "=r"(a) : "l"(p));
    return a;
}
__device__ __forceinline__ void cp_async16(uint32_t dst, const void* src) {
    asm volatile("cp.async.cg.shared.global [%0], [%1], 16;"
                 :: "r"(dst), "l"(src) : "memory");
}
__device__ __forceinline__ void cp_commit() {
    asm volatile("cp.async.commit_group;" ::: "memory");
}
template<int N>
__device__ __forceinline__ void cp_wait() {
    asm volatile("cp.async.wait_group %0;" :: "n"(N) : "memory");
}
__device__ __forceinline__ void ldmatrix_x4(uint32_t& r0, uint32_t& r1,
                                            uint32_t& r2, uint32_t& r3,
                                            uint32_t addr) {
    asm volatile("ldmatrix.sync.aligned.m8n8.x4.shared.b16 {%0,%1,%2,%3}, [%4];"
                 : "=r"(r0), "=r"(r1), "=r"(r2), "=r"(r3) : "r"(addr));
}
__device__ __forceinline__ void mma_bf16(float& c0, float& c1, float& c2, float& c3,
                                         uint32_t a0, uint32_t a1, uint32_t a2, uint32_t a3,
                                         uint32_t b0, uint32_t b1) {
    asm volatile(
        "mma.sync.aligned.m16n8k16.row.col.f32.bf16.bf16.f32 "
        "{%0,%1,%2,%3}, {%4,%5,%6,%7}, {%8,%9}, {%0,%1,%2,%3};"
        : "+f"(c0), "+f"(c1), "+f"(c2), "+f"(c3)
        : "r"(a0), "r"(a1), "r"(a2), "r"(a3), "r"(b0), "r"(b1));
}

// smem tile layout: row-major [row][32 bf16] = 64B/row; 16B granules XOR-swizzled
__device__ __forceinline__ uint32_t sw_off(int row, int kg) {
    return (uint32_t)(row * 64 + ((kg ^ ((row >> 1) & 3)) << 4));
}

// exp via MUFU ex2.approx (1 FMA + 1 MUFU; overlaps with FMA pipe).
__device__ __forceinline__ float fexp(float x) {
    float y = x * 1.4426950408889634f;
    float r;
    asm("ex2.approx.f32 %0, %1;" : "=f"(r) : "f"(y));
    return r;
}

// ---------------------------------------------------------------------------
// K2: S[b] = q[b] @ k[b]^T via mma.sync bf16. Block tile 128x128, BK=32,
// 8 warps (4M x 2N, warp tile 32x64), 3-stage cp.async pipeline.
// Fused epilogue: writes bf16 S AND per-tile softmax partials (rowmax, sumexp).
// rowmax uses raw fp32 acc (valid: m cancels exactly in final s[n]).
// ---------------------------------------------------------------------------
__global__ void __launch_bounds__(256, 2)
qk_mma_kernel(const __nv_bfloat16* __restrict__ Q,
              const __nv_bfloat16* __restrict__ Kmat,
              __nv_bfloat16* __restrict__ S,
              float* __restrict__ pm, float* __restrict__ pl)
{
    __shared__ __align__(1024) char smem[3 * 16384];
    const uint32_t sbase = smem_u32(smem);

    const int tid = threadIdx.x;
    const int wid = tid >> 5;
    const int lid = tid & 31;
    const int wm  = wid & 3;
    const int wn  = wid >> 2;
    const int n0  = blockIdx.x * 128;
    const int m0  = blockIdx.y * 128;
    const int bz  = blockIdx.z;

    const __nv_bfloat16* Qb = Q    + ((size_t)bz * NN_ + m0) * CC;
    const __nv_bfloat16* Kb = Kmat + ((size_t)bz * NN_ + n0) * CC;

    const int mgrp = lid >> 3;
    const int lr   = lid & 7;
    uint32_t aoff[2][2], boff[4][2];
#pragma unroll
    for (int mt = 0; mt < 2; mt++)
#pragma unroll
        for (int kh = 0; kh < 2; kh++) {
            int row = wm * 32 + mt * 16 + lr + ((mgrp & 1) << 3);
            int kg  = 2 * kh + (mgrp >> 1);
            aoff[mt][kh] = sw_off(row, kg);
        }
#pragma unroll
    for (int i = 0; i < 4; i++)
#pragma unroll
        for (int kh = 0; kh < 2; kh++) {
            int row = wn * 64 + i * 16 + lr + ((mgrp >> 1) << 3);
            int kg  = 2 * kh + (mgrp & 1);
            boff[i][kh] = 8192u + sw_off(row, kg);
        }

    float acc[2][8][4];
#pragma unroll
    for (int mt = 0; mt < 2; mt++)
#pragma unroll
        for (int nt = 0; nt < 8; nt++)
#pragma unroll
            for (int e = 0; e < 4; e++) acc[mt][nt][e] = 0.0f;

    auto load_stage = [&](int kb, int buf) {
        uint32_t dstb = sbase + buf * 16384;
#pragma unroll
        for (int it = 0; it < 2; it++) {
            int idx = tid + it * 256;
            int row = idx >> 2, kg = idx & 3;
            cp_async16(dstb + sw_off(row, kg), Qb + (size_t)row * CC + kb * 32 + kg * 8);
        }
#pragma unroll
        for (int it = 0; it < 2; it++) {
            int idx = tid + it * 256;
            int row = idx >> 2, kg = idx & 3;
            cp_async16(dstb + 8192 + sw_off(row, kg), Kb + (size_t)row * CC + kb * 32 + kg * 8);
        }
        cp_commit();
    };

    load_stage(0, 0);
    load_stage(1, 1);

    const int KB = CC / 32;
    for (int kb = 0; kb < KB; kb++) {
        const int buf = kb % 3;
        if (kb < KB - 1) cp_wait<1>(); else cp_wait<0>();
        __syncthreads();
        if (kb + 2 < KB) load_stage(kb + 2, (kb + 2) % 3);

        const uint32_t stb = sbase + buf * 16384;
#pragma unroll
        for (int kh = 0; kh < 2; kh++) {
            uint32_t af[2][4], bf[4][4];
#pragma unroll
            for (int mt = 0; mt < 2; mt++)
                ldmatrix_x4(af[mt][0], af[mt][1], af[mt][2], af[mt][3],
                            stb + aoff[mt][kh]);
#pragma unroll
            for (int i = 0; i < 4; i++)
                ldmatrix_x4(bf[i][0], bf[i][1], bf[i][2], bf[i][3],
                            stb + boff[i][kh]);
#pragma unroll
            for (int mt = 0; mt < 2; mt++)
#pragma unroll
                for (int i = 0; i < 4; i++) {
                    mma_bf16(acc[mt][2*i][0], acc[mt][2*i][1], acc[mt][2*i][2], acc[mt][2*i][3],
                             af[mt][0], af[mt][1], af[mt][2], af[mt][3],
                             bf[i][0], bf[i][1]);
                    mma_bf16(acc[mt][2*i+1][0], acc[mt][2*i+1][1], acc[mt][2*i+1][2], acc[mt][2*i+1][3],
                             af[mt][0], af[mt][1], af[mt][2], af[mt][3],
                             bf[i][2], bf[i][3]);
                }
        }
    }

    __syncthreads();   // pipeline smem now reusable for reductions

    float* s_red = (float*)smem;        // [128][2] per-(row, wn) max
    float* s_tm  = s_red + 256;         // [128] tile row max
    float* s_l   = s_tm + 128;          // [128][2] per-(row, wn) sumexp

    const int grow = lid >> 2;
    const int gcol = (lid & 3) * 2;

    // Sweep 1: per-thread row maxes over raw fp32 acc
    float pmax[2][2];
#pragma unroll
    for (int mt = 0; mt < 2; mt++) { pmax[mt][0] = -3.0e38f; pmax[mt][1] = -3.0e38f; }
#pragma unroll
    for (int mt = 0; mt < 2; mt++)
#pragma unroll
        for (int nt = 0; nt < 8; nt++) {
            pmax[mt][0] = fmaxf(pmax[mt][0], fmaxf(acc[mt][nt][0], acc[mt][nt][1]));
            pmax[mt][1] = fmaxf(pmax[mt][1], fmaxf(acc[mt][nt][2], acc[mt][nt][3]));
        }
#pragma unroll
    for (int mt = 0; mt < 2; mt++)
#pragma unroll
        for (int h = 0; h < 2; h++) {
            float v = pmax[mt][h];
            v = fmaxf(v, __shfl_xor_sync(0xffffffffu, v, 1));
            v = fmaxf(v, __shfl_xor_sync(0xffffffffu, v, 2));
            if ((lid & 3) == 0)
                s_red[(wm * 32 + mt * 16 + h * 8 + grow) * 2 + wn] = v;
        }
    __syncthreads();
    if (tid < 128) s_tm[tid] = fmaxf(s_red[tid * 2], s_red[tid * 2 + 1]);
    __syncthreads();

    // Sweep 2: store bf16 S + per-thread sumexp (from bf16-rounded values)
    float psum[2][2] = {{0.0f, 0.0f}, {0.0f, 0.0f}};
#pragma unroll
    for (int mt = 0; mt < 2; mt++) {
        const float tm0 = s_tm[wm * 32 + mt * 16 + grow];
        const float tm1 = s_tm[wm * 32 + mt * 16 + 8 + grow];
        const int rowa = m0 + wm * 32 + mt * 16 + grow;
#pragma unroll
        for (int nt = 0; nt < 8; nt++) {
            const int col = n0 + wn * 64 + nt * 8 + gcol;
            __nv_bfloat162 h0 = __float22bfloat162_rn(
                make_float2(acc[mt][nt][0], acc[mt][nt][1]));
            __nv_bfloat162 h1 = __float22bfloat162_rn(
                make_float2(acc[mt][nt][2], acc[mt][nt][3]));
            *(__nv_bfloat162*)(S + (size_t)bz * SBATCH + (size_t)rowa * NN_ + col) = h0;
            *(__nv_bfloat162*)(S + (size_t)bz * SBATCH + (size_t)(rowa + 8) * NN_ + col) = h1;
            float2 f0 = __bfloat1622float2(h0);
            float2 f1 = __bfloat1622float2(h1);
            psum[mt][0] += fexp(f0.x - tm0) + fexp(f0.y - tm0);
            psum[mt][1] += fexp(f1.x - tm1) + fexp(f1.y - tm1);
        }
    }
#pragma unroll
    for (int mt = 0; mt < 2; mt++)
#pragma unroll
        for (int h = 0; h < 2; h++) {
            float v = psum[mt][h];
            v += __shfl_xor_sync(0xffffffffu, v, 1);
            v += __shfl_xor_sync(0xffffffffu, v, 2);
            if ((lid & 3) == 0)
                s_l[(wm * 32 + mt * 16 + h * 8 + grow) * 2 + wn] = v;
        }
    __syncthreads();
    if (tid < 128) {
        const size_t brow = (size_t)bz * NN_ + m0 + tid;
        pm[(size_t)blockIdx.x * MM + brow] = s_tm[tid];
        pl[(size_t)blockIdx.x * MM + brow] = s_l[tid * 2] + s_l[tid * 2 + 1];
    }
}

// Combine 32 per-tile partials into rowm / rowinvl.
__global__ void __launch_bounds__(256)
combine_kernel(const float* __restrict__ pm, const float* __restrict__ pl,
               float* __restrict__ rowm, float* __restrict__ rowinvl)
{
    const int r = blockIdx.x * 256 + threadIdx.x;
    float M = -3.0e38f;
#pragma unroll
    for (int t = 0; t < 32; t++) M = fmaxf(M, pm[(size_t)t * MM + r]);
    float L = 0.0f;
#pragma unroll
    for (int t = 0; t < 32; t++)
        L += pl[(size_t)t * MM + r] * fexp(pm[(size_t)t * MM + r] - M);
    rowm[r] = M;
    rowinvl[r] = 1.0f / L;
}

// ---------------------------------------------------------------------------
// Generic mma GEMM: C[M x N] = sum over TERMS of A-variants @ B-variants^T.
// TERMS=1: Ah@Bh.  TERMS=3: Ah@Bh + Ah@Bl + Al@Bh (split-bf16 fp32 emulation).
// EPI 0: +bias -> bf16 out. EPI 1: +bias -> fp32 out.
// EPI 2: +bias, BN, relu, +xres -> fp32 out.
// If gridDim.z == 2, blockIdx.z == 1 switches to (Bh2, bias2, Cout2):
// lets two GEMMs sharing the A operand run in ONE launch (better wave packing).
// ---------------------------------------------------------------------------
template<int TERMS, int EPI>
__global__ void __launch_bounds__(256)
mma_gemm_kernel(const __nv_bfloat16* __restrict__ Ah,
                const __nv_bfloat16* __restrict__ Al,
                const __nv_bfloat16* __restrict__ Bh,
                const __nv_bfloat16* __restrict__ Bl,
                void* __restrict__ Cout, int N, int K,
                const float* __restrict__ bias,
                const float* __restrict__ xres,
                const float* __restrict__ bns,
                const float* __restrict__ bnb,
                const float* __restrict__ bnm,
                const float* __restrict__ bnv,
                const __nv_bfloat16* __restrict__ Bh2,
                const float* __restrict__ bias2,
                void* __restrict__ Cout2)
{
    constexpr int STAGE = (TERMS == 3) ? 32768 : 16384;
    constexpr uint32_t BOFF = (TERMS == 3) ? 16384u : 8192u;
    extern __shared__ __align__(1024) char smem[];
    const uint32_t sbase = smem_u32(smem);

    if (blockIdx.z == 1) { Bh = Bh2; bias = bias2; Cout = Cout2; }

    const int tid = threadIdx.x;
    const int wid = tid >> 5;
    const int lid = tid & 31;
    const int wm  = wid & 3;
    const int wn  = wid >> 2;
    const int n0  = blockIdx.x * 128;
    const int m0  = blockIdx.y * 128;

    const __nv_bfloat16* Ahb = Ah + (size_t)m0 * K;
    const __nv_bfloat16* Alb = (TERMS == 3) ? Al + (size_t)m0 * K : nullptr;
    const __nv_bfloat16* Bhb = Bh + (size_t)n0 * K;
    const __nv_bfloat16* Blb = (TERMS == 3) ? Bl + (size_t)n0 * K : nullptr;

    const int mgrp = lid >> 3;
    const int lr   = lid & 7;
    uint32_t aoff[2][2], boff[4][2];
#pragma unroll
    for (int mt = 0; mt < 2; mt++)
#pragma unroll
        for (int kh = 0; kh < 2; kh++) {
            int row = wm * 32 + mt * 16 + lr + ((mgrp & 1) << 3);
            int kg  = 2 * kh + (mgrp >> 1);
            aoff[mt][kh] = sw_off(row, kg);
        }
#pragma unroll
    for (int i = 0; i < 4; i++)
#pragma unroll
        for (int kh = 0; kh < 2; kh++) {
            int row = wn * 64 + i * 16 + lr + ((mgrp >> 1) << 3);
            int kg  = 2 * kh + (mgrp & 1);
            boff[i][kh] = BOFF + sw_off(row, kg);
        }

    float acc[2][8][4];
#pragma unroll
    for (int mt = 0; mt < 2; mt++)
#pragma unroll
        for (int nt = 0; nt < 8; nt++)
#pragma unroll
            for (int e = 0; e < 4; e++) acc[mt][nt][e] = 0.0f;

    auto load_stage = [&](int kb, int buf) {
        uint32_t dstb = sbase + buf * STAGE;
#pragma unroll
        for (int it = 0; it < 2; it++) {
            int idx = tid + it * 256;
            int row = idx >> 2, kg = idx & 3;
            size_t goff = (size_t)row * K + kb * 32 + kg * 8;
            uint32_t so = sw_off(row, kg);
            cp_async16(dstb + so, Ahb + goff);
            if (TERMS == 3) cp_async16(dstb + 8192u + so, Alb + goff);
            cp_async16(dstb + BOFF + so, Bhb + goff);
            if (TERMS == 3) cp_async16(dstb + BOFF + 8192u + so, Blb + goff);
        }
        cp_commit();
    };

    load_stage(0, 0);
    load_stage(1, 1);

    const int KB = K / 32;
    for (int kb = 0; kb < KB; kb++) {
        const int buf = kb % 3;
        if (kb < KB - 1) cp_wait<1>(); else cp_wait<0>();
        __syncthreads();
        if (kb + 2 < KB) load_stage(kb + 2, (kb + 2) % 3);

        const uint32_t stb = sbase + buf * STAGE;
#pragma unroll
        for (int kh = 0; kh < 2; kh++) {
            uint32_t afh[2][4], bfh[4][4];
            uint32_t afl[2][4], bfl[4][4];
#pragma unroll
            for (int mt = 0; mt < 2; mt++) {
                ldmatrix_x4(afh[mt][0], afh[mt][1], afh[mt][2], afh[mt][3],
                            stb + aoff[mt][kh]);
                if (TERMS == 3)
                    ldmatrix_x4(afl[mt][0], afl[mt][1], afl[mt][2], afl[mt][3],
                                stb + 8192u + aoff[mt][kh]);
            }
#pragma unroll
            for (int i = 0; i < 4; i++) {
                ldmatrix_x4(bfh[i][0], bfh[i][1], bfh[i][2], bfh[i][3],
                            stb + boff[i][kh]);
                if (TERMS == 3)
                    ldmatrix_x4(bfl[i][0], bfl[i][1], bfl[i][2], bfl[i][3],
                                stb + 8192u + boff[i][kh]);
            }
#pragma unroll
            for (int mt = 0; mt < 2; mt++)
#pragma unroll
                for (int i = 0; i < 4; i++) {
#pragma unroll
                    for (int h = 0; h < 2; h++) {
                        float* c0 = acc[mt][2*i + h];
                        mma_bf16(c0[0], c0[1], c0[2], c0[3],
                                 afh[mt][0], afh[mt][1], afh[mt][2], afh[mt][3],
                                 bfh[i][2*h], bfh[i][2*h + 1]);
                        if (TERMS == 3) {
                            mma_bf16(c0[0], c0[1], c0[2], c0[3],
                                     afh[mt][0], afh[mt][1], afh[mt][2], afh[mt][3],
                                     bfl[i][2*h], bfl[i][2*h + 1]);
                            mma_bf16(c0[0], c0[1], c0[2], c0[3],
                                     afl[mt][0], afl[mt][1], afl[mt][2], afl[mt][3],
                                     bfh[i][2*h], bfh[i][2*h + 1]);
                        }
                    }
                }
        }
    }

    const int grow = lid >> 2;
    const int gcol = (lid & 3) * 2;
#pragma unroll
    for (int mt = 0; mt < 2; mt++) {
#pragma unroll
        for (int nt = 0; nt < 8; nt++) {
            const int col  = n0 + wn * 64 + nt * 8 + gcol;
            const int rowa = m0 + wm * 32 + mt * 16 + grow;
            float b0 = bias[col], b1 = bias[col + 1];
            float v00 = acc[mt][nt][0] + b0, v01 = acc[mt][nt][1] + b1;
            float v10 = acc[mt][nt][2] + b0, v11 = acc[mt][nt][3] + b1;
            if (EPI == 0) {
                *(__nv_bfloat162*)((__nv_bfloat16*)Cout + (size_t)rowa * N + col)
                    = __float22bfloat162_rn(make_float2(v00, v01));
                *(__nv_bfloat162*)((__nv_bfloat16*)Cout + (size_t)(rowa + 8) * N + col)
                    = __float22bfloat162_rn(make_float2(v10, v11));
            } else if (EPI == 1) {
                *(float2*)((float*)Cout + (size_t)rowa * N + col)
                    = make_float2(v00, v01);
                *(float2*)((float*)Cout + (size_t)(rowa + 8) * N + col)
                    = make_float2(v10, v11);
            } else {
                float g0 = rsqrtf(bnv[col] + 1e-5f) * bns[col];
                float g1 = rsqrtf(bnv[col + 1] + 1e-5f) * bns[col + 1];
                float m0c = bnm[col], m1c = bnm[col + 1];
                float a0 = bnb[col], a1 = bnb[col + 1];
                v00 = fmaxf((v00 - m0c) * g0 + a0, 0.0f);
                v01 = fmaxf((v01 - m1c) * g1 + a1, 0.0f);
                v10 = fmaxf((v10 - m0c) * g0 + a0, 0.0f);
                v11 = fmaxf((v11 - m1c) * g1 + a1, 0.0f);
                float2 r0 = *(const float2*)(xres + (size_t)rowa * N + col);
                float2 r1 = *(const float2*)(xres + (size_t)(rowa + 8) * N + col);
                *(float2*)((float*)Cout + (size_t)rowa * N + col)
                    = make_float2(v00 + r0.x, v01 + r0.y);
                *(float2*)((float*)Cout + (size_t)(rowa + 8) * N + col)
                    = make_float2(v10 + r1.x, v11 + r1.y);
            }
        }
    }
}

// ---------------------------------------------------------------------------
// Prep kernels
// ---------------------------------------------------------------------------
__global__ void __launch_bounds__(256)
split_kernel(const float* __restrict__ x,
             __nv_bfloat16* __restrict__ xh, __nv_bfloat16* __restrict__ xl)
{
    size_t i = ((size_t)blockIdx.x * 256 + threadIdx.x) * 4;
    float4 v = *(const float4*)(x + i);
    __nv_bfloat16 h0 = __float2bfloat16(v.x), h1 = __float2bfloat16(v.y);
    __nv_bfloat16 h2 = __float2bfloat16(v.z), h3 = __float2bfloat16(v.w);
    __nv_bfloat16 l0 = __float2bfloat16(v.x - __bfloat162float(h0));
    __nv_bfloat16 l1 = __float2bfloat16(v.y - __bfloat162float(h1));
    __nv_bfloat16 l2 = __float2bfloat16(v.z - __bfloat162float(h2));
    __nv_bfloat16 l3 = __float2bfloat16(v.w - __bfloat162float(h3));
    __nv_bfloat162 hp[2] = {{h0, h1}, {h2, h3}};
    __nv_bfloat162 lp[2] = {{l0, l1}, {l2, l3}};
    *(uint2*)(xh + i) = *(uint2*)hp;
    *(uint2*)(xl + i) = *(uint2*)lp;
}

__global__ void __launch_bounds__(256)
split_vs_kernel(const float* __restrict__ v, const float* __restrict__ srow,
                __nv_bfloat16* __restrict__ vh, __nv_bfloat16* __restrict__ vl)
{
    size_t i = ((size_t)blockIdx.x * 256 + threadIdx.x) * 4;
    float s = srow[i >> 9];
    float4 x = *(const float4*)(v + i);
    x.x *= s; x.y *= s; x.z *= s; x.w *= s;
    __nv_bfloat16 h0 = __float2bfloat16(x.x), h1 = __float2bfloat16(x.y);
    __nv_bfloat16 h2 = __float2bfloat16(x.z), h3 = __float2bfloat16(x.w);
    __nv_bfloat16 l0 = __float2bfloat16(x.x - __bfloat162float(h0));
    __nv_bfloat16 l1 = __float2bfloat16(x.y - __bfloat162float(h1));
    __nv_bfloat16 l2 = __float2bfloat16(x.z - __bfloat162float(h2));
    __nv_bfloat16 l3 = __float2bfloat16(x.w - __bfloat162float(h3));
    __nv_bfloat162 hp[2] = {{h0, h1}, {h2, h3}};
    __nv_bfloat162 lp[2] = {{l0, l1}, {l2, l3}};
    *(uint2*)(vh + i) = *(uint2*)hp;
    *(uint2*)(vl + i) = *(uint2*)lp;
}

// Transpose+split all 4 weights in ONE launch (z selects the weight).
__global__ void __launch_bounds__(1024)
wprep_all_kernel(const float* __restrict__ Wq, const float* __restrict__ Wk,
                 const float* __restrict__ Wv, const float* __restrict__ Wo,
                 __nv_bfloat16* __restrict__ WqT, __nv_bfloat16* __restrict__ WkT,
                 __nv_bfloat16* __restrict__ WvhT, __nv_bfloat16* __restrict__ WvlT,
                 __nv_bfloat16* __restrict__ WohT, __nv_bfloat16* __restrict__ WolT)
{
    const float* W;
    __nv_bfloat16 *Th, *Tl = nullptr;
    switch (blockIdx.z) {
        case 0:  W = Wq; Th = WqT;  break;
        case 1:  W = Wk; Th = WkT;  break;
        case 2:  W = Wv; Th = WvhT; Tl = WvlT; break;
        default: W = Wo; Th = WohT; Tl = WolT; break;
    }
    __shared__ float t[32][33];
    const int tx = threadIdx.x, ty = threadIdx.y;
    const int bx = blockIdx.x * 32, by = blockIdx.y * 32;
    t[ty][tx] = W[(size_t)(by + ty) * CC + bx + tx];
    __syncthreads();
    const int n = bx + ty, k = by + tx;
    float v = t[tx][ty];
    __nv_bfloat16 h = __float2bfloat16(v);
    Th[(size_t)n * CC + k] = h;
    if (Tl) Tl[(size_t)n * CC + k] = __float2bfloat16(v - __bfloat162float(h));
}

// ---------------------------------------------------------------------------
// Column sums of normalized attention (bf16 S), 32-way m-split, 4 cols/thread.
// ---------------------------------------------------------------------------
__global__ void __launch_bounds__(256)
colsum_part_kernel(const __nv_bfloat16* __restrict__ S,
                   const float* __restrict__ rowm,
                   const float* __restrict__ rowinvl,
                   float* __restrict__ cpart)
{
    __shared__ float sm[128], si[128];
    const int b     = blockIdx.z;
    const int n     = blockIdx.x * 1024 + threadIdx.x * 4;
    const int m0    = blockIdx.y * 128;
    const int rbase = b * 4096;
    if (threadIdx.x < 128) {
        sm[threadIdx.x] = rowm[rbase + m0 + threadIdx.x];
        si[threadIdx.x] = rowinvl[rbase + m0 + threadIdx.x];
    }
    __syncthreads();
    const __nv_bfloat16* Sb = S + (size_t)b * SBATCH + (size_t)m0 * 4096 + n;
    float a0 = 0.0f, a1 = 0.0f, a2 = 0.0f, a3 = 0.0f;
#pragma unroll 4
    for (int mm = 0; mm < 128; mm++) {
        uint2 u = *(const uint2*)(Sb + (size_t)mm * 4096);
        float2 f0 = __bfloat1622float2(reinterpret_cast<__nv_bfloat162&>(u.x));
        float2 f1 = __bfloat1622float2(reinterpret_cast<__nv_bfloat162&>(u.y));
        float m = sm[mm], iv = si[mm];
        a0 += fexp(f0.x - m) * iv;
        a1 += fexp(f0.y - m) * iv;
        a2 += fexp(f1.x - m) * iv;
        a3 += fexp(f1.y - m) * iv;
    }
    *(float4*)(cpart + (size_t)blockIdx.y * MM + rbase + n)
        = make_float4(a0, a1, a2, a3);
}

__global__ void __launch_bounds__(256)
colsum_final_kernel(const float* __restrict__ cpart, float* __restrict__ srow)
{
    const int i = blockIdx.x * 256 + threadIdx.x;
    float c = 0.0f;
#pragma unroll
    for (int p = 0; p < 32; p++) c += cpart[(size_t)p * MM + i];
    srow[i] = c / (c + 1e-9f);
}

// ---------------------------------------------------------------------------
extern "C" void kernel_launch(void* const* d_in, const int* in_sizes, int n_in,
                              void* d_out, int out_size)
{
    // metadata order: inputs, Wq, Wk, Wv, Wo, bq, bk, bv, bo, bn_* (two loops!)
    const float* x   = (const float*)d_in[0];
    const float* Wq  = (const float*)d_in[1];
    const float* Wk  = (const float*)d_in[2];
    const float* Wv  = (const float*)d_in[3];
    const float* Wo  = (const float*)d_in[4];
    const float* bq  = (const float*)d_in[5];
    const float* bk  = (const float*)d_in[6];
    const float* bv  = (const float*)d_in[7];
    const float* bo  = (const float*)d_in[8];
    const float* bns = (const float*)d_in[9];
    const float* bnb = (const float*)d_in[10];
    const float* bnm = (const float*)d_in[11];
    const float* bnv = (const float*)d_in[12];
    float* out = (float*)d_out;

    void *xh, *xl, *qh, *kh, *v, *vsh, *vsl, *S;
    void *WqT, *WkT, *WvhT, *WvlT, *WohT, *WolT;
    void *pm, *pl, *rowm, *rowinvl, *cpart, *srow;
    cudaGetSymbolAddress(&xh,   g_xh);   cudaGetSymbolAddress(&xl,   g_xl);
    cudaGetSymbolAddress(&qh,   g_qh);   cudaGetSymbolAddress(&kh,   g_kh);
    cudaGetSymbolAddress(&v,    g_v);
    cudaGetSymbolAddress(&vsh,  g_vsh);  cudaGetSymbolAddress(&vsl,  g_vsl);
    cudaGetSymbolAddress(&S,    g_S);
    cudaGetSymbolAddress(&WqT,  g_WqT);  cudaGetSymbolAddress(&WkT,  g_WkT);
    cudaGetSymbolAddress(&WvhT, g_WvhT); cudaGetSymbolAddress(&WvlT, g_WvlT);
    cudaGetSymbolAddress(&WohT, g_WohT); cudaGetSymbolAddress(&WolT, g_WolT);
    cudaGetSymbolAddress(&pm,      g_pm);
    cudaGetSymbolAddress(&pl,      g_pl);
    cudaGetSymbolAddress(&rowm,    g_rowm);
    cudaGetSymbolAddress(&rowinvl, g_rowinvl);
    cudaGetSymbolAddress(&cpart,   g_cpart);
    cudaGetSymbolAddress(&srow,    g_srow);

    static bool attr_done = false;
    if (!attr_done) {
        cudaFuncSetAttribute(mma_gemm_kernel<1, 0>,
            cudaFuncAttributeMaxDynamicSharedMemorySize, 49152);
        cudaFuncSetAttribute(mma_gemm_kernel<3, 1>,
            cudaFuncAttributeMaxDynamicSharedMemorySize, 98304);
        cudaFuncSetAttribute(mma_gemm_kernel<3, 2>,
            cudaFuncAttributeMaxDynamicSharedMemorySize, 98304);
        attr_done = true;
    }

    dim3 blk(256);
    dim3 gProj(CC / 128, MM / 128);           // (4, 64)
    dim3 gProj2(CC / 128, MM / 128, 2);       // fused q+k projections

    // P1: split x into bf16 hi/lo
    split_kernel<<<(MM * CC) / 1024, blk>>>(x, (__nv_bfloat16*)xh, (__nv_bfloat16*)xl);
    // P2: transpose+split all weights (one launch)
    wprep_all_kernel<<<dim3(16, 16, 4), dim3(32, 32)>>>(
        Wq, Wk, Wv, Wo,
        (__nv_bfloat16*)WqT, (__nv_bfloat16*)WkT,
        (__nv_bfloat16*)WvhT, (__nv_bfloat16*)WvlT,
        (__nv_bfloat16*)WohT, (__nv_bfloat16*)WolT);

    // G1+G2 fused: q,k projections in one launch (z selects Wq/Wk)
    mma_gemm_kernel<1, 0><<<gProj2, blk, 49152>>>(
        (const __nv_bfloat16*)xh, nullptr, (const __nv_bfloat16*)WqT, nullptr,
        qh, CC, CC, bq, nullptr, nullptr, nullptr, nullptr, nullptr,
        (const __nv_bfloat16*)WkT, bk, kh);
    // G3: v projection (split-bf16, fp32 out)
    mma_gemm_kernel<3, 1><<<gProj, blk, 98304>>>(
        (const __nv_bfloat16*)xh, (const __nv_bfloat16*)xl,
        (const __nv_bfloat16*)WvhT, (const __nv_bfloat16*)WvlT,
        v, CC, CC, bv, nullptr, nullptr, nullptr, nullptr, nullptr,
        nullptr, nullptr, nullptr);

    // K2: S = q @ k^T per batch + fused per-tile softmax stats
    qk_mma_kernel<<<dim3(32, 32, 2), blk>>>(
        (const __nv_bfloat16*)qh, (const __nv_bfloat16*)kh, (__nv_bfloat16*)S,
        (float*)pm, (float*)pl);

    // K3': combine partials -> rowm, rowinvl
    combine_kernel<<<MM / 256, blk>>>((const float*)pm, (const float*)pl,
                                      (float*)rowm, (float*)rowinvl);

    // K4: column sums -> s[n]
    colsum_part_kernel<<<dim3(4, 32, 2), blk>>>((const __nv_bfloat16*)S,
        (const float*)rowm, (const float*)rowinvl, (float*)cpart);
    colsum_final_kernel<<<MM / 256, blk>>>((const float*)cpart, (float*)srow);

    // P3: vs = v * s[row], split into bf16 hi/lo
    split_vs_kernel<<<(MM * CC) / 1024, blk>>>(
        (const float*)v, (const float*)srow,
        (__nv_bfloat16*)vsh, (__nv_bfloat16*)vsl);

    // G4: out = relu(BN(vs @ Wo + bo)) + x  (split-bf16, fp32 epilogue)
    mma_gemm_kernel<3, 2><<<gProj, blk, 98304>>>(
        (const __nv_bfloat16*)vsh, (const __nv_bfloat16*)vsl,
        (const __nv_bfloat16*)WohT, (const __nv_bfloat16*)WolT,
        out, CC, CC, bo, x, bns, bnb, bnm, bnv,
        nullptr, nullptr, nullptr);
}

// round 8
// speedup vs baseline: 6.1200x; 1.0364x over previous
#include <cuda_runtime.h>
#include <cuda_bf16.h>
#include <math.h>
#include <stdint.h>

// Problem dims (fixed by the dataset)
static constexpr int  BB  = 2;
static constexpr int  NN_ = 4096;
static constexpr int  CC  = 512;
static constexpr int  MM  = BB * NN_;               // 8192 rows total
static constexpr size_t SBATCH = (size_t)NN_ * NN_; // 16777216

// Scratch (device globals: no cudaMalloc allowed)
__device__ __align__(256) unsigned short g_xh[(size_t)MM * CC];  // bf16 x hi
__device__ __align__(256) unsigned short g_xl[(size_t)MM * CC];  // bf16 x lo
__device__ __align__(256) unsigned short g_qh[(size_t)MM * CC];  // bf16 q
__device__ __align__(256) unsigned short g_kh[(size_t)MM * CC];  // bf16 k
__device__ __align__(256) float          g_v [(size_t)MM * CC];  // fp32 v
__device__ __align__(256) unsigned short g_vsh[(size_t)MM * CC]; // bf16 v*s hi
__device__ __align__(256) unsigned short g_vsl[(size_t)MM * CC]; // bf16 v*s lo
__device__ __align__(256) unsigned short g_S [(size_t)BB * SBATCH]; // bf16 logits
// transposed weights [N x K] bf16
__device__ __align__(256) unsigned short g_WqT[CC * CC];
__device__ __align__(256) unsigned short g_WkT[CC * CC];
__device__ __align__(256) unsigned short g_WvhT[CC * CC];
__device__ __align__(256) unsigned short g_WvlT[CC * CC];
__device__ __align__(256) unsigned short g_WohT[CC * CC];
__device__ __align__(256) unsigned short g_WolT[CC * CC];
// per-(row, n-tile) softmax partials (32 n-tiles per batch row)
__device__ float g_pm[32 * MM];
__device__ float g_pl[32 * MM];
__device__ float g_rowm[MM];
__device__ float g_rowinvl[MM];
__device__ float g_cpart[32 * MM];
__device__ float g_srow[MM];

// ---------------------------------------------------------------------------
// PTX helpers (plain sm_103-compatible: mma.sync / ldmatrix / cp.async)
// ---------------------------------------------------------------------------
__device__ __forceinline__ uint32_t smem_u32(const void* p) {
    uint32_t a;
    asm("{ .reg .u64 t; cvta.to.shared.u64 t, %1; cvt.u32.u64 %0, t; }"
        : "=r"(a) : "l"(p));
    return a;
}
__device__ __forceinline__ void cp_async16(uint32_t dst, const void* src) {
    asm volatile("cp.async.cg.shared.global [%0], [%1], 16;"
                 :: "r"(dst), "l"(src) : "memory");
}
__device__ __forceinline__ void cp_commit() {
    asm volatile("cp.async.commit_group;" ::: "memory");
}
template<int N>
__device__ __forceinline__ void cp_wait() {
    asm volatile("cp.async.wait_group %0;" :: "n"(N) : "memory");
}
__device__ __forceinline__ void ldmatrix_x4(uint32_t& r0, uint32_t& r1,
                                            uint32_t& r2, uint32_t& r3,
                                            uint32_t addr) {
    asm volatile("ldmatrix.sync.aligned.m8n8.x4.shared.b16 {%0,%1,%2,%3}, [%4];"
                 : "=r"(r0), "=r"(r1), "=r"(r2), "=r"(r3) : "r"(addr));
}
__device__ __forceinline__ void mma_bf16(float& c0, float& c1, float& c2, float& c3,
                                         uint32_t a0, uint32_t a1, uint32_t a2, uint32_t a3,
                                         uint32_t b0, uint32_t b1) {
    asm volatile(
        "mma.sync.aligned.m16n8k16.row.col.f32.bf16.bf16.f32 "
        "{%0,%1,%2,%3}, {%4,%5,%6,%7}, {%8,%9}, {%0,%1,%2,%3};"
        : "+f"(c0), "+f"(c1), "+f"(c2), "+f"(c3)
        : "r"(a0), "r"(a1), "r"(a2), "r"(a3), "r"(b0), "r"(b1));
}

// smem tile layout: row-major [row][32 bf16] = 64B/row; 16B granules XOR-swizzled
__device__ __forceinline__ uint32_t sw_off(int row, int kg) {
    return (uint32_t)(row * 64 + ((kg ^ ((row >> 1) & 3)) << 4));
}

// exp via MUFU ex2.approx (1 FMA + 1 MUFU; overlaps with FMA pipe).
__device__ __forceinline__ float fexp(float x) {
    float y = x * 1.4426950408889634f;
    float r;
    asm("ex2.approx.f32 %0, %1;" : "=f"(r) : "f"(y));
    return r;
}

// ---------------------------------------------------------------------------
// K2: S[b] = q[b] @ k[b]^T via mma.sync bf16. Block tile 128x128, BK=32,
// 8 warps (4M x 2N, warp tile 32x64), 3-stage cp.async pipeline.
// Fused epilogue: writes bf16 S AND per-tile softmax partials (rowmax, sumexp).
// rowmax uses raw fp32 acc (valid: m cancels exactly in final s[n]).
// ---------------------------------------------------------------------------
__global__ void __launch_bounds__(256, 2)
qk_mma_kernel(const __nv_bfloat16* __restrict__ Q,
              const __nv_bfloat16* __restrict__ Kmat,
              __nv_bfloat16* __restrict__ S,
              float* __restrict__ pm, float* __restrict__ pl)
{
    __shared__ __align__(1024) char smem[3 * 16384];
    const uint32_t sbase = smem_u32(smem);

    const int tid = threadIdx.x;
    const int wid = tid >> 5;
    const int lid = tid & 31;
    const int wm  = wid & 3;
    const int wn  = wid >> 2;
    const int n0  = blockIdx.x * 128;
    const int m0  = blockIdx.y * 128;
    const int bz  = blockIdx.z;

    const __nv_bfloat16* Qb = Q    + ((size_t)bz * NN_ + m0) * CC;
    const __nv_bfloat16* Kb = Kmat + ((size_t)bz * NN_ + n0) * CC;

    const int mgrp = lid >> 3;
    const int lr   = lid & 7;
    uint32_t aoff[2][2], boff[4][2];
#pragma unroll
    for (int mt = 0; mt < 2; mt++)
#pragma unroll
        for (int kh = 0; kh < 2; kh++) {
            int row = wm * 32 + mt * 16 + lr + ((mgrp & 1) << 3);
            int kg  = 2 * kh + (mgrp >> 1);
            aoff[mt][kh] = sw_off(row, kg);
        }
#pragma unroll
    for (int i = 0; i < 4; i++)
#pragma unroll
        for (int kh = 0; kh < 2; kh++) {
            int row = wn * 64 + i * 16 + lr + ((mgrp >> 1) << 3);
            int kg  = 2 * kh + (mgrp & 1);
            boff[i][kh] = 8192u + sw_off(row, kg);
        }

    float acc[2][8][4];
#pragma unroll
    for (int mt = 0; mt < 2; mt++)
#pragma unroll
        for (int nt = 0; nt < 8; nt++)
#pragma unroll
            for (int e = 0; e < 4; e++) acc[mt][nt][e] = 0.0f;

    auto load_stage = [&](int kb, int buf) {
        uint32_t dstb = sbase + buf * 16384;
#pragma unroll
        for (int it = 0; it < 2; it++) {
            int idx = tid + it * 256;
            int row = idx >> 2, kg = idx & 3;
            cp_async16(dstb + sw_off(row, kg), Qb + (size_t)row * CC + kb * 32 + kg * 8);
        }
#pragma unroll
        for (int it = 0; it < 2; it++) {
            int idx = tid + it * 256;
            int row = idx >> 2, kg = idx & 3;
            cp_async16(dstb + 8192 + sw_off(row, kg), Kb + (size_t)row * CC + kb * 32 + kg * 8);
        }
        cp_commit();
    };

    load_stage(0, 0);
    load_stage(1, 1);

    const int KB = CC / 32;
    for (int kb = 0; kb < KB; kb++) {
        const int buf = kb % 3;
        if (kb < KB - 1) cp_wait<1>(); else cp_wait<0>();
        __syncthreads();
        if (kb + 2 < KB) load_stage(kb + 2, (kb + 2) % 3);

        const uint32_t stb = sbase + buf * 16384;
#pragma unroll
        for (int kh = 0; kh < 2; kh++) {
            uint32_t af[2][4], bf[4][4];
#pragma unroll
            for (int mt = 0; mt < 2; mt++)
                ldmatrix_x4(af[mt][0], af[mt][1], af[mt][2], af[mt][3],
                            stb + aoff[mt][kh]);
#pragma unroll
            for (int i = 0; i < 4; i++)
                ldmatrix_x4(bf[i][0], bf[i][1], bf[i][2], bf[i][3],
                            stb + boff[i][kh]);
#pragma unroll
            for (int mt = 0; mt < 2; mt++)
#pragma unroll
                for (int i = 0; i < 4; i++) {
                    mma_bf16(acc[mt][2*i][0], acc[mt][2*i][1], acc[mt][2*i][2], acc[mt][2*i][3],
                             af[mt][0], af[mt][1], af[mt][2], af[mt][3],
                             bf[i][0], bf[i][1]);
                    mma_bf16(acc[mt][2*i+1][0], acc[mt][2*i+1][1], acc[mt][2*i+1][2], acc[mt][2*i+1][3],
                             af[mt][0], af[mt][1], af[mt][2], af[mt][3],
                             bf[i][2], bf[i][3]);
                }
        }
    }

    __syncthreads();   // pipeline smem now reusable for reductions

    float* s_red = (float*)smem;        // [128][2] per-(row, wn) max
    float* s_tm  = s_red + 256;         // [128] tile row max
    float* s_l   = s_tm + 128;          // [128][2] per-(row, wn) sumexp

    const int grow = lid >> 2;
    const int gcol = (lid & 3) * 2;

    // Sweep 1: per-thread row maxes over raw fp32 acc
    float pmax[2][2];
#pragma unroll
    for (int mt = 0; mt < 2; mt++) { pmax[mt][0] = -3.0e38f; pmax[mt][1] = -3.0e38f; }
#pragma unroll
    for (int mt = 0; mt < 2; mt++)
#pragma unroll
        for (int nt = 0; nt < 8; nt++) {
            pmax[mt][0] = fmaxf(pmax[mt][0], fmaxf(acc[mt][nt][0], acc[mt][nt][1]));
            pmax[mt][1] = fmaxf(pmax[mt][1], fmaxf(acc[mt][nt][2], acc[mt][nt][3]));
        }
#pragma unroll
    for (int mt = 0; mt < 2; mt++)
#pragma unroll
        for (int h = 0; h < 2; h++) {
            float v = pmax[mt][h];
            v = fmaxf(v, __shfl_xor_sync(0xffffffffu, v, 1));
            v = fmaxf(v, __shfl_xor_sync(0xffffffffu, v, 2));
            if ((lid & 3) == 0)
                s_red[(wm * 32 + mt * 16 + h * 8 + grow) * 2 + wn] = v;
        }
    __syncthreads();
    if (tid < 128) s_tm[tid] = fmaxf(s_red[tid * 2], s_red[tid * 2 + 1]);
    __syncthreads();

    // Sweep 2: store bf16 S + per-thread sumexp (from bf16-rounded values)
    float psum[2][2] = {{0.0f, 0.0f}, {0.0f, 0.0f}};
#pragma unroll
    for (int mt = 0; mt < 2; mt++) {
        const float tm0 = s_tm[wm * 32 + mt * 16 + grow];
        const float tm1 = s_tm[wm * 32 + mt * 16 + 8 + grow];
        const int rowa = m0 + wm * 32 + mt * 16 + grow;
#pragma unroll
        for (int nt = 0; nt < 8; nt++) {
            const int col = n0 + wn * 64 + nt * 8 + gcol;
            __nv_bfloat162 h0 = __float22bfloat162_rn(
                make_float2(acc[mt][nt][0], acc[mt][nt][1]));
            __nv_bfloat162 h1 = __float22bfloat162_rn(
                make_float2(acc[mt][nt][2], acc[mt][nt][3]));
            *(__nv_bfloat162*)(S + (size_t)bz * SBATCH + (size_t)rowa * NN_ + col) = h0;
            *(__nv_bfloat162*)(S + (size_t)bz * SBATCH + (size_t)(rowa + 8) * NN_ + col) = h1;
            float2 f0 = __bfloat1622float2(h0);
            float2 f1 = __bfloat1622float2(h1);
            psum[mt][0] += fexp(f0.x - tm0) + fexp(f0.y - tm0);
            psum[mt][1] += fexp(f1.x - tm1) + fexp(f1.y - tm1);
        }
    }
#pragma unroll
    for (int mt = 0; mt < 2; mt++)
#pragma unroll
        for (int h = 0; h < 2; h++) {
            float v = psum[mt][h];
            v += __shfl_xor_sync(0xffffffffu, v, 1);
            v += __shfl_xor_sync(0xffffffffu, v, 2);
            if ((lid & 3) == 0)
                s_l[(wm * 32 + mt * 16 + h * 8 + grow) * 2 + wn] = v;
        }
    __syncthreads();
    if (tid < 128) {
        const size_t brow = (size_t)bz * NN_ + m0 + tid;
        pm[(size_t)blockIdx.x * MM + brow] = s_tm[tid];
        pl[(size_t)blockIdx.x * MM + brow] = s_l[tid * 2] + s_l[tid * 2 + 1];
    }
}

// Combine 32 per-tile partials into rowm / rowinvl.
__global__ void __launch_bounds__(256)
combine_kernel(const float* __restrict__ pm, const float* __restrict__ pl,
               float* __restrict__ rowm, float* __restrict__ rowinvl)
{
    const int r = blockIdx.x * 256 + threadIdx.x;
    float M = -3.0e38f;
#pragma unroll
    for (int t = 0; t < 32; t++) M = fmaxf(M, pm[(size_t)t * MM + r]);
    float L = 0.0f;
#pragma unroll
    for (int t = 0; t < 32; t++)
        L += pl[(size_t)t * MM + r] * fexp(pm[(size_t)t * MM + r] - M);
    rowm[r] = M;
    rowinvl[r] = 1.0f / L;
}

// ---------------------------------------------------------------------------
// Generic mma GEMM: C[M x N] = sum over TERMS of A-variants @ B-variants^T.
// TERMS=1: Ah@Bh.  TERMS=3: Ah@Bh + Ah@Bl + Al@Bh (split-bf16 fp32 emulation).
// EPI 0: +bias -> bf16 out. EPI 1: +bias -> fp32 out.
// EPI 2: +bias, BN, relu, +xres -> fp32 out.
// If gridDim.z == 2, blockIdx.z == 1 switches to (Bh2, bias2, Cout2).
// __launch_bounds__(256, 2): cap regs at 128 so 2 CTAs/SM fit the regfile
// (134 regs at 1 CTA/SM left the SM latency-starved: issue was 15.9%).
// ---------------------------------------------------------------------------
template<int TERMS, int EPI>
__global__ void __launch_bounds__(256, 2)
mma_gemm_kernel(const __nv_bfloat16* __restrict__ Ah,
                const __nv_bfloat16* __restrict__ Al,
                const __nv_bfloat16* __restrict__ Bh,
                const __nv_bfloat16* __restrict__ Bl,
                void* __restrict__ Cout, int N, int K,
                const float* __restrict__ bias,
                const float* __restrict__ xres,
                const float* __restrict__ bns,
                const float* __restrict__ bnb,
                const float* __restrict__ bnm,
                const float* __restrict__ bnv,
                const __nv_bfloat16* __restrict__ Bh2,
                const float* __restrict__ bias2,
                void* __restrict__ Cout2)
{
    constexpr int STAGE = (TERMS == 3) ? 32768 : 16384;
    constexpr uint32_t BOFF = (TERMS == 3) ? 16384u : 8192u;
    extern __shared__ __align__(1024) char smem[];
    const uint32_t sbase = smem_u32(smem);

    if (blockIdx.z == 1) { Bh = Bh2; bias = bias2; Cout = Cout2; }

    const int tid = threadIdx.x;
    const int wid = tid >> 5;
    const int lid = tid & 31;
    const int wm  = wid & 3;
    const int wn  = wid >> 2;
    const int n0  = blockIdx.x * 128;
    const int m0  = blockIdx.y * 128;

    const __nv_bfloat16* Ahb = Ah + (size_t)m0 * K;
    const __nv_bfloat16* Alb = (TERMS == 3) ? Al + (size_t)m0 * K : nullptr;
    const __nv_bfloat16* Bhb = Bh + (size_t)n0 * K;
    const __nv_bfloat16* Blb = (TERMS == 3) ? Bl + (size_t)n0 * K : nullptr;

    const int mgrp = lid >> 3;
    const int lr   = lid & 7;
    uint32_t aoff[2][2], boff[4][2];
#pragma unroll
    for (int mt = 0; mt < 2; mt++)
#pragma unroll
        for (int kh = 0; kh < 2; kh++) {
            int row = wm * 32 + mt * 16 + lr + ((mgrp & 1) << 3);
            int kg  = 2 * kh + (mgrp >> 1);
            aoff[mt][kh] = sw_off(row, kg);
        }
#pragma unroll
    for (int i = 0; i < 4; i++)
#pragma unroll
        for (int kh = 0; kh < 2; kh++) {
            int row = wn * 64 + i * 16 + lr + ((mgrp >> 1) << 3);
            int kg  = 2 * kh + (mgrp & 1);
            boff[i][kh] = BOFF + sw_off(row, kg);
        }

    float acc[2][8][4];
#pragma unroll
    for (int mt = 0; mt < 2; mt++)
#pragma unroll
        for (int nt = 0; nt < 8; nt++)
#pragma unroll
            for (int e = 0; e < 4; e++) acc[mt][nt][e] = 0.0f;

    auto load_stage = [&](int kb, int buf) {
        uint32_t dstb = sbase + buf * STAGE;
#pragma unroll
        for (int it = 0; it < 2; it++) {
            int idx = tid + it * 256;
            int row = idx >> 2, kg = idx & 3;
            size_t goff = (size_t)row * K + kb * 32 + kg * 8;
            uint32_t so = sw_off(row, kg);
            cp_async16(dstb + so, Ahb + goff);
            if (TERMS == 3) cp_async16(dstb + 8192u + so, Alb + goff);
            cp_async16(dstb + BOFF + so, Bhb + goff);
            if (TERMS == 3) cp_async16(dstb + BOFF + 8192u + so, Blb + goff);
        }
        cp_commit();
    };

    load_stage(0, 0);
    load_stage(1, 1);

    const int KB = K / 32;
    for (int kb = 0; kb < KB; kb++) {
        const int buf = kb % 3;
        if (kb < KB - 1) cp_wait<1>(); else cp_wait<0>();
        __syncthreads();
        if (kb + 2 < KB) load_stage(kb + 2, (kb + 2) % 3);

        const uint32_t stb = sbase + buf * STAGE;
#pragma unroll
        for (int kh = 0; kh < 2; kh++) {
            uint32_t afh[2][4], bfh[4][4];
            uint32_t afl[2][4], bfl[4][4];
#pragma unroll
            for (int mt = 0; mt < 2; mt++) {
                ldmatrix_x4(afh[mt][0], afh[mt][1], afh[mt][2], afh[mt][3],
                            stb + aoff[mt][kh]);
                if (TERMS == 3)
                    ldmatrix_x4(afl[mt][0], afl[mt][1], afl[mt][2], afl[mt][3],
                                stb + 8192u + aoff[mt][kh]);
            }
#pragma unroll
            for (int i = 0; i < 4; i++) {
                ldmatrix_x4(bfh[i][0], bfh[i][1], bfh[i][2], bfh[i][3],
                            stb + boff[i][kh]);
                if (TERMS == 3)
                    ldmatrix_x4(bfl[i][0], bfl[i][1], bfl[i][2], bfl[i][3],
                                stb + 8192u + boff[i][kh]);
            }
#pragma unroll
            for (int mt = 0; mt < 2; mt++)
#pragma unroll
                for (int i = 0; i < 4; i++) {
#pragma unroll
                    for (int h = 0; h < 2; h++) {
                        float* c0 = acc[mt][2*i + h];
                        mma_bf16(c0[0], c0[1], c0[2], c0[3],
                                 afh[mt][0], afh[mt][1], afh[mt][2], afh[mt][3],
                                 bfh[i][2*h], bfh[i][2*h + 1]);
                        if (TERMS == 3) {
                            mma_bf16(c0[0], c0[1], c0[2], c0[3],
                                     afh[mt][0], afh[mt][1], afh[mt][2], afh[mt][3],
                                     bfl[i][2*h], bfl[i][2*h + 1]);
                            mma_bf16(c0[0], c0[1], c0[2], c0[3],
                                     afl[mt][0], afl[mt][1], afl[mt][2], afl[mt][3],
                                     bfh[i][2*h], bfh[i][2*h + 1]);
                        }
                    }
                }
        }
    }

    const int grow = lid >> 2;
    const int gcol = (lid & 3) * 2;
#pragma unroll
    for (int mt = 0; mt < 2; mt++) {
#pragma unroll
        for (int nt = 0; nt < 8; nt++) {
            const int col  = n0 + wn * 64 + nt * 8 + gcol;
            const int rowa = m0 + wm * 32 + mt * 16 + grow;
            float b0 = bias[col], b1 = bias[col + 1];
            float v00 = acc[mt][nt][0] + b0, v01 = acc[mt][nt][1] + b1;
            float v10 = acc[mt][nt][2] + b0, v11 = acc[mt][nt][3] + b1;
            if (EPI == 0) {
                *(__nv_bfloat162*)((__nv_bfloat16*)Cout + (size_t)rowa * N + col)
                    = __float22bfloat162_rn(make_float2(v00, v01));
                *(__nv_bfloat162*)((__nv_bfloat16*)Cout + (size_t)(rowa + 8) * N + col)
                    = __float22bfloat162_rn(make_float2(v10, v11));
            } else if (EPI == 1) {
                *(float2*)((float*)Cout + (size_t)rowa * N + col)
                    = make_float2(v00, v01);
                *(float2*)((float*)Cout + (size_t)(rowa + 8) * N + col)
                    = make_float2(v10, v11);
            } else {
                float g0 = rsqrtf(bnv[col] + 1e-5f) * bns[col];
                float g1 = rsqrtf(bnv[col + 1] + 1e-5f) * bns[col + 1];
                float m0c = bnm[col], m1c = bnm[col + 1];
                float a0 = bnb[col], a1 = bnb[col + 1];
                v00 = fmaxf((v00 - m0c) * g0 + a0, 0.0f);
                v01 = fmaxf((v01 - m1c) * g1 + a1, 0.0f);
                v10 = fmaxf((v10 - m0c) * g0 + a0, 0.0f);
                v11 = fmaxf((v11 - m1c) * g1 + a1, 0.0f);
                float2 r0 = *(const float2*)(xres + (size_t)rowa * N + col);
                float2 r1 = *(const float2*)(xres + (size_t)(rowa + 8) * N + col);
                *(float2*)((float*)Cout + (size_t)rowa * N + col)
                    = make_float2(v00 + r0.x, v01 + r0.y);
                *(float2*)((float*)Cout + (size_t)(rowa + 8) * N + col)
                    = make_float2(v10 + r1.x, v11 + r1.y);
            }
        }
    }
}

// ---------------------------------------------------------------------------
// Prep kernels
// ---------------------------------------------------------------------------
__global__ void __launch_bounds__(256)
split_kernel(const float* __restrict__ x,
             __nv_bfloat16* __restrict__ xh, __nv_bfloat16* __restrict__ xl)
{
    size_t i = ((size_t)blockIdx.x * 256 + threadIdx.x) * 4;
    float4 v = *(const float4*)(x + i);
    __nv_bfloat16 h0 = __float2bfloat16(v.x), h1 = __float2bfloat16(v.y);
    __nv_bfloat16 h2 = __float2bfloat16(v.z), h3 = __float2bfloat16(v.w);
    __nv_bfloat16 l0 = __float2bfloat16(v.x - __bfloat162float(h0));
    __nv_bfloat16 l1 = __float2bfloat16(v.y - __bfloat162float(h1));
    __nv_bfloat16 l2 = __float2bfloat16(v.z - __bfloat162float(h2));
    __nv_bfloat16 l3 = __float2bfloat16(v.w - __bfloat162float(h3));
    __nv_bfloat162 hp[2] = {{h0, h1}, {h2, h3}};
    __nv_bfloat162 lp[2] = {{l0, l1}, {l2, l3}};
    *(uint2*)(xh + i) = *(uint2*)hp;
    *(uint2*)(xl + i) = *(uint2*)lp;
}

__global__ void __launch_bounds__(256)
split_vs_kernel(const float* __restrict__ v, const float* __restrict__ srow,
                __nv_bfloat16* __restrict__ vh, __nv_bfloat16* __restrict__ vl)
{
    size_t i = ((size_t)blockIdx.x * 256 + threadIdx.x) * 4;
    float s = srow[i >> 9];
    float4 x = *(const float4*)(v + i);
    x.x *= s; x.y *= s; x.z *= s; x.w *= s;
    __nv_bfloat16 h0 = __float2bfloat16(x.x), h1 = __float2bfloat16(x.y);
    __nv_bfloat16 h2 = __float2bfloat16(x.z), h3 = __float2bfloat16(x.w);
    __nv_bfloat16 l0 = __float2bfloat16(x.x - __bfloat162float(h0));
    __nv_bfloat16 l1 = __float2bfloat16(x.y - __bfloat162float(h1));
    __nv_bfloat16 l2 = __float2bfloat16(x.z - __bfloat162float(h2));
    __nv_bfloat16 l3 = __float2bfloat16(x.w - __bfloat162float(h3));
    __nv_bfloat162 hp[2] = {{h0, h1}, {h2, h3}};
    __nv_bfloat162 lp[2] = {{l0, l1}, {l2, l3}};
    *(uint2*)(vh + i) = *(uint2*)hp;
    *(uint2*)(vl + i) = *(uint2*)lp;
}

// Transpose+split all 4 weights in ONE launch (z selects the weight).
__global__ void __launch_bounds__(1024)
wprep_all_kernel(const float* __restrict__ Wq, const float* __restrict__ Wk,
                 const float* __restrict__ Wv, const float* __restrict__ Wo,
                 __nv_bfloat16* __restrict__ WqT, __nv_bfloat16* __restrict__ WkT,
                 __nv_bfloat16* __restrict__ WvhT, __nv_bfloat16* __restrict__ WvlT,
                 __nv_bfloat16* __restrict__ WohT, __nv_bfloat16* __restrict__ WolT)
{
    const float* W;
    __nv_bfloat16 *Th, *Tl = nullptr;
    switch (blockIdx.z) {
        case 0:  W = Wq; Th = WqT;  break;
        case 1:  W = Wk; Th = WkT;  break;
        case 2:  W = Wv; Th = WvhT; Tl = WvlT; break;
        default: W = Wo; Th = WohT; Tl = WolT; break;
    }
    __shared__ float t[32][33];
    const int tx = threadIdx.x, ty = threadIdx.y;
    const int bx = blockIdx.x * 32, by = blockIdx.y * 32;
    t[ty][tx] = W[(size_t)(by + ty) * CC + bx + tx];
    __syncthreads();
    const int n = bx + ty, k = by + tx;
    float v = t[tx][ty];
    __nv_bfloat16 h = __float2bfloat16(v);
    Th[(size_t)n * CC + k] = h;
    if (Tl) Tl[(size_t)n * CC + k] = __float2bfloat16(v - __bfloat162float(h));
}

// ---------------------------------------------------------------------------
// Column sums of normalized attention (bf16 S), 32-way m-split, 4 cols/thread.
// ---------------------------------------------------------------------------
__global__ void __launch_bounds__(256)
colsum_part_kernel(const __nv_bfloat16* __restrict__ S,
                   const float* __restrict__ rowm,
                   const float* __restrict__ rowinvl,
                   float* __restrict__ cpart)
{
    __shared__ float sm[128], si[128];
    const int b     = blockIdx.z;
    const int n     = blockIdx.x * 1024 + threadIdx.x * 4;
    const int m0    = blockIdx.y * 128;
    const int rbase = b * 4096;
    if (threadIdx.x < 128) {
        sm[threadIdx.x] = rowm[rbase + m0 + threadIdx.x];
        si[threadIdx.x] = rowinvl[rbase + m0 + threadIdx.x];
    }
    __syncthreads();
    const __nv_bfloat16* Sb = S + (size_t)b * SBATCH + (size_t)m0 * 4096 + n;
    float a0 = 0.0f, a1 = 0.0f, a2 = 0.0f, a3 = 0.0f;
#pragma unroll 4
    for (int mm = 0; mm < 128; mm++) {
        uint2 u = *(const uint2*)(Sb + (size_t)mm * 4096);
        float2 f0 = __bfloat1622float2(reinterpret_cast<__nv_bfloat162&>(u.x));
        float2 f1 = __bfloat1622float2(reinterpret_cast<__nv_bfloat162&>(u.y));
        float m = sm[mm], iv = si[mm];
        a0 += fexp(f0.x - m) * iv;
        a1 += fexp(f0.y - m) * iv;
        a2 += fexp(f1.x - m) * iv;
        a3 += fexp(f1.y - m) * iv;
    }
    *(float4*)(cpart + (size_t)blockIdx.y * MM + rbase + n)
        = make_float4(a0, a1, a2, a3);
}

__global__ void __launch_bounds__(256)
colsum_final_kernel(const float* __restrict__ cpart, float* __restrict__ srow)
{
    const int i = blockIdx.x * 256 + threadIdx.x;
    float c = 0.0f;
#pragma unroll
    for (int p = 0; p < 32; p++) c += cpart[(size_t)p * MM + i];
    srow[i] = c / (c + 1e-9f);
}

// ---------------------------------------------------------------------------
extern "C" void kernel_launch(void* const* d_in, const int* in_sizes, int n_in,
                              void* d_out, int out_size)
{
    // metadata order: inputs, Wq, Wk, Wv, Wo, bq, bk, bv, bo, bn_* (two loops!)
    const float* x   = (const float*)d_in[0];
    const float* Wq  = (const float*)d_in[1];
    const float* Wk  = (const float*)d_in[2];
    const float* Wv  = (const float*)d_in[3];
    const float* Wo  = (const float*)d_in[4];
    const float* bq  = (const float*)d_in[5];
    const float* bk  = (const float*)d_in[6];
    const float* bv  = (const float*)d_in[7];
    const float* bo  = (const float*)d_in[8];
    const float* bns = (const float*)d_in[9];
    const float* bnb = (const float*)d_in[10];
    const float* bnm = (const float*)d_in[11];
    const float* bnv = (const float*)d_in[12];
    float* out = (float*)d_out;

    void *xh, *xl, *qh, *kh, *v, *vsh, *vsl, *S;
    void *WqT, *WkT, *WvhT, *WvlT, *WohT, *WolT;
    void *pm, *pl, *rowm, *rowinvl, *cpart, *srow;
    cudaGetSymbolAddress(&xh,   g_xh);   cudaGetSymbolAddress(&xl,   g_xl);
    cudaGetSymbolAddress(&qh,   g_qh);   cudaGetSymbolAddress(&kh,   g_kh);
    cudaGetSymbolAddress(&v,    g_v);
    cudaGetSymbolAddress(&vsh,  g_vsh);  cudaGetSymbolAddress(&vsl,  g_vsl);
    cudaGetSymbolAddress(&S,    g_S);
    cudaGetSymbolAddress(&WqT,  g_WqT);  cudaGetSymbolAddress(&WkT,  g_WkT);
    cudaGetSymbolAddress(&WvhT, g_WvhT); cudaGetSymbolAddress(&WvlT, g_WvlT);
    cudaGetSymbolAddress(&WohT, g_WohT); cudaGetSymbolAddress(&WolT, g_WolT);
    cudaGetSymbolAddress(&pm,      g_pm);
    cudaGetSymbolAddress(&pl,      g_pl);
    cudaGetSymbolAddress(&rowm,    g_rowm);
    cudaGetSymbolAddress(&rowinvl, g_rowinvl);
    cudaGetSymbolAddress(&cpart,   g_cpart);
    cudaGetSymbolAddress(&srow,    g_srow);

    static bool attr_done = false;
    if (!attr_done) {
        cudaFuncSetAttribute(mma_gemm_kernel<1, 0>,
            cudaFuncAttributeMaxDynamicSharedMemorySize, 49152);
        cudaFuncSetAttribute(mma_gemm_kernel<3, 1>,
            cudaFuncAttributeMaxDynamicSharedMemorySize, 98304);
        cudaFuncSetAttribute(mma_gemm_kernel<3, 2>,
            cudaFuncAttributeMaxDynamicSharedMemorySize, 98304);
        attr_done = true;
    }

    dim3 blk(256);
    dim3 gProj(CC / 128, MM / 128);           // (4, 64)
    dim3 gProj2(CC / 128, MM / 128, 2);       // fused q+k projections

    // P1: split x into bf16 hi/lo
    split_kernel<<<(MM * CC) / 1024, blk>>>(x, (__nv_bfloat16*)xh, (__nv_bfloat16*)xl);
    // P2: transpose+split all weights (one launch)
    wprep_all_kernel<<<dim3(16, 16, 4), dim3(32, 32)>>>(
        Wq, Wk, Wv, Wo,
        (__nv_bfloat16*)WqT, (__nv_bfloat16*)WkT,
        (__nv_bfloat16*)WvhT, (__nv_bfloat16*)WvlT,
        (__nv_bfloat16*)WohT, (__nv_bfloat16*)WolT);

    // G1+G2 fused: q,k projections in one launch (z selects Wq/Wk)
    mma_gemm_kernel<1, 0><<<gProj2, blk, 49152>>>(
        (const __nv_bfloat16*)xh, nullptr, (const __nv_bfloat16*)WqT, nullptr,
        qh, CC, CC, bq, nullptr, nullptr, nullptr, nullptr, nullptr,
        (const __nv_bfloat16*)WkT, bk, kh);
    // G3: v projection (split-bf16, fp32 out)
    mma_gemm_kernel<3, 1><<<gProj, blk, 98304>>>(
        (const __nv_bfloat16*)xh, (const __nv_bfloat16*)xl,
        (const __nv_bfloat16*)WvhT, (const __nv_bfloat16*)WvlT,
        v, CC, CC, bv, nullptr, nullptr, nullptr, nullptr, nullptr,
        nullptr, nullptr, nullptr);

    // K2: S = q @ k^T per batch + fused per-tile softmax stats
    qk_mma_kernel<<<dim3(32, 32, 2), blk>>>(
        (const __nv_bfloat16*)qh, (const __nv_bfloat16*)kh, (__nv_bfloat16*)S,
        (float*)pm, (float*)pl);

    // K3': combine partials -> rowm, rowinvl
    combine_kernel<<<MM / 256, blk>>>((const float*)pm, (const float*)pl,
                                      (float*)rowm, (float*)rowinvl);

    // K4: column sums -> s[n]
    colsum_part_kernel<<<dim3(4, 32, 2), blk>>>((const __nv_bfloat16*)S,
        (const float*)rowm, (const float*)rowinvl, (float*)cpart);
    colsum_final_kernel<<<MM / 256, blk>>>((const float*)cpart, (float*)srow);

    // P3: vs = v * s[row], split into bf16 hi/lo
    split_vs_kernel<<<(MM * CC) / 1024, blk>>>(
        (const float*)v, (const float*)srow,
        (__nv_bfloat16*)vsh, (__nv_bfloat16*)vsl);

    // G4: out = relu(BN(vs @ Wo + bo)) + x  (split-bf16, fp32 epilogue)
    mma_gemm_kernel<3, 2><<<gProj, blk, 98304>>>(
        (const __nv_bfloat16*)vsh, (const __nv_bfloat16*)vsl,
        (const __nv_bfloat16*)WohT, (const __nv_bfloat16*)WolT,
        out, CC, CC, bo, x, bns, bnb, bnm, bnv,
        nullptr, nullptr, nullptr);
}

// round 9
// speedup vs baseline: 6.1871x; 1.0110x over previous
#include <cuda_runtime.h>
#include <cuda_bf16.h>
#include <math.h>
#include <stdint.h>

// Problem dims (fixed by the dataset)
static constexpr int  BB  = 2;
static constexpr int  NN_ = 4096;
static constexpr int  CC  = 512;
static constexpr int  MM  = BB * NN_;               // 8192 rows total
static constexpr size_t SBATCH = (size_t)NN_ * NN_; // 16777216

// Scratch (device globals: no cudaMalloc allowed)
__device__ __align__(256) unsigned short g_xh[(size_t)MM * CC];  // bf16 x hi
__device__ __align__(256) unsigned short g_xl[(size_t)MM * CC];  // bf16 x lo
__device__ __align__(256) unsigned short g_qh[(size_t)MM * CC];  // bf16 q
__device__ __align__(256) unsigned short g_kh[(size_t)MM * CC];  // bf16 k
__device__ __align__(256) float          g_v [(size_t)MM * CC];  // fp32 v
__device__ __align__(256) unsigned short g_vsh[(size_t)MM * CC]; // bf16 v*s hi
__device__ __align__(256) unsigned short g_vsl[(size_t)MM * CC]; // bf16 v*s lo
__device__ __align__(256) unsigned short g_S [(size_t)BB * SBATCH]; // bf16 logits
// transposed weights [N x K] bf16
__device__ __align__(256) unsigned short g_WqT[CC * CC];
__device__ __align__(256) unsigned short g_WkT[CC * CC];
__device__ __align__(256) unsigned short g_WvhT[CC * CC];
__device__ __align__(256) unsigned short g_WvlT[CC * CC];
__device__ __align__(256) unsigned short g_WohT[CC * CC];
__device__ __align__(256) unsigned short g_WolT[CC * CC];
// per-(row, n-tile) softmax partials (32 n-tiles per batch row)
__device__ float g_pm[32 * MM];
__device__ float g_pl[32 * MM];
__device__ float g_cpart[32 * MM];
__device__ float g_srow[MM];

// ---------------------------------------------------------------------------
// PTX helpers (plain sm_103-compatible: mma.sync / ldmatrix / cp.async)
// ---------------------------------------------------------------------------
__device__ __forceinline__ uint32_t smem_u32(const void* p) {
    uint32_t a;
    asm("{ .reg .u64 t; cvta.to.shared.u64 t, %1; cvt.u32.u64 %0, t; }"
        : "=r"(a) : "l"(p));
    return a;
}
__device__ __forceinline__ void cp_async16(uint32_t dst, const void* src) {
    asm volatile("cp.async.cg.shared.global [%0], [%1], 16;"
                 :: "r"(dst), "l"(src) : "memory");
}
__device__ __forceinline__ void cp_commit() {
    asm volatile("cp.async.commit_group;" ::: "memory");
}
template<int N>
__device__ __forceinline__ void cp_wait() {
    asm volatile("cp.async.wait_group %0;" :: "n"(N) : "memory");
}
__device__ __forceinline__ void ldmatrix_x4(uint32_t& r0, uint32_t& r1,
                                            uint32_t& r2, uint32_t& r3,
                                            uint32_t addr) {
    asm volatile("ldmatrix.sync.aligned.m8n8.x4.shared.b16 {%0,%1,%2,%3}, [%4];"
                 : "=r"(r0), "=r"(r1), "=r"(r2), "=r"(r3) : "r"(addr));
}
__device__ __forceinline__ void mma_bf16(float& c0, float& c1, float& c2, float& c3,
                                         uint32_t a0, uint32_t a1, uint32_t a2, uint32_t a3,
                                         uint32_t b0, uint32_t b1) {
    asm volatile(
        "mma.sync.aligned.m16n8k16.row.col.f32.bf16.bf16.f32 "
        "{%0,%1,%2,%3}, {%4,%5,%6,%7}, {%8,%9}, {%0,%1,%2,%3};"
        : "+f"(c0), "+f"(c1), "+f"(c2), "+f"(c3)
        : "r"(a0), "r"(a1), "r"(a2), "r"(a3), "r"(b0), "r"(b1));
}

// smem tile layout: row-major [row][32 bf16] = 64B/row; 16B granules XOR-swizzled
__device__ __forceinline__ uint32_t sw_off(int row, int kg) {
    return (uint32_t)(row * 64 + ((kg ^ ((row >> 1) & 3)) << 4));
}

// exp via MUFU ex2.approx (1 FMA + 1 MUFU; overlaps with FMA pipe).
__device__ __forceinline__ float fexp(float x) {
    float y = x * 1.4426950408889634f;
    float r;
    asm("ex2.approx.f32 %0, %1;" : "=f"(r) : "f"(y));
    return r;
}

// ---------------------------------------------------------------------------
// K2: S[b] = q[b] @ k[b]^T via mma.sync bf16. Block tile 128x128, BK=32,
// 8 warps (4M x 2N, warp tile 32x64), 3-stage cp.async pipeline.
// Fused epilogue: writes bf16 S AND per-tile softmax partials (rowmax, sumexp).
// rowmax uses raw fp32 acc (valid: m cancels exactly in final s[n]).
// ---------------------------------------------------------------------------
__global__ void __launch_bounds__(256, 2)
qk_mma_kernel(const __nv_bfloat16* __restrict__ Q,
              const __nv_bfloat16* __restrict__ Kmat,
              __nv_bfloat16* __restrict__ S,
              float* __restrict__ pm, float* __restrict__ pl)
{
    __shared__ __align__(1024) char smem[3 * 16384];
    const uint32_t sbase = smem_u32(smem);

    const int tid = threadIdx.x;
    const int wid = tid >> 5;
    const int lid = tid & 31;
    const int wm  = wid & 3;
    const int wn  = wid >> 2;
    const int n0  = blockIdx.x * 128;
    const int m0  = blockIdx.y * 128;
    const int bz  = blockIdx.z;

    const __nv_bfloat16* Qb = Q    + ((size_t)bz * NN_ + m0) * CC;
    const __nv_bfloat16* Kb = Kmat + ((size_t)bz * NN_ + n0) * CC;

    const int mgrp = lid >> 3;
    const int lr   = lid & 7;
    uint32_t aoff[2][2], boff[4][2];
#pragma unroll
    for (int mt = 0; mt < 2; mt++)
#pragma unroll
        for (int kh = 0; kh < 2; kh++) {
            int row = wm * 32 + mt * 16 + lr + ((mgrp & 1) << 3);
            int kg  = 2 * kh + (mgrp >> 1);
            aoff[mt][kh] = sw_off(row, kg);
        }
#pragma unroll
    for (int i = 0; i < 4; i++)
#pragma unroll
        for (int kh = 0; kh < 2; kh++) {
            int row = wn * 64 + i * 16 + lr + ((mgrp >> 1) << 3);
            int kg  = 2 * kh + (mgrp & 1);
            boff[i][kh] = 8192u + sw_off(row, kg);
        }

    float acc[2][8][4];
#pragma unroll
    for (int mt = 0; mt < 2; mt++)
#pragma unroll
        for (int nt = 0; nt < 8; nt++)
#pragma unroll
            for (int e = 0; e < 4; e++) acc[mt][nt][e] = 0.0f;

    auto load_stage = [&](int kb, int buf) {
        uint32_t dstb = sbase + buf * 16384;
#pragma unroll
        for (int it = 0; it < 2; it++) {
            int idx = tid + it * 256;
            int row = idx >> 2, kg = idx & 3;
            cp_async16(dstb + sw_off(row, kg), Qb + (size_t)row * CC + kb * 32 + kg * 8);
        }
#pragma unroll
        for (int it = 0; it < 2; it++) {
            int idx = tid + it * 256;
            int row = idx >> 2, kg = idx & 3;
            cp_async16(dstb + 8192 + sw_off(row, kg), Kb + (size_t)row * CC + kb * 32 + kg * 8);
        }
        cp_commit();
    };

    load_stage(0, 0);
    load_stage(1, 1);

    const int KB = CC / 32;
    for (int kb = 0; kb < KB; kb++) {
        const int buf = kb % 3;
        if (kb < KB - 1) cp_wait<1>(); else cp_wait<0>();
        __syncthreads();
        if (kb + 2 < KB) load_stage(kb + 2, (kb + 2) % 3);

        const uint32_t stb = sbase + buf * 16384;
#pragma unroll
        for (int kh = 0; kh < 2; kh++) {
            uint32_t af[2][4], bf[4][4];
#pragma unroll
            for (int mt = 0; mt < 2; mt++)
                ldmatrix_x4(af[mt][0], af[mt][1], af[mt][2], af[mt][3],
                            stb + aoff[mt][kh]);
#pragma unroll
            for (int i = 0; i < 4; i++)
                ldmatrix_x4(bf[i][0], bf[i][1], bf[i][2], bf[i][3],
                            stb + boff[i][kh]);
#pragma unroll
            for (int mt = 0; mt < 2; mt++)
#pragma unroll
                for (int i = 0; i < 4; i++) {
                    mma_bf16(acc[mt][2*i][0], acc[mt][2*i][1], acc[mt][2*i][2], acc[mt][2*i][3],
                             af[mt][0], af[mt][1], af[mt][2], af[mt][3],
                             bf[i][0], bf[i][1]);
                    mma_bf16(acc[mt][2*i+1][0], acc[mt][2*i+1][1], acc[mt][2*i+1][2], acc[mt][2*i+1][3],
                             af[mt][0], af[mt][1], af[mt][2], af[mt][3],
                             bf[i][2], bf[i][3]);
                }
        }
    }

    __syncthreads();   // pipeline smem now reusable for reductions

    float* s_red = (float*)smem;        // [128][2] per-(row, wn) max
    float* s_tm  = s_red + 256;         // [128] tile row max
    float* s_l   = s_tm + 128;          // [128][2] per-(row, wn) sumexp

    const int grow = lid >> 2;
    const int gcol = (lid & 3) * 2;

    // Sweep 1: per-thread row maxes over raw fp32 acc
    float pmax[2][2];
#pragma unroll
    for (int mt = 0; mt < 2; mt++) { pmax[mt][0] = -3.0e38f; pmax[mt][1] = -3.0e38f; }
#pragma unroll
    for (int mt = 0; mt < 2; mt++)
#pragma unroll
        for (int nt = 0; nt < 8; nt++) {
            pmax[mt][0] = fmaxf(pmax[mt][0], fmaxf(acc[mt][nt][0], acc[mt][nt][1]));
            pmax[mt][1] = fmaxf(pmax[mt][1], fmaxf(acc[mt][nt][2], acc[mt][nt][3]));
        }
#pragma unroll
    for (int mt = 0; mt < 2; mt++)
#pragma unroll
        for (int h = 0; h < 2; h++) {
            float v = pmax[mt][h];
            v = fmaxf(v, __shfl_xor_sync(0xffffffffu, v, 1));
            v = fmaxf(v, __shfl_xor_sync(0xffffffffu, v, 2));
            if ((lid & 3) == 0)
                s_red[(wm * 32 + mt * 16 + h * 8 + grow) * 2 + wn] = v;
        }
    __syncthreads();
    if (tid < 128) s_tm[tid] = fmaxf(s_red[tid * 2], s_red[tid * 2 + 1]);
    __syncthreads();

    // Sweep 2: store bf16 S + per-thread sumexp (from bf16-rounded values)
    float psum[2][2] = {{0.0f, 0.0f}, {0.0f, 0.0f}};
#pragma unroll
    for (int mt = 0; mt < 2; mt++) {
        const float tm0 = s_tm[wm * 32 + mt * 16 + grow];
        const float tm1 = s_tm[wm * 32 + mt * 16 + 8 + grow];
        const int rowa = m0 + wm * 32 + mt * 16 + grow;
#pragma unroll
        for (int nt = 0; nt < 8; nt++) {
            const int col = n0 + wn * 64 + nt * 8 + gcol;
            __nv_bfloat162 h0 = __float22bfloat162_rn(
                make_float2(acc[mt][nt][0], acc[mt][nt][1]));
            __nv_bfloat162 h1 = __float22bfloat162_rn(
                make_float2(acc[mt][nt][2], acc[mt][nt][3]));
            *(__nv_bfloat162*)(S + (size_t)bz * SBATCH + (size_t)rowa * NN_ + col) = h0;
            *(__nv_bfloat162*)(S + (size_t)bz * SBATCH + (size_t)(rowa + 8) * NN_ + col) = h1;
            float2 f0 = __bfloat1622float2(h0);
            float2 f1 = __bfloat1622float2(h1);
            psum[mt][0] += fexp(f0.x - tm0) + fexp(f0.y - tm0);
            psum[mt][1] += fexp(f1.x - tm1) + fexp(f1.y - tm1);
        }
    }
#pragma unroll
    for (int mt = 0; mt < 2; mt++)
#pragma unroll
        for (int h = 0; h < 2; h++) {
            float v = psum[mt][h];
            v += __shfl_xor_sync(0xffffffffu, v, 1);
            v += __shfl_xor_sync(0xffffffffu, v, 2);
            if ((lid & 3) == 0)
                s_l[(wm * 32 + mt * 16 + h * 8 + grow) * 2 + wn] = v;
        }
    __syncthreads();
    if (tid < 128) {
        const size_t brow = (size_t)bz * NN_ + m0 + tid;
        pm[(size_t)blockIdx.x * MM + brow] = s_tm[tid];
        pl[(size_t)blockIdx.x * MM + brow] = s_l[tid * 2] + s_l[tid * 2 + 1];
    }
}

// ---------------------------------------------------------------------------
// Generic mma GEMM: C[M x N] = sum over TERMS of A-variants @ B-variants^T.
// TERMS=1: Ah@Bh.  TERMS=3: Ah@Bh + Ah@Bl + Al@Bh (split-bf16 fp32 emulation).
// EPI 0: +bias -> bf16 out. EPI 1: +bias -> fp32 out.
// EPI 2: +bias, BN, relu, +xres -> fp32 out.
// If gridDim.z == 2, blockIdx.z == 1 switches to (Bh2, bias2, Cout2).
// __launch_bounds__(256, 2): cap regs at 128 so 2 CTAs/SM fit the regfile.
// ---------------------------------------------------------------------------
template<int TERMS, int EPI>
__global__ void __launch_bounds__(256, 2)
mma_gemm_kernel(const __nv_bfloat16* __restrict__ Ah,
                const __nv_bfloat16* __restrict__ Al,
                const __nv_bfloat16* __restrict__ Bh,
                const __nv_bfloat16* __restrict__ Bl,
                void* __restrict__ Cout, int N, int K,
                const float* __restrict__ bias,
                const float* __restrict__ xres,
                const float* __restrict__ bns,
                const float* __restrict__ bnb,
                const float* __restrict__ bnm,
                const float* __restrict__ bnv,
                const __nv_bfloat16* __restrict__ Bh2,
                const float* __restrict__ bias2,
                void* __restrict__ Cout2)
{
    constexpr int STAGE = (TERMS == 3) ? 32768 : 16384;
    constexpr uint32_t BOFF = (TERMS == 3) ? 16384u : 8192u;
    extern __shared__ __align__(1024) char smem[];
    const uint32_t sbase = smem_u32(smem);

    if (blockIdx.z == 1) { Bh = Bh2; bias = bias2; Cout = Cout2; }

    const int tid = threadIdx.x;
    const int wid = tid >> 5;
    const int lid = tid & 31;
    const int wm  = wid & 3;
    const int wn  = wid >> 2;
    const int n0  = blockIdx.x * 128;
    const int m0  = blockIdx.y * 128;

    const __nv_bfloat16* Ahb = Ah + (size_t)m0 * K;
    const __nv_bfloat16* Alb = (TERMS == 3) ? Al + (size_t)m0 * K : nullptr;
    const __nv_bfloat16* Bhb = Bh + (size_t)n0 * K;
    const __nv_bfloat16* Blb = (TERMS == 3) ? Bl + (size_t)n0 * K : nullptr;

    const int mgrp = lid >> 3;
    const int lr   = lid & 7;
    uint32_t aoff[2][2], boff[4][2];
#pragma unroll
    for (int mt = 0; mt < 2; mt++)
#pragma unroll
        for (int kh = 0; kh < 2; kh++) {
            int row = wm * 32 + mt * 16 + lr + ((mgrp & 1) << 3);
            int kg  = 2 * kh + (mgrp >> 1);
            aoff[mt][kh] = sw_off(row, kg);
        }
#pragma unroll
    for (int i = 0; i < 4; i++)
#pragma unroll
        for (int kh = 0; kh < 2; kh++) {
            int row = wn * 64 + i * 16 + lr + ((mgrp >> 1) << 3);
            int kg  = 2 * kh + (mgrp & 1);
            boff[i][kh] = BOFF + sw_off(row, kg);
        }

    float acc[2][8][4];
#pragma unroll
    for (int mt = 0; mt < 2; mt++)
#pragma unroll
        for (int nt = 0; nt < 8; nt++)
#pragma unroll
            for (int e = 0; e < 4; e++) acc[mt][nt][e] = 0.0f;

    auto load_stage = [&](int kb, int buf) {
        uint32_t dstb = sbase + buf * STAGE;
#pragma unroll
        for (int it = 0; it < 2; it++) {
            int idx = tid + it * 256;
            int row = idx >> 2, kg = idx & 3;
            size_t goff = (size_t)row * K + kb * 32 + kg * 8;
            uint32_t so = sw_off(row, kg);
            cp_async16(dstb + so, Ahb + goff);
            if (TERMS == 3) cp_async16(dstb + 8192u + so, Alb + goff);
            cp_async16(dstb + BOFF + so, Bhb + goff);
            if (TERMS == 3) cp_async16(dstb + BOFF + 8192u + so, Blb + goff);
        }
        cp_commit();
    };

    load_stage(0, 0);
    load_stage(1, 1);

    const int KB = K / 32;
    for (int kb = 0; kb < KB; kb++) {
        const int buf = kb % 3;
        if (kb < KB - 1) cp_wait<1>(); else cp_wait<0>();
        __syncthreads();
        if (kb + 2 < KB) load_stage(kb + 2, (kb + 2) % 3);

        const uint32_t stb = sbase + buf * STAGE;
#pragma unroll
        for (int kh = 0; kh < 2; kh++) {
            uint32_t afh[2][4], bfh[4][4];
            uint32_t afl[2][4], bfl[4][4];
#pragma unroll
            for (int mt = 0; mt < 2; mt++) {
                ldmatrix_x4(afh[mt][0], afh[mt][1], afh[mt][2], afh[mt][3],
                            stb + aoff[mt][kh]);
                if (TERMS == 3)
                    ldmatrix_x4(afl[mt][0], afl[mt][1], afl[mt][2], afl[mt][3],
                                stb + 8192u + aoff[mt][kh]);
            }
#pragma unroll
            for (int i = 0; i < 4; i++) {
                ldmatrix_x4(bfh[i][0], bfh[i][1], bfh[i][2], bfh[i][3],
                            stb + boff[i][kh]);
                if (TERMS == 3)
                    ldmatrix_x4(bfl[i][0], bfl[i][1], bfl[i][2], bfl[i][3],
                                stb + 8192u + boff[i][kh]);
            }
#pragma unroll
            for (int mt = 0; mt < 2; mt++)
#pragma unroll
                for (int i = 0; i < 4; i++) {
#pragma unroll
                    for (int h = 0; h < 2; h++) {
                        float* c0 = acc[mt][2*i + h];
                        mma_bf16(c0[0], c0[1], c0[2], c0[3],
                                 afh[mt][0], afh[mt][1], afh[mt][2], afh[mt][3],
                                 bfh[i][2*h], bfh[i][2*h + 1]);
                        if (TERMS == 3) {
                            mma_bf16(c0[0], c0[1], c0[2], c0[3],
                                     afh[mt][0], afh[mt][1], afh[mt][2], afh[mt][3],
                                     bfl[i][2*h], bfl[i][2*h + 1]);
                            mma_bf16(c0[0], c0[1], c0[2], c0[3],
                                     afl[mt][0], afl[mt][1], afl[mt][2], afl[mt][3],
                                     bfh[i][2*h], bfh[i][2*h + 1]);
                        }
                    }
                }
        }
    }

    const int grow = lid >> 2;
    const int gcol = (lid & 3) * 2;
#pragma unroll
    for (int mt = 0; mt < 2; mt++) {
#pragma unroll
        for (int nt = 0; nt < 8; nt++) {
            const int col  = n0 + wn * 64 + nt * 8 + gcol;
            const int rowa = m0 + wm * 32 + mt * 16 + grow;
            float b0 = bias[col], b1 = bias[col + 1];
            float v00 = acc[mt][nt][0] + b0, v01 = acc[mt][nt][1] + b1;
            float v10 = acc[mt][nt][2] + b0, v11 = acc[mt][nt][3] + b1;
            if (EPI == 0) {
                *(__nv_bfloat162*)((__nv_bfloat16*)Cout + (size_t)rowa * N + col)
                    = __float22bfloat162_rn(make_float2(v00, v01));
                *(__nv_bfloat162*)((__nv_bfloat16*)Cout + (size_t)(rowa + 8) * N + col)
                    = __float22bfloat162_rn(make_float2(v10, v11));
            } else if (EPI == 1) {
                *(float2*)((float*)Cout + (size_t)rowa * N + col)
                    = make_float2(v00, v01);
                *(float2*)((float*)Cout + (size_t)(rowa + 8) * N + col)
                    = make_float2(v10, v11);
            } else {
                float g0 = rsqrtf(bnv[col] + 1e-5f) * bns[col];
                float g1 = rsqrtf(bnv[col + 1] + 1e-5f) * bns[col + 1];
                float m0c = bnm[col], m1c = bnm[col + 1];
                float a0 = bnb[col], a1 = bnb[col + 1];
                v00 = fmaxf((v00 - m0c) * g0 + a0, 0.0f);
                v01 = fmaxf((v01 - m1c) * g1 + a1, 0.0f);
                v10 = fmaxf((v10 - m0c) * g0 + a0, 0.0f);
                v11 = fmaxf((v11 - m1c) * g1 + a1, 0.0f);
                float2 r0 = *(const float2*)(xres + (size_t)rowa * N + col);
                float2 r1 = *(const float2*)(xres + (size_t)(rowa + 8) * N + col);
                *(float2*)((float*)Cout + (size_t)rowa * N + col)
                    = make_float2(v00 + r0.x, v01 + r0.y);
                *(float2*)((float*)Cout + (size_t)(rowa + 8) * N + col)
                    = make_float2(v10 + r1.x, v11 + r1.y);
            }
        }
    }
}

// ---------------------------------------------------------------------------
// Prep kernels
// ---------------------------------------------------------------------------
__global__ void __launch_bounds__(256)
split_kernel(const float* __restrict__ x,
             __nv_bfloat16* __restrict__ xh, __nv_bfloat16* __restrict__ xl)
{
    size_t i = ((size_t)blockIdx.x * 256 + threadIdx.x) * 4;
    float4 v = *(const float4*)(x + i);
    __nv_bfloat16 h0 = __float2bfloat16(v.x), h1 = __float2bfloat16(v.y);
    __nv_bfloat16 h2 = __float2bfloat16(v.z), h3 = __float2bfloat16(v.w);
    __nv_bfloat16 l0 = __float2bfloat16(v.x - __bfloat162float(h0));
    __nv_bfloat16 l1 = __float2bfloat16(v.y - __bfloat162float(h1));
    __nv_bfloat16 l2 = __float2bfloat16(v.z - __bfloat162float(h2));
    __nv_bfloat16 l3 = __float2bfloat16(v.w - __bfloat162float(h3));
    __nv_bfloat162 hp[2] = {{h0, h1}, {h2, h3}};
    __nv_bfloat162 lp[2] = {{l0, l1}, {l2, l3}};
    *(uint2*)(xh + i) = *(uint2*)hp;
    *(uint2*)(xl + i) = *(uint2*)lp;
}

__global__ void __launch_bounds__(256)
split_vs_kernel(const float* __restrict__ v, const float* __restrict__ srow,
                __nv_bfloat16* __restrict__ vh, __nv_bfloat16* __restrict__ vl)
{
    size_t i = ((size_t)blockIdx.x * 256 + threadIdx.x) * 4;
    float s = srow[i >> 9];
    float4 x = *(const float4*)(v + i);
    x.x *= s; x.y *= s; x.z *= s; x.w *= s;
    __nv_bfloat16 h0 = __float2bfloat16(x.x), h1 = __float2bfloat16(x.y);
    __nv_bfloat16 h2 = __float2bfloat16(x.z), h3 = __float2bfloat16(x.w);
    __nv_bfloat16 l0 = __float2bfloat16(x.x - __bfloat162float(h0));
    __nv_bfloat16 l1 = __float2bfloat16(x.y - __bfloat162float(h1));
    __nv_bfloat16 l2 = __float2bfloat16(x.z - __bfloat162float(h2));
    __nv_bfloat16 l3 = __float2bfloat16(x.w - __bfloat162float(h3));
    __nv_bfloat162 hp[2] = {{h0, h1}, {h2, h3}};
    __nv_bfloat162 lp[2] = {{l0, l1}, {l2, l3}};
    *(uint2*)(vh + i) = *(uint2*)hp;
    *(uint2*)(vl + i) = *(uint2*)lp;
}

// Transpose+split all 4 weights in ONE launch (z selects the weight).
__global__ void __launch_bounds__(1024)
wprep_all_kernel(const float* __restrict__ Wq, const float* __restrict__ Wk,
                 const float* __restrict__ Wv, const float* __restrict__ Wo,
                 __nv_bfloat16* __restrict__ WqT, __nv_bfloat16* __restrict__ WkT,
                 __nv_bfloat16* __restrict__ WvhT, __nv_bfloat16* __restrict__ WvlT,
                 __nv_bfloat16* __restrict__ WohT, __nv_bfloat16* __restrict__ WolT)
{
    const float* W;
    __nv_bfloat16 *Th, *Tl = nullptr;
    switch (blockIdx.z) {
        case 0:  W = Wq; Th = WqT;  break;
        case 1:  W = Wk; Th = WkT;  break;
        case 2:  W = Wv; Th = WvhT; Tl = WvlT; break;
        default: W = Wo; Th = WohT; Tl = WolT; break;
    }
    __shared__ float t[32][33];
    const int tx = threadIdx.x, ty = threadIdx.y;
    const int bx = blockIdx.x * 32, by = blockIdx.y * 32;
    t[ty][tx] = W[(size_t)(by + ty) * CC + bx + tx];
    __syncthreads();
    const int n = bx + ty, k = by + tx;
    float v = t[tx][ty];
    __nv_bfloat16 h = __float2bfloat16(v);
    Th[(size_t)n * CC + k] = h;
    if (Tl) Tl[(size_t)n * CC + k] = __float2bfloat16(v - __bfloat162float(h));
}

// ---------------------------------------------------------------------------
// Column sums of normalized attention (bf16 S), 32-way m-split, 4 cols/thread.
// Fused combine: each block derives rowm/rowinvl for its 128 rows from pm/pl.
// ---------------------------------------------------------------------------
__global__ void __launch_bounds__(256)
colsum_part_kernel(const __nv_bfloat16* __restrict__ S,
                   const float* __restrict__ pm,
                   const float* __restrict__ pl,
                   float* __restrict__ cpart)
{
    __shared__ float sm[128], si[128];
    const int b     = blockIdx.z;
    const int n     = blockIdx.x * 1024 + threadIdx.x * 4;
    const int m0    = blockIdx.y * 128;
    const int rbase = b * 4096;
    if (threadIdx.x < 128) {
        const int r = rbase + m0 + threadIdx.x;
        float M = -3.0e38f;
#pragma unroll
        for (int t = 0; t < 32; t++) M = fmaxf(M, pm[(size_t)t * MM + r]);
        float L = 0.0f;
#pragma unroll
        for (int t = 0; t < 32; t++)
            L += pl[(size_t)t * MM + r] * fexp(pm[(size_t)t * MM + r] - M);
        sm[threadIdx.x] = M;
        si[threadIdx.x] = 1.0f / L;
    }
    __syncthreads();
    const __nv_bfloat16* Sb = S + (size_t)b * SBATCH + (size_t)m0 * 4096 + n;
    float a0 = 0.0f, a1 = 0.0f, a2 = 0.0f, a3 = 0.0f;
#pragma unroll 4
    for (int mm = 0; mm < 128; mm++) {
        uint2 u = *(const uint2*)(Sb + (size_t)mm * 4096);
        float2 f0 = __bfloat1622float2(reinterpret_cast<__nv_bfloat162&>(u.x));
        float2 f1 = __bfloat1622float2(reinterpret_cast<__nv_bfloat162&>(u.y));
        float m = sm[mm], iv = si[mm];
        a0 += fexp(f0.x - m) * iv;
        a1 += fexp(f0.y - m) * iv;
        a2 += fexp(f1.x - m) * iv;
        a3 += fexp(f1.y - m) * iv;
    }
    *(float4*)(cpart + (size_t)blockIdx.y * MM + rbase + n)
        = make_float4(a0, a1, a2, a3);
}

__global__ void __launch_bounds__(256)
colsum_final_kernel(const float* __restrict__ cpart, float* __restrict__ srow)
{
    const int i = blockIdx.x * 256 + threadIdx.x;
    float c = 0.0f;
#pragma unroll
    for (int p = 0; p < 32; p++) c += cpart[(size_t)p * MM + i];
    srow[i] = c / (c + 1e-9f);
}

// ---------------------------------------------------------------------------
extern "C" void kernel_launch(void* const* d_in, const int* in_sizes, int n_in,
                              void* d_out, int out_size)
{
    // metadata order: inputs, Wq, Wk, Wv, Wo, bq, bk, bv, bo, bn_* (two loops!)
    const float* x   = (const float*)d_in[0];
    const float* Wq  = (const float*)d_in[1];
    const float* Wk  = (const float*)d_in[2];
    const float* Wv  = (const float*)d_in[3];
    const float* Wo  = (const float*)d_in[4];
    const float* bq  = (const float*)d_in[5];
    const float* bk  = (const float*)d_in[6];
    const float* bv  = (const float*)d_in[7];
    const float* bo  = (const float*)d_in[8];
    const float* bns = (const float*)d_in[9];
    const float* bnb = (const float*)d_in[10];
    const float* bnm = (const float*)d_in[11];
    const float* bnv = (const float*)d_in[12];
    float* out = (float*)d_out;

    void *xh, *xl, *qh, *kh, *v, *vsh, *vsl, *S;
    void *WqT, *WkT, *WvhT, *WvlT, *WohT, *WolT;
    void *pm, *pl, *cpart, *srow;
    cudaGetSymbolAddress(&xh,   g_xh);   cudaGetSymbolAddress(&xl,   g_xl);
    cudaGetSymbolAddress(&qh,   g_qh);   cudaGetSymbolAddress(&kh,   g_kh);
    cudaGetSymbolAddress(&v,    g_v);
    cudaGetSymbolAddress(&vsh,  g_vsh);  cudaGetSymbolAddress(&vsl,  g_vsl);
    cudaGetSymbolAddress(&S,    g_S);
    cudaGetSymbolAddress(&WqT,  g_WqT);  cudaGetSymbolAddress(&WkT,  g_WkT);
    cudaGetSymbolAddress(&WvhT, g_WvhT); cudaGetSymbolAddress(&WvlT, g_WvlT);
    cudaGetSymbolAddress(&WohT, g_WohT); cudaGetSymbolAddress(&WolT, g_WolT);
    cudaGetSymbolAddress(&pm,    g_pm);
    cudaGetSymbolAddress(&pl,    g_pl);
    cudaGetSymbolAddress(&cpart, g_cpart);
    cudaGetSymbolAddress(&srow,  g_srow);

    // One-time resource setup (outside capture: the harness runs kernel_launch
    // once for correctness BEFORE capturing).
    static cudaStream_t s2 = nullptr;
    static cudaEvent_t  eFork = nullptr, eJoin = nullptr;
    if (s2 == nullptr) {
        cudaStreamCreateWithFlags(&s2, cudaStreamNonBlocking);
        cudaEventCreateWithFlags(&eFork, cudaEventDisableTiming);
        cudaEventCreateWithFlags(&eJoin, cudaEventDisableTiming);
        cudaFuncSetAttribute(mma_gemm_kernel<1, 0>,
            cudaFuncAttributeMaxDynamicSharedMemorySize, 49152);
        cudaFuncSetAttribute(mma_gemm_kernel<3, 1>,
            cudaFuncAttributeMaxDynamicSharedMemorySize, 98304);
        cudaFuncSetAttribute(mma_gemm_kernel<3, 2>,
            cudaFuncAttributeMaxDynamicSharedMemorySize, 98304);
    }

    dim3 blk(256);
    dim3 gProj(CC / 128, MM / 128);           // (4, 64)
    dim3 gProj2(CC / 128, MM / 128, 2);       // fused q+k projections

    // P1: split x into bf16 hi/lo
    split_kernel<<<(MM * CC) / 1024, blk>>>(x, (__nv_bfloat16*)xh, (__nv_bfloat16*)xl);
    // P2: transpose+split all weights (one launch)
    wprep_all_kernel<<<dim3(16, 16, 4), dim3(32, 32)>>>(
        Wq, Wk, Wv, Wo,
        (__nv_bfloat16*)WqT, (__nv_bfloat16*)WkT,
        (__nv_bfloat16*)WvhT, (__nv_bfloat16*)WvlT,
        (__nv_bfloat16*)WohT, (__nv_bfloat16*)WolT);

    // Fork: G3 (v projection) runs on s2, overlapping G1+G2 and K2.
    cudaEventRecord(eFork, 0);
    cudaStreamWaitEvent(s2, eFork, 0);

    // G1+G2 fused: q,k projections in one launch (z selects Wq/Wk)
    mma_gemm_kernel<1, 0><<<gProj2, blk, 49152>>>(
        (const __nv_bfloat16*)xh, nullptr, (const __nv_bfloat16*)WqT, nullptr,
        qh, CC, CC, bq, nullptr, nullptr, nullptr, nullptr, nullptr,
        (const __nv_bfloat16*)WkT, bk, kh);

    // G3 on s2: v projection (split-bf16, fp32 out)
    mma_gemm_kernel<3, 1><<<gProj, blk, 98304, s2>>>(
        (const __nv_bfloat16*)xh, (const __nv_bfloat16*)xl,
        (const __nv_bfloat16*)WvhT, (const __nv_bfloat16*)WvlT,
        v, CC, CC, bv, nullptr, nullptr, nullptr, nullptr, nullptr,
        nullptr, nullptr, nullptr);
    cudaEventRecord(eJoin, s2);

    // K2: S = q @ k^T per batch + fused per-tile softmax stats
    qk_mma_kernel<<<dim3(32, 32, 2), blk>>>(
        (const __nv_bfloat16*)qh, (const __nv_bfloat16*)kh, (__nv_bfloat16*)S,
        (float*)pm, (float*)pl);

    // K4: column sums -> s[n] (combine fused into part kernel)
    colsum_part_kernel<<<dim3(4, 32, 2), blk>>>((const __nv_bfloat16*)S,
        (const float*)pm, (const float*)pl, (float*)cpart);
    colsum_final_kernel<<<MM / 256, blk>>>((const float*)cpart, (float*)srow);

    // Join: split_vs needs v (from G3 on s2) and srow.
    cudaStreamWaitEvent(0, eJoin, 0);

    // P3: vs = v * s[row], split into bf16 hi/lo
    split_vs_kernel<<<(MM * CC) / 1024, blk>>>(
        (const float*)v, (const float*)srow,
        (__nv_bfloat16*)vsh, (__nv_bfloat16*)vsl);

    // G4: out = relu(BN(vs @ Wo + bo)) + x  (split-bf16, fp32 epilogue)
    mma_gemm_kernel<3, 2><<<gProj, blk, 98304>>>(
        (const __nv_bfloat16*)vsh, (const __nv_bfloat16*)vsl,
        (const __nv_bfloat16*)WohT, (const __nv_bfloat16*)WolT,
        out, CC, CC, bo, x, bns, bnb, bnm, bnv,
        nullptr, nullptr, nullptr);
}

// round 10
// speedup vs baseline: 6.3233x; 1.0220x over previous
#include <cuda_runtime.h>
#include <cuda_bf16.h>
#include <math.h>
#include <stdint.h>

// Problem dims (fixed by the dataset)
static constexpr int  BB  = 2;
static constexpr int  NN_ = 4096;
static constexpr int  CC  = 512;
static constexpr int  MM  = BB * NN_;               // 8192 rows total
static constexpr size_t SBATCH = (size_t)NN_ * NN_; // 16777216

// Scratch (device globals: no cudaMalloc allowed)
__device__ __align__(256) unsigned short g_xh[(size_t)MM * CC];  // bf16 x hi
__device__ __align__(256) unsigned short g_xl[(size_t)MM * CC];  // bf16 x lo
__device__ __align__(256) unsigned short g_qh[(size_t)MM * CC];  // bf16 q
__device__ __align__(256) unsigned short g_kh[(size_t)MM * CC];  // bf16 k
__device__ __align__(256) float          g_v [(size_t)MM * CC];  // fp32 v
__device__ __align__(256) unsigned short g_vsh[(size_t)MM * CC]; // bf16 v*s hi
__device__ __align__(256) unsigned short g_vsl[(size_t)MM * CC]; // bf16 v*s lo
__device__ __align__(256) unsigned short g_S [(size_t)BB * SBATCH]; // bf16 logits
// transposed weights [N x K] bf16
__device__ __align__(256) unsigned short g_WqT[CC * CC];
__device__ __align__(256) unsigned short g_WkT[CC * CC];
__device__ __align__(256) unsigned short g_WvhT[CC * CC];
__device__ __align__(256) unsigned short g_WvlT[CC * CC];
__device__ __align__(256) unsigned short g_WohT[CC * CC];
__device__ __align__(256) unsigned short g_WolT[CC * CC];
// per-(row, n-tile) softmax partials (32 n-tiles per batch row)
__device__ float g_pm[32 * MM];
__device__ float g_pl[32 * MM];
__device__ float g_cpart[32 * MM];
__device__ float g_srow[MM];

// ---------------------------------------------------------------------------
// PTX helpers (plain sm_103-compatible: mma.sync / ldmatrix / cp.async)
// ---------------------------------------------------------------------------
__device__ __forceinline__ uint32_t smem_u32(const void* p) {
    uint32_t a;
    asm("{ .reg .u64 t; cvta.to.shared.u64 t, %1; cvt.u32.u64 %0, t; }"
        : "=r"(a) : "l"(p));
    return a;
}
__device__ __forceinline__ void cp_async16(uint32_t dst, const void* src) {
    asm volatile("cp.async.cg.shared.global [%0], [%1], 16;"
                 :: "r"(dst), "l"(src) : "memory");
}
__device__ __forceinline__ void cp_commit() {
    asm volatile("cp.async.commit_group;" ::: "memory");
}
template<int N>
__device__ __forceinline__ void cp_wait() {
    asm volatile("cp.async.wait_group %0;" :: "n"(N) : "memory");
}
__device__ __forceinline__ void ldmatrix_x4(uint32_t& r0, uint32_t& r1,
                                            uint32_t& r2, uint32_t& r3,
                                            uint32_t addr) {
    asm volatile("ldmatrix.sync.aligned.m8n8.x4.shared.b16 {%0,%1,%2,%3}, [%4];"
                 : "=r"(r0), "=r"(r1), "=r"(r2), "=r"(r3) : "r"(addr));
}
__device__ __forceinline__ void mma_bf16(float& c0, float& c1, float& c2, float& c3,
                                         uint32_t a0, uint32_t a1, uint32_t a2, uint32_t a3,
                                         uint32_t b0, uint32_t b1) {
    asm volatile(
        "mma.sync.aligned.m16n8k16.row.col.f32.bf16.bf16.f32 "
        "{%0,%1,%2,%3}, {%4,%5,%6,%7}, {%8,%9}, {%0,%1,%2,%3};"
        : "+f"(c0), "+f"(c1), "+f"(c2), "+f"(c3)
        : "r"(a0), "r"(a1), "r"(a2), "r"(a3), "r"(b0), "r"(b1));
}

// smem tile layout: row-major [row][32 bf16] = 64B/row; 16B granules XOR-swizzled
__device__ __forceinline__ uint32_t sw_off(int row, int kg) {
    return (uint32_t)(row * 64 + ((kg ^ ((row >> 1) & 3)) << 4));
}

// exp via MUFU ex2.approx (1 FMA + 1 MUFU; overlaps with FMA pipe).
__device__ __forceinline__ float fexp(float x) {
    float y = x * 1.4426950408889634f;
    float r;
    asm("ex2.approx.f32 %0, %1;" : "=f"(r) : "f"(y));
    return r;
}

// ---------------------------------------------------------------------------
// K2: S[b] = q[b] @ k[b]^T via mma.sync bf16. Block tile 128x128, BK=32,
// 8 warps (4M x 2N, warp tile 32x64), 3-stage cp.async pipeline.
// Fused epilogue: smem-staged COALESCED bf16 S store + per-tile softmax
// partials (rowmax from raw fp32 acc — m cancels exactly in final s[n]).
// ---------------------------------------------------------------------------
__global__ void __launch_bounds__(256, 2)
qk_mma_kernel(const __nv_bfloat16* __restrict__ Q,
              const __nv_bfloat16* __restrict__ Kmat,
              __nv_bfloat16* __restrict__ S,
              float* __restrict__ pm, float* __restrict__ pl)
{
    __shared__ __align__(1024) char smem[3 * 16384];
    const uint32_t sbase = smem_u32(smem);

    const int tid = threadIdx.x;
    const int wid = tid >> 5;
    const int lid = tid & 31;
    const int wm  = wid & 3;
    const int wn  = wid >> 2;
    const int n0  = blockIdx.x * 128;
    const int m0  = blockIdx.y * 128;
    const int bz  = blockIdx.z;

    const __nv_bfloat16* Qb = Q    + ((size_t)bz * NN_ + m0) * CC;
    const __nv_bfloat16* Kb = Kmat + ((size_t)bz * NN_ + n0) * CC;

    const int mgrp = lid >> 3;
    const int lr   = lid & 7;
    uint32_t aoff[2][2], boff[4][2];
#pragma unroll
    for (int mt = 0; mt < 2; mt++)
#pragma unroll
        for (int kh = 0; kh < 2; kh++) {
            int row = wm * 32 + mt * 16 + lr + ((mgrp & 1) << 3);
            int kg  = 2 * kh + (mgrp >> 1);
            aoff[mt][kh] = sw_off(row, kg);
        }
#pragma unroll
    for (int i = 0; i < 4; i++)
#pragma unroll
        for (int kh = 0; kh < 2; kh++) {
            int row = wn * 64 + i * 16 + lr + ((mgrp >> 1) << 3);
            int kg  = 2 * kh + (mgrp & 1);
            boff[i][kh] = 8192u + sw_off(row, kg);
        }

    float acc[2][8][4];
#pragma unroll
    for (int mt = 0; mt < 2; mt++)
#pragma unroll
        for (int nt = 0; nt < 8; nt++)
#pragma unroll
            for (int e = 0; e < 4; e++) acc[mt][nt][e] = 0.0f;

    auto load_stage = [&](int kb, int buf) {
        uint32_t dstb = sbase + buf * 16384;
#pragma unroll
        for (int it = 0; it < 2; it++) {
            int idx = tid + it * 256;
            int row = idx >> 2, kg = idx & 3;
            cp_async16(dstb + sw_off(row, kg), Qb + (size_t)row * CC + kb * 32 + kg * 8);
        }
#pragma unroll
        for (int it = 0; it < 2; it++) {
            int idx = tid + it * 256;
            int row = idx >> 2, kg = idx & 3;
            cp_async16(dstb + 8192 + sw_off(row, kg), Kb + (size_t)row * CC + kb * 32 + kg * 8);
        }
        cp_commit();
    };

    load_stage(0, 0);
    load_stage(1, 1);

    const int KB = CC / 32;
    for (int kb = 0; kb < KB; kb++) {
        const int buf = kb % 3;
        if (kb < KB - 1) cp_wait<1>(); else cp_wait<0>();
        __syncthreads();
        if (kb + 2 < KB) load_stage(kb + 2, (kb + 2) % 3);

        const uint32_t stb = sbase + buf * 16384;
#pragma unroll
        for (int kh = 0; kh < 2; kh++) {
            uint32_t af[2][4], bf[4][4];
#pragma unroll
            for (int mt = 0; mt < 2; mt++)
                ldmatrix_x4(af[mt][0], af[mt][1], af[mt][2], af[mt][3],
                            stb + aoff[mt][kh]);
#pragma unroll
            for (int i = 0; i < 4; i++)
                ldmatrix_x4(bf[i][0], bf[i][1], bf[i][2], bf[i][3],
                            stb + boff[i][kh]);
#pragma unroll
            for (int mt = 0; mt < 2; mt++)
#pragma unroll
                for (int i = 0; i < 4; i++) {
                    mma_bf16(acc[mt][2*i][0], acc[mt][2*i][1], acc[mt][2*i][2], acc[mt][2*i][3],
                             af[mt][0], af[mt][1], af[mt][2], af[mt][3],
                             bf[i][0], bf[i][1]);
                    mma_bf16(acc[mt][2*i+1][0], acc[mt][2*i+1][1], acc[mt][2*i+1][2], acc[mt][2*i+1][3],
                             af[mt][0], af[mt][1], af[mt][2], af[mt][3],
                             bf[i][2], bf[i][3]);
                }
        }
    }

    __syncthreads();   // pipeline smem now reusable

    // Layout of the 48KB smem in epilogue:
    //   [0, 32768): staged bf16 S tile [128][128]
    //   [32768, +): reduction scratch (s_red 256f, s_tm 128f, s_l 256f)
    __nv_bfloat16* sS = (__nv_bfloat16*)smem;
    float* s_red = (float*)(smem + 32768);
    float* s_tm  = s_red + 256;
    float* s_l   = s_tm + 128;

    const int grow = lid >> 2;
    const int gcol = (lid & 3) * 2;

    // Sweep 1: per-thread row maxes over raw fp32 acc
    float pmax[2][2];
#pragma unroll
    for (int mt = 0; mt < 2; mt++) { pmax[mt][0] = -3.0e38f; pmax[mt][1] = -3.0e38f; }
#pragma unroll
    for (int mt = 0; mt < 2; mt++)
#pragma unroll
        for (int nt = 0; nt < 8; nt++) {
            pmax[mt][0] = fmaxf(pmax[mt][0], fmaxf(acc[mt][nt][0], acc[mt][nt][1]));
            pmax[mt][1] = fmaxf(pmax[mt][1], fmaxf(acc[mt][nt][2], acc[mt][nt][3]));
        }
#pragma unroll
    for (int mt = 0; mt < 2; mt++)
#pragma unroll
        for (int h = 0; h < 2; h++) {
            float v = pmax[mt][h];
            v = fmaxf(v, __shfl_xor_sync(0xffffffffu, v, 1));
            v = fmaxf(v, __shfl_xor_sync(0xffffffffu, v, 2));
            if ((lid & 3) == 0)
                s_red[(wm * 32 + mt * 16 + h * 8 + grow) * 2 + wn] = v;
        }
    __syncthreads();
    if (tid < 128) s_tm[tid] = fmaxf(s_red[tid * 2], s_red[tid * 2 + 1]);
    __syncthreads();

    // Sweep 2: stage bf16 S tile in smem + per-thread sumexp
    float psum[2][2] = {{0.0f, 0.0f}, {0.0f, 0.0f}};
#pragma unroll
    for (int mt = 0; mt < 2; mt++) {
        const int rl0 = wm * 32 + mt * 16 + grow;
        const float tm0 = s_tm[rl0];
        const float tm1 = s_tm[rl0 + 8];
#pragma unroll
        for (int nt = 0; nt < 8; nt++) {
            const int cl = wn * 64 + nt * 8 + gcol;
            __nv_bfloat162 h0 = __float22bfloat162_rn(
                make_float2(acc[mt][nt][0], acc[mt][nt][1]));
            __nv_bfloat162 h1 = __float22bfloat162_rn(
                make_float2(acc[mt][nt][2], acc[mt][nt][3]));
            *(__nv_bfloat162*)(sS + rl0 * 128 + cl) = h0;
            *(__nv_bfloat162*)(sS + (rl0 + 8) * 128 + cl) = h1;
            float2 f0 = __bfloat1622float2(h0);
            float2 f1 = __bfloat1622float2(h1);
            psum[mt][0] += fexp(f0.x - tm0) + fexp(f0.y - tm0);
            psum[mt][1] += fexp(f1.x - tm1) + fexp(f1.y - tm1);
        }
    }
#pragma unroll
    for (int mt = 0; mt < 2; mt++)
#pragma unroll
        for (int h = 0; h < 2; h++) {
            float v = psum[mt][h];
            v += __shfl_xor_sync(0xffffffffu, v, 1);
            v += __shfl_xor_sync(0xffffffffu, v, 2);
            if ((lid & 3) == 0)
                s_l[(wm * 32 + mt * 16 + h * 8 + grow) * 2 + wn] = v;
        }
    __syncthreads();

    // Coalesced S store: 16 consecutive threads stream one 256B row.
    {
        __nv_bfloat16* Sg = S + (size_t)bz * SBATCH + (size_t)m0 * NN_ + n0;
#pragma unroll
        for (int it = 0; it < 8; it++) {
            int c   = tid + it * 256;        // 0..2047
            int row = c >> 4;
            int off = (c & 15) * 8;          // bf16 units
            *(uint4*)(Sg + (size_t)row * NN_ + off) = *(uint4*)(sS + row * 128 + off);
        }
    }
    if (tid < 128) {
        const size_t brow = (size_t)bz * NN_ + m0 + tid;
        pm[(size_t)blockIdx.x * MM + brow] = s_tm[tid];
        pl[(size_t)blockIdx.x * MM + brow] = s_l[tid * 2] + s_l[tid * 2 + 1];
    }
}

// ---------------------------------------------------------------------------
// Generic mma GEMM: C[M x N] = sum over TERMS of A-variants @ B-variants^T.
// TERMS=1: Ah@Bh.  TERMS=3: Ah@Bh + Ah@Bl + Al@Bh (split-bf16 fp32 emulation).
// EPI 0: +bias -> bf16 out (smem-staged coalesced store).
// EPI 1: +bias -> fp32 out.  EPI 2: +bias, BN, relu, +xres -> fp32 out.
// If gridDim.z == 2, blockIdx.z == 1 switches to (Bh2, bias2, Cout2).
// __launch_bounds__(256, 2): cap regs at 128 so 2 CTAs/SM fit the regfile.
// ---------------------------------------------------------------------------
template<int TERMS, int EPI>
__global__ void __launch_bounds__(256, 2)
mma_gemm_kernel(const __nv_bfloat16* __restrict__ Ah,
                const __nv_bfloat16* __restrict__ Al,
                const __nv_bfloat16* __restrict__ Bh,
                const __nv_bfloat16* __restrict__ Bl,
                void* __restrict__ Cout, int N, int K,
                const float* __restrict__ bias,
                const float* __restrict__ xres,
                const float* __restrict__ bns,
                const float* __restrict__ bnb,
                const float* __restrict__ bnm,
                const float* __restrict__ bnv,
                const __nv_bfloat16* __restrict__ Bh2,
                const float* __restrict__ bias2,
                void* __restrict__ Cout2)
{
    constexpr int STAGE = (TERMS == 3) ? 32768 : 16384;
    constexpr uint32_t BOFF = (TERMS == 3) ? 16384u : 8192u;
    extern __shared__ __align__(1024) char smem[];
    const uint32_t sbase = smem_u32(smem);

    if (blockIdx.z == 1) { Bh = Bh2; bias = bias2; Cout = Cout2; }

    const int tid = threadIdx.x;
    const int wid = tid >> 5;
    const int lid = tid & 31;
    const int wm  = wid & 3;
    const int wn  = wid >> 2;
    const int n0  = blockIdx.x * 128;
    const int m0  = blockIdx.y * 128;

    const __nv_bfloat16* Ahb = Ah + (size_t)m0 * K;
    const __nv_bfloat16* Alb = (TERMS == 3) ? Al + (size_t)m0 * K : nullptr;
    const __nv_bfloat16* Bhb = Bh + (size_t)n0 * K;
    const __nv_bfloat16* Blb = (TERMS == 3) ? Bl + (size_t)n0 * K : nullptr;

    const int mgrp = lid >> 3;
    const int lr   = lid & 7;
    uint32_t aoff[2][2], boff[4][2];
#pragma unroll
    for (int mt = 0; mt < 2; mt++)
#pragma unroll
        for (int kh = 0; kh < 2; kh++) {
            int row = wm * 32 + mt * 16 + lr + ((mgrp & 1) << 3);
            int kg  = 2 * kh + (mgrp >> 1);
            aoff[mt][kh] = sw_off(row, kg);
        }
#pragma unroll
    for (int i = 0; i < 4; i++)
#pragma unroll
        for (int kh = 0; kh < 2; kh++) {
            int row = wn * 64 + i * 16 + lr + ((mgrp >> 1) << 3);
            int kg  = 2 * kh + (mgrp & 1);
            boff[i][kh] = BOFF + sw_off(row, kg);
        }

    float acc[2][8][4];
#pragma unroll
    for (int mt = 0; mt < 2; mt++)
#pragma unroll
        for (int nt = 0; nt < 8; nt++)
#pragma unroll
            for (int e = 0; e < 4; e++) acc[mt][nt][e] = 0.0f;

    auto load_stage = [&](int kb, int buf) {
        uint32_t dstb = sbase + buf * STAGE;
#pragma unroll
        for (int it = 0; it < 2; it++) {
            int idx = tid + it * 256;
            int row = idx >> 2, kg = idx & 3;
            size_t goff = (size_t)row * K + kb * 32 + kg * 8;
            uint32_t so = sw_off(row, kg);
            cp_async16(dstb + so, Ahb + goff);
            if (TERMS == 3) cp_async16(dstb + 8192u + so, Alb + goff);
            cp_async16(dstb + BOFF + so, Bhb + goff);
            if (TERMS == 3) cp_async16(dstb + BOFF + 8192u + so, Blb + goff);
        }
        cp_commit();
    };

    load_stage(0, 0);
    load_stage(1, 1);

    const int KB = K / 32;
    for (int kb = 0; kb < KB; kb++) {
        const int buf = kb % 3;
        if (kb < KB - 1) cp_wait<1>(); else cp_wait<0>();
        __syncthreads();
        if (kb + 2 < KB) load_stage(kb + 2, (kb + 2) % 3);

        const uint32_t stb = sbase + buf * STAGE;
#pragma unroll
        for (int kh = 0; kh < 2; kh++) {
            uint32_t afh[2][4], bfh[4][4];
            uint32_t afl[2][4], bfl[4][4];
#pragma unroll
            for (int mt = 0; mt < 2; mt++) {
                ldmatrix_x4(afh[mt][0], afh[mt][1], afh[mt][2], afh[mt][3],
                            stb + aoff[mt][kh]);
                if (TERMS == 3)
                    ldmatrix_x4(afl[mt][0], afl[mt][1], afl[mt][2], afl[mt][3],
                                stb + 8192u + aoff[mt][kh]);
            }
#pragma unroll
            for (int i = 0; i < 4; i++) {
                ldmatrix_x4(bfh[i][0], bfh[i][1], bfh[i][2], bfh[i][3],
                            stb + boff[i][kh]);
                if (TERMS == 3)
                    ldmatrix_x4(bfl[i][0], bfl[i][1], bfl[i][2], bfl[i][3],
                                stb + 8192u + boff[i][kh]);
            }
#pragma unroll
            for (int mt = 0; mt < 2; mt++)
#pragma unroll
                for (int i = 0; i < 4; i++) {
#pragma unroll
                    for (int h = 0; h < 2; h++) {
                        float* c0 = acc[mt][2*i + h];
                        mma_bf16(c0[0], c0[1], c0[2], c0[3],
                                 afh[mt][0], afh[mt][1], afh[mt][2], afh[mt][3],
                                 bfh[i][2*h], bfh[i][2*h + 1]);
                        if (TERMS == 3) {
                            mma_bf16(c0[0], c0[1], c0[2], c0[3],
                                     afh[mt][0], afh[mt][1], afh[mt][2], afh[mt][3],
                                     bfl[i][2*h], bfl[i][2*h + 1]);
                            mma_bf16(c0[0], c0[1], c0[2], c0[3],
                                     afl[mt][0], afl[mt][1], afl[mt][2], afl[mt][3],
                                     bfh[i][2*h], bfh[i][2*h + 1]);
                        }
                    }
                }
        }
    }

    const int grow = lid >> 2;
    const int gcol = (lid & 3) * 2;
    if (EPI == 0) {
        // Stage bf16 tile in smem, then coalesced 16B stores.
        __syncthreads();
        __nv_bfloat16* sC = (__nv_bfloat16*)smem;
#pragma unroll
        for (int mt = 0; mt < 2; mt++) {
            const int rl0 = wm * 32 + mt * 16 + grow;
#pragma unroll
            for (int nt = 0; nt < 8; nt++) {
                const int cl  = wn * 64 + nt * 8 + gcol;
                const int col = n0 + cl;
                float b0 = bias[col], b1 = bias[col + 1];
                *(__nv_bfloat162*)(sC + rl0 * 128 + cl) = __float22bfloat162_rn(
                    make_float2(acc[mt][nt][0] + b0, acc[mt][nt][1] + b1));
                *(__nv_bfloat162*)(sC + (rl0 + 8) * 128 + cl) = __float22bfloat162_rn(
                    make_float2(acc[mt][nt][2] + b0, acc[mt][nt][3] + b1));
            }
        }
        __syncthreads();
        __nv_bfloat16* Cg = (__nv_bfloat16*)Cout + (size_t)m0 * N + n0;
#pragma unroll
        for (int it = 0; it < 8; it++) {
            int c   = tid + it * 256;
            int row = c >> 4;
            int off = (c & 15) * 8;
            *(uint4*)(Cg + (size_t)row * N + off) = *(uint4*)(sC + row * 128 + off);
        }
    } else {
#pragma unroll
        for (int mt = 0; mt < 2; mt++) {
#pragma unroll
            for (int nt = 0; nt < 8; nt++) {
                const int col  = n0 + wn * 64 + nt * 8 + gcol;
                const int rowa = m0 + wm * 32 + mt * 16 + grow;
                float b0 = bias[col], b1 = bias[col + 1];
                float v00 = acc[mt][nt][0] + b0, v01 = acc[mt][nt][1] + b1;
                float v10 = acc[mt][nt][2] + b0, v11 = acc[mt][nt][3] + b1;
                if (EPI == 1) {
                    *(float2*)((float*)Cout + (size_t)rowa * N + col)
                        = make_float2(v00, v01);
                    *(float2*)((float*)Cout + (size_t)(rowa + 8) * N + col)
                        = make_float2(v10, v11);
                } else {
                    float g0 = rsqrtf(bnv[col] + 1e-5f) * bns[col];
                    float g1 = rsqrtf(bnv[col + 1] + 1e-5f) * bns[col + 1];
                    float m0c = bnm[col], m1c = bnm[col + 1];
                    float a0 = bnb[col], a1 = bnb[col + 1];
                    v00 = fmaxf((v00 - m0c) * g0 + a0, 0.0f);
                    v01 = fmaxf((v01 - m1c) * g1 + a1, 0.0f);
                    v10 = fmaxf((v10 - m0c) * g0 + a0, 0.0f);
                    v11 = fmaxf((v11 - m1c) * g1 + a1, 0.0f);
                    float2 r0 = *(const float2*)(xres + (size_t)rowa * N + col);
                    float2 r1 = *(const float2*)(xres + (size_t)(rowa + 8) * N + col);
                    *(float2*)((float*)Cout + (size_t)rowa * N + col)
                        = make_float2(v00 + r0.x, v01 + r0.y);
                    *(float2*)((float*)Cout + (size_t)(rowa + 8) * N + col)
                        = make_float2(v10 + r1.x, v11 + r1.y);
                }
            }
        }
    }
}

// ---------------------------------------------------------------------------
// Prep kernels
// ---------------------------------------------------------------------------
__global__ void __launch_bounds__(256)
split_kernel(const float* __restrict__ x,
             __nv_bfloat16* __restrict__ xh, __nv_bfloat16* __restrict__ xl)
{
    size_t i = ((size_t)blockIdx.x * 256 + threadIdx.x) * 4;
    float4 v = *(const float4*)(x + i);
    __nv_bfloat16 h0 = __float2bfloat16(v.x), h1 = __float2bfloat16(v.y);
    __nv_bfloat16 h2 = __float2bfloat16(v.z), h3 = __float2bfloat16(v.w);
    __nv_bfloat16 l0 = __float2bfloat16(v.x - __bfloat162float(h0));
    __nv_bfloat16 l1 = __float2bfloat16(v.y - __bfloat162float(h1));
    __nv_bfloat16 l2 = __float2bfloat16(v.z - __bfloat162float(h2));
    __nv_bfloat16 l3 = __float2bfloat16(v.w - __bfloat162float(h3));
    __nv_bfloat162 hp[2] = {{h0, h1}, {h2, h3}};
    __nv_bfloat162 lp[2] = {{l0, l1}, {l2, l3}};
    *(uint2*)(xh + i) = *(uint2*)hp;
    *(uint2*)(xl + i) = *(uint2*)lp;
}

__global__ void __launch_bounds__(256)
split_vs_kernel(const float* __restrict__ v, const float* __restrict__ srow,
                __nv_bfloat16* __restrict__ vh, __nv_bfloat16* __restrict__ vl)
{
    size_t i = ((size_t)blockIdx.x * 256 + threadIdx.x) * 4;
    float s = srow[i >> 9];
    float4 x = *(const float4*)(v + i);
    x.x *= s; x.y *= s; x.z *= s; x.w *= s;
    __nv_bfloat16 h0 = __float2bfloat16(x.x), h1 = __float2bfloat16(x.y);
    __nv_bfloat16 h2 = __float2bfloat16(x.z), h3 = __float2bfloat16(x.w);
    __nv_bfloat16 l0 = __float2bfloat16(x.x - __bfloat162float(h0));
    __nv_bfloat16 l1 = __float2bfloat16(x.y - __bfloat162float(h1));
    __nv_bfloat16 l2 = __float2bfloat16(x.z - __bfloat162float(h2));
    __nv_bfloat16 l3 = __float2bfloat16(x.w - __bfloat162float(h3));
    __nv_bfloat162 hp[2] = {{h0, h1}, {h2, h3}};
    __nv_bfloat162 lp[2] = {{l0, l1}, {l2, l3}};
    *(uint2*)(vh + i) = *(uint2*)hp;
    *(uint2*)(vl + i) = *(uint2*)lp;
}

// Transpose+split all 4 weights in ONE launch (z selects the weight).
__global__ void __launch_bounds__(1024)
wprep_all_kernel(const float* __restrict__ Wq, const float* __restrict__ Wk,
                 const float* __restrict__ Wv, const float* __restrict__ Wo,
                 __nv_bfloat16* __restrict__ WqT, __nv_bfloat16* __restrict__ WkT,
                 __nv_bfloat16* __restrict__ WvhT, __nv_bfloat16* __restrict__ WvlT,
                 __nv_bfloat16* __restrict__ WohT, __nv_bfloat16* __restrict__ WolT)
{
    const float* W;
    __nv_bfloat16 *Th, *Tl = nullptr;
    switch (blockIdx.z) {
        case 0:  W = Wq; Th = WqT;  break;
        case 1:  W = Wk; Th = WkT;  break;
        case 2:  W = Wv; Th = WvhT; Tl = WvlT; break;
        default: W = Wo; Th = WohT; Tl = WolT; break;
    }
    __shared__ float t[32][33];
    const int tx = threadIdx.x, ty = threadIdx.y;
    const int bx = blockIdx.x * 32, by = blockIdx.y * 32;
    t[ty][tx] = W[(size_t)(by + ty) * CC + bx + tx];
    __syncthreads();
    const int n = bx + ty, k = by + tx;
    float v = t[tx][ty];
    __nv_bfloat16 h = __float2bfloat16(v);
    Th[(size_t)n * CC + k] = h;
    if (Tl) Tl[(size_t)n * CC + k] = __float2bfloat16(v - __bfloat162float(h));
}

// ---------------------------------------------------------------------------
// Column sums of normalized attention (bf16 S), 32-way m-split, 4 cols/thread.
// Fused combine: each block derives rowm/rowinvl for its 128 rows from pm/pl.
// ---------------------------------------------------------------------------
__global__ void __launch_bounds__(256)
colsum_part_kernel(const __nv_bfloat16* __restrict__ S,
                   const float* __restrict__ pm,
                   const float* __restrict__ pl,
                   float* __restrict__ cpart)
{
    __shared__ float sm[128], si[128];
    const int b     = blockIdx.z;
    const int n     = blockIdx.x * 1024 + threadIdx.x * 4;
    const int m0    = blockIdx.y * 128;
    const int rbase = b * 4096;
    if (threadIdx.x < 128) {
        const int r = rbase + m0 + threadIdx.x;
        float M = -3.0e38f;
#pragma unroll
        for (int t = 0; t < 32; t++) M = fmaxf(M, pm[(size_t)t * MM + r]);
        float L = 0.0f;
#pragma unroll
        for (int t = 0; t < 32; t++)
            L += pl[(size_t)t * MM + r] * fexp(pm[(size_t)t * MM + r] - M);
        sm[threadIdx.x] = M;
        si[threadIdx.x] = 1.0f / L;
    }
    __syncthreads();
    const __nv_bfloat16* Sb = S + (size_t)b * SBATCH + (size_t)m0 * 4096 + n;
    float a0 = 0.0f, a1 = 0.0f, a2 = 0.0f, a3 = 0.0f;
#pragma unroll 4
    for (int mm = 0; mm < 128; mm++) {
        uint2 u = *(const uint2*)(Sb + (size_t)mm * 4096);
        float2 f0 = __bfloat1622float2(reinterpret_cast<__nv_bfloat162&>(u.x));
        float2 f1 = __bfloat1622float2(reinterpret_cast<__nv_bfloat162&>(u.y));
        float m = sm[mm], iv = si[mm];
        a0 += fexp(f0.x - m) * iv;
        a1 += fexp(f0.y - m) * iv;
        a2 += fexp(f1.x - m) * iv;
        a3 += fexp(f1.y - m) * iv;
    }
    *(float4*)(cpart + (size_t)blockIdx.y * MM + rbase + n)
        = make_float4(a0, a1, a2, a3);
}

__global__ void __launch_bounds__(256)
colsum_final_kernel(const float* __restrict__ cpart, float* __restrict__ srow)
{
    const int i = blockIdx.x * 256 + threadIdx.x;
    float c = 0.0f;
#pragma unroll
    for (int p = 0; p < 32; p++) c += cpart[(size_t)p * MM + i];
    srow[i] = c / (c + 1e-9f);
}

// ---------------------------------------------------------------------------
extern "C" void kernel_launch(void* const* d_in, const int* in_sizes, int n_in,
                              void* d_out, int out_size)
{
    // metadata order: inputs, Wq, Wk, Wv, Wo, bq, bk, bv, bo, bn_* (two loops!)
    const float* x   = (const float*)d_in[0];
    const float* Wq  = (const float*)d_in[1];
    const float* Wk  = (const float*)d_in[2];
    const float* Wv  = (const float*)d_in[3];
    const float* Wo  = (const float*)d_in[4];
    const float* bq  = (const float*)d_in[5];
    const float* bk  = (const float*)d_in[6];
    const float* bv  = (const float*)d_in[7];
    const float* bo  = (const float*)d_in[8];
    const float* bns = (const float*)d_in[9];
    const float* bnb = (const float*)d_in[10];
    const float* bnm = (const float*)d_in[11];
    const float* bnv = (const float*)d_in[12];
    float* out = (float*)d_out;

    void *xh, *xl, *qh, *kh, *v, *vsh, *vsl, *S;
    void *WqT, *WkT, *WvhT, *WvlT, *WohT, *WolT;
    void *pm, *pl, *cpart, *srow;
    cudaGetSymbolAddress(&xh,   g_xh);   cudaGetSymbolAddress(&xl,   g_xl);
    cudaGetSymbolAddress(&qh,   g_qh);   cudaGetSymbolAddress(&kh,   g_kh);
    cudaGetSymbolAddress(&v,    g_v);
    cudaGetSymbolAddress(&vsh,  g_vsh);  cudaGetSymbolAddress(&vsl,  g_vsl);
    cudaGetSymbolAddress(&S,    g_S);
    cudaGetSymbolAddress(&WqT,  g_WqT);  cudaGetSymbolAddress(&WkT,  g_WkT);
    cudaGetSymbolAddress(&WvhT, g_WvhT); cudaGetSymbolAddress(&WvlT, g_WvlT);
    cudaGetSymbolAddress(&WohT, g_WohT); cudaGetSymbolAddress(&WolT, g_WolT);
    cudaGetSymbolAddress(&pm,    g_pm);
    cudaGetSymbolAddress(&pl,    g_pl);
    cudaGetSymbolAddress(&cpart, g_cpart);
    cudaGetSymbolAddress(&srow,  g_srow);

    static cudaStream_t s2 = nullptr;
    static cudaEvent_t  eFork = nullptr, eJoin = nullptr;
    if (s2 == nullptr) {
        cudaStreamCreateWithFlags(&s2, cudaStreamNonBlocking);
        cudaEventCreateWithFlags(&eFork, cudaEventDisableTiming);
        cudaEventCreateWithFlags(&eJoin, cudaEventDisableTiming);
        cudaFuncSetAttribute(mma_gemm_kernel<1, 0>,
            cudaFuncAttributeMaxDynamicSharedMemorySize, 49152);
        cudaFuncSetAttribute(mma_gemm_kernel<3, 1>,
            cudaFuncAttributeMaxDynamicSharedMemorySize, 98304);
        cudaFuncSetAttribute(mma_gemm_kernel<3, 2>,
            cudaFuncAttributeMaxDynamicSharedMemorySize, 98304);
    }

    dim3 blk(256);
    dim3 gProj(CC / 128, MM / 128);           // (4, 64)
    dim3 gProj2(CC / 128, MM / 128, 2);       // fused q+k projections

    // P1: split x into bf16 hi/lo
    split_kernel<<<(MM * CC) / 1024, blk>>>(x, (__nv_bfloat16*)xh, (__nv_bfloat16*)xl);
    // P2: transpose+split all weights (one launch)
    wprep_all_kernel<<<dim3(16, 16, 4), dim3(32, 32)>>>(
        Wq, Wk, Wv, Wo,
        (__nv_bfloat16*)WqT, (__nv_bfloat16*)WkT,
        (__nv_bfloat16*)WvhT, (__nv_bfloat16*)WvlT,
        (__nv_bfloat16*)WohT, (__nv_bfloat16*)WolT);

    // Fork: G3 (v projection) runs on s2 (tail-packing with main stream).
    cudaEventRecord(eFork, 0);
    cudaStreamWaitEvent(s2, eFork, 0);

    // G1+G2 fused: q,k projections in one launch (z selects Wq/Wk)
    mma_gemm_kernel<1, 0><<<gProj2, blk, 49152>>>(
        (const __nv_bfloat16*)xh, nullptr, (const __nv_bfloat16*)WqT, nullptr,
        qh, CC, CC, bq, nullptr, nullptr, nullptr, nullptr, nullptr,
        (const __nv_bfloat16*)WkT, bk, kh);

    // G3 on s2: v projection (split-bf16, fp32 out)
    mma_gemm_kernel<3, 1><<<gProj, blk, 98304, s2>>>(
        (const __nv_bfloat16*)xh, (const __nv_bfloat16*)xl,
        (const __nv_bfloat16*)WvhT, (const __nv_bfloat16*)WvlT,
        v, CC, CC, bv, nullptr, nullptr, nullptr, nullptr, nullptr,
        nullptr, nullptr, nullptr);
    cudaEventRecord(eJoin, s2);

    // K2: S = q @ k^T per batch + fused per-tile softmax stats
    qk_mma_kernel<<<dim3(32, 32, 2), blk>>>(
        (const __nv_bfloat16*)qh, (const __nv_bfloat16*)kh, (__nv_bfloat16*)S,
        (float*)pm, (float*)pl);

    // K4: column sums -> s[n] (combine fused into part kernel)
    colsum_part_kernel<<<dim3(4, 32, 2), blk>>>((const __nv_bfloat16*)S,
        (const float*)pm, (const float*)pl, (float*)cpart);
    colsum_final_kernel<<<MM / 256, blk>>>((const float*)cpart, (float*)srow);

    // Join: split_vs needs v (from G3 on s2) and srow.
    cudaStreamWaitEvent(0, eJoin, 0);

    // P3: vs = v * s[row], split into bf16 hi/lo
    split_vs_kernel<<<(MM * CC) / 1024, blk>>>(
        (const float*)v, (const float*)srow,
        (__nv_bfloat16*)vsh, (__nv_bfloat16*)vsl);

    // G4: out = relu(BN(vs @ Wo + bo)) + x  (split-bf16, fp32 epilogue)
    mma_gemm_kernel<3, 2><<<gProj, blk, 98304>>>(
        (const __nv_bfloat16*)vsh, (const __nv_bfloat16*)vsl,
        (const __nv_bfloat16*)WohT, (const __nv_bfloat16*)WolT,
        out, CC, CC, bo, x, bns, bnb, bnm, bnv,
        nullptr, nullptr, nullptr);
}